// round 1
// baseline (speedup 1.0000x reference)
#include <cuda_runtime.h>
#include <math.h>

#define NN 50000
#define NE 400000
#define DD 128
#define NM 20400
#define NG 30
#define LMAX 680
#define NHEADS 4
#define NL 4
#define FFD 2048
#define NCHUNK 160   // ceil(20400/128)

// ---------------- scratch (device globals; no runtime allocation) ----------------
__device__ __align__(16) float g_h[(size_t)NN * DD];
__device__ __align__(16) float g_gout[(size_t)NN * DD];
__device__ __align__(16) float g_acc[(size_t)NN * DD];
__device__ __align__(16) float g_als[NN * NHEADS];
__device__ __align__(16) float g_ald[NN * NHEADS];
__device__ __align__(16) float g_mx[NN * NHEADS];
__device__ __align__(16) float g_den[NN * NHEADS];
__device__ __align__(16) float g_y[(size_t)NM * DD];
__device__ __align__(16) float g_qkv[(size_t)NM * 3 * DD];
__device__ __align__(16) float g_attn[(size_t)NM * DD];
__device__ __align__(16) float g_tmp[(size_t)NM * DD];
__device__ __align__(16) float g_ffn[(size_t)NM * FFD];
__device__ __align__(16) float g_xm[(size_t)NM * DD];
__device__ __align__(16) float g_pooled[NG * DD];
__device__ __align__(16) float g_pe[NG * DD];
__device__ int g_pos[NM];
__device__ int g_cnt[NG];
__device__ int g_chist[NCHUNK * NG];

// ---------------- small helpers ----------------
__device__ __forceinline__ float leakyf(float x, float s) { return x >= 0.f ? x : s * x; }

__device__ __forceinline__ void atomicMaxF(float* addr, float val) {
    if (!(__float_as_uint(val) >> 31)) {           // val >= +0
        atomicMax((int*)addr, __float_as_int(val));
    } else {                                        // val negative (incl -0)
        atomicMin((unsigned int*)addr, __float_as_uint(val));
    }
}

__device__ __forceinline__ float dot4(float4 a, float4 b) {
    return a.x * b.x + a.y * b.y + a.z * b.z + a.w * b.w;
}

// ---------------- generic SGEMM: C = epi(A[M,K] * B[N,K]^T + bias) ----------------
// epi: 0 = store (+bias if bias!=null)
//      1 = relu(v+bias)
//      2 = C += scale * leaky_{0.01}(v+bias)
__global__ __launch_bounds__(256) void gemm128(
    const float* __restrict__ A, const float* __restrict__ B,
    const float* __restrict__ bias, float* __restrict__ C,
    int M, int N, int K, int ldb, int epi, float scale)
{
    __shared__ float As[16][128];
    __shared__ float Bs[16][128];
    const int tid = threadIdx.x;
    const int tx = tid & 15, ty = tid >> 4;
    const int row0 = blockIdx.y * 128, col0 = blockIdx.x * 128;

    float acc[8][8];
#pragma unroll
    for (int i = 0; i < 8; i++)
#pragma unroll
        for (int j = 0; j < 8; j++) acc[i][j] = 0.f;

    for (int k0 = 0; k0 < K; k0 += 16) {
#pragma unroll
        for (int L = tid; L < 512; L += 256) {
            int ar = L >> 2;
            int kc = (L & 3) * 4;
            float4 v = make_float4(0.f, 0.f, 0.f, 0.f);
            int gr = row0 + ar;
            if (gr < M) v = *(const float4*)(A + (size_t)gr * K + k0 + kc);
            As[kc + 0][ar] = v.x; As[kc + 1][ar] = v.y;
            As[kc + 2][ar] = v.z; As[kc + 3][ar] = v.w;
        }
#pragma unroll
        for (int L = tid; L < 512; L += 256) {
            int br = L >> 2;
            int kc = (L & 3) * 4;
            float4 v = make_float4(0.f, 0.f, 0.f, 0.f);
            int gc = col0 + br;
            if (gc < N) v = *(const float4*)(B + (size_t)gc * ldb + k0 + kc);
            Bs[kc + 0][br] = v.x; Bs[kc + 1][br] = v.y;
            Bs[kc + 2][br] = v.z; Bs[kc + 3][br] = v.w;
        }
        __syncthreads();
#pragma unroll
        for (int k = 0; k < 16; k++) {
            float4 a0 = *(float4*)&As[k][ty * 8];
            float4 a1 = *(float4*)&As[k][ty * 8 + 4];
            float4 b0 = *(float4*)&Bs[k][tx * 8];
            float4 b1 = *(float4*)&Bs[k][tx * 8 + 4];
            float a[8] = {a0.x, a0.y, a0.z, a0.w, a1.x, a1.y, a1.z, a1.w};
            float b[8] = {b0.x, b0.y, b0.z, b0.w, b1.x, b1.y, b1.z, b1.w};
#pragma unroll
            for (int i = 0; i < 8; i++)
#pragma unroll
                for (int j = 0; j < 8; j++) acc[i][j] = fmaf(a[i], b[j], acc[i][j]);
        }
        __syncthreads();
    }

#pragma unroll
    for (int i = 0; i < 8; i++) {
        int r = row0 + ty * 8 + i;
        if (r < M) {
#pragma unroll
            for (int jj = 0; jj < 2; jj++) {
                int c = col0 + tx * 8 + jj * 4;
                if (c < N) {
                    float4 v = make_float4(acc[i][jj * 4 + 0], acc[i][jj * 4 + 1],
                                           acc[i][jj * 4 + 2], acc[i][jj * 4 + 3]);
                    if (bias) {
                        float4 bb = *(const float4*)(bias + c);
                        v.x += bb.x; v.y += bb.y; v.z += bb.z; v.w += bb.w;
                    }
                    float* cp = C + (size_t)r * N + c;
                    if (epi == 0) {
                        *(float4*)cp = v;
                    } else if (epi == 1) {
                        v.x = fmaxf(v.x, 0.f); v.y = fmaxf(v.y, 0.f);
                        v.z = fmaxf(v.z, 0.f); v.w = fmaxf(v.w, 0.f);
                        *(float4*)cp = v;
                    } else {
                        float4 o = *(float4*)cp;
                        o.x += scale * leakyf(v.x, 0.01f);
                        o.y += scale * leakyf(v.y, 0.01f);
                        o.z += scale * leakyf(v.z, 0.01f);
                        o.w += scale * leakyf(v.w, 0.01f);
                        *(float4*)cp = o;
                    }
                }
            }
        }
    }
}

// ---------------- GAT kernels ----------------
__global__ void zero_acc_kernel() {
    size_t i = (size_t)blockIdx.x * blockDim.x + threadIdx.x;
    if (i < (size_t)NN * DD / 4) ((float4*)g_acc)[i] = make_float4(0.f, 0.f, 0.f, 0.f);
}
__global__ void zero_y_kernel() {
    size_t i = (size_t)blockIdx.x * blockDim.x + threadIdx.x;
    if (i < (size_t)NM * DD / 4) ((float4*)g_y)[i] = make_float4(0.f, 0.f, 0.f, 0.f);
}

// warp per node: al_src/al_dst reductions + init max/den + out=bias
__global__ void gat_prep_kernel(const float* __restrict__ a_src,
                                const float* __restrict__ a_dst,
                                const float* __restrict__ bias)
{
    int gid = blockIdx.x * blockDim.x + threadIdx.x;
    int node = gid >> 5, lane = gid & 31;
    if (node >= NN) return;
    float s[4], d[4];
#pragma unroll
    for (int j = 0; j < 4; j++) {
        int c = j * 32 + lane;
        float hv = g_h[(size_t)node * DD + c];
        s[j] = hv * a_src[c];
        d[j] = hv * a_dst[c];
        g_gout[(size_t)node * DD + c] = bias[c];
    }
#pragma unroll
    for (int j = 0; j < 4; j++)
#pragma unroll
        for (int o = 16; o > 0; o >>= 1) {
            s[j] += __shfl_xor_sync(0xffffffffu, s[j], o);
            d[j] += __shfl_xor_sync(0xffffffffu, d[j], o);
        }
    if (lane == 0) {
        *(float4*)&g_als[node * 4] = make_float4(s[0], s[1], s[2], s[3]);
        *(float4*)&g_ald[node * 4] = make_float4(d[0], d[1], d[2], d[3]);
        *(float4*)&g_mx[node * 4] = make_float4(-INFINITY, -INFINITY, -INFINITY, -INFINITY);
        *(float4*)&g_den[node * 4] = make_float4(0.f, 0.f, 0.f, 0.f);
    }
}

__global__ void edge_max_kernel(const int* __restrict__ ei) {
    int t = blockIdx.x * blockDim.x + threadIdx.x;
    if (t >= NE + NN) return;
    int src, dst;
    if (t < NE) { src = ei[t]; dst = ei[NE + t]; }
    else { src = dst = t - NE; }
    float4 a = *(const float4*)&g_als[src * 4];
    float4 b = *(const float4*)&g_ald[dst * 4];
    atomicMaxF(&g_mx[dst * 4 + 0], leakyf(a.x + b.x, 0.2f));
    atomicMaxF(&g_mx[dst * 4 + 1], leakyf(a.y + b.y, 0.2f));
    atomicMaxF(&g_mx[dst * 4 + 2], leakyf(a.z + b.z, 0.2f));
    atomicMaxF(&g_mx[dst * 4 + 3], leakyf(a.w + b.w, 0.2f));
}

__global__ void edge_sum_kernel(const int* __restrict__ ei) {
    int t = blockIdx.x * blockDim.x + threadIdx.x;
    if (t >= NE + NN) return;
    int src, dst;
    if (t < NE) { src = ei[t]; dst = ei[NE + t]; }
    else { src = dst = t - NE; }
    float4 a = *(const float4*)&g_als[src * 4];
    float4 b = *(const float4*)&g_ald[dst * 4];
    float4 m = *(const float4*)&g_mx[dst * 4];
    atomicAdd(&g_den[dst * 4 + 0], expf(leakyf(a.x + b.x, 0.2f) - m.x));
    atomicAdd(&g_den[dst * 4 + 1], expf(leakyf(a.y + b.y, 0.2f) - m.y));
    atomicAdd(&g_den[dst * 4 + 2], expf(leakyf(a.z + b.z, 0.2f) - m.z));
    atomicAdd(&g_den[dst * 4 + 3], expf(leakyf(a.w + b.w, 0.2f) - m.w));
}

// warp per (edge or self-loop): out[dst, :] += alpha_h * h[src, :]
__global__ void edge_aggr_kernel(const int* __restrict__ ei) {
    int gid = blockIdx.x * blockDim.x + threadIdx.x;
    int item = gid >> 5, lane = gid & 31;
    if (item >= NE + NN) return;
    int src, dst;
    if (item < NE) { src = ei[item]; dst = ei[NE + item]; }
    else { src = dst = item - NE; }
    float4 a = *(const float4*)&g_als[src * 4];
    float4 b = *(const float4*)&g_ald[dst * 4];
    float4 m = *(const float4*)&g_mx[dst * 4];
    float4 dn = *(const float4*)&g_den[dst * 4];
    float al[4];
    al[0] = expf(leakyf(a.x + b.x, 0.2f) - m.x) / dn.x;
    al[1] = expf(leakyf(a.y + b.y, 0.2f) - m.y) / dn.y;
    al[2] = expf(leakyf(a.z + b.z, 0.2f) - m.z) / dn.z;
    al[3] = expf(leakyf(a.w + b.w, 0.2f) - m.w) / dn.w;
#pragma unroll
    for (int j = 0; j < 4; j++) {
        int c = j * 32 + lane;
        float v = g_h[(size_t)src * DD + c] * al[j];
        atomicAdd(&g_gout[(size_t)dst * DD + c], v);
    }
}

// ---------------- position / count kernels ----------------
__global__ void hist_kernel(const int* __restrict__ genre) {
    __shared__ int loc[NG];
    if (threadIdx.x < NG) loc[threadIdx.x] = 0;
    __syncthreads();
    int i = blockIdx.x * 128 + threadIdx.x;
    if (i < NM) atomicAdd(&loc[genre[i]], 1);
    __syncthreads();
    if (threadIdx.x < NG) g_chist[blockIdx.x * NG + threadIdx.x] = loc[threadIdx.x];
}
__global__ void scan_kernel() {
    int g = threadIdx.x;
    if (g >= NG) return;
    int run = 0;
    for (int c = 0; c < NCHUNK; c++) {
        int t = g_chist[c * NG + g];
        g_chist[c * NG + g] = run;
        run += t;
    }
    g_cnt[g] = run;
}
__global__ void pos_kernel(const int* __restrict__ genre) {
    int c = blockIdx.x * blockDim.x + threadIdx.x;
    if (c >= NCHUNK) return;
    int off[NG];
    for (int g = 0; g < NG; g++) off[g] = g_chist[c * NG + g];
    int base = c * 128;
    int end = base + 128; if (end > NM) end = NM;
    for (int i = base; i < end; i++) {
        int g = genre[i];
        g_pos[i] = off[g]++;
    }
}

__global__ void gather_kernel(const int* __restrict__ movie_idx, const int* __restrict__ genre) {
    int t = blockIdx.x * blockDim.x + threadIdx.x;
    if (t >= NM * 32) return;
    int i = t >> 5, c4 = (t & 31) * 4;
    float4 v = *(const float4*)&g_acc[(size_t)movie_idx[i] * DD + c4];
    *(float4*)&g_xm[(size_t)i * DD + c4] = v;
    int row = genre[i] * LMAX + g_pos[i];
    *(float4*)&g_y[(size_t)row * DD + c4] = v;
}

// ---------------- attention (flash-style, thread per query) ----------------
__global__ __launch_bounds__(128) void attn_kernel() {
    __shared__ float Ks[64 * 32];
    __shared__ float Vs[64 * 32];
    int b = blockIdx.z, h = blockIdx.y;
    int q = blockIdx.x * 128 + threadIdx.x;
    int S = g_cnt[b];
    bool active = q < LMAX;

    float4 qv4[8];
    if (active) {
        const float* qp = g_qkv + (size_t)(b * LMAX + q) * 3 * DD + h * 32;
#pragma unroll
        for (int d4 = 0; d4 < 8; d4++) qv4[d4] = *(const float4*)(qp + d4 * 4);
    }
    float m = -INFINITY, den = 0.f;
    float4 ov4[8];
#pragma unroll
    for (int d4 = 0; d4 < 8; d4++) ov4[d4] = make_float4(0.f, 0.f, 0.f, 0.f);

    for (int kb = 0; kb < LMAX; kb += 64) {
        int nk = LMAX - kb; if (nk > 64) nk = 64;
        for (int idx = threadIdx.x; idx < 64 * 8; idx += 128) {
            int s = idx >> 3;
            int d4 = (idx & 7) * 4;
            float4 kv = make_float4(0.f, 0.f, 0.f, 0.f);
            float4 vv = make_float4(0.f, 0.f, 0.f, 0.f);
            if (s < nk) {
                const float* base = g_qkv + (size_t)(b * LMAX + kb + s) * 3 * DD;
                kv = *(const float4*)(base + DD + h * 32 + d4);
                vv = *(const float4*)(base + 2 * DD + h * 32 + d4);
            }
            *(float4*)&Ks[s * 32 + d4] = kv;
            *(float4*)&Vs[s * 32 + d4] = vv;
        }
        __syncthreads();
        if (active) {
            int ns = S - kb; if (ns > 64) ns = 64;
            for (int s = 0; s < ns; s++) {
                const float4* kp = (const float4*)&Ks[s * 32];
                float sc = 0.f;
#pragma unroll
                for (int d4 = 0; d4 < 8; d4++) sc += dot4(qv4[d4], kp[d4]);
                sc *= 0.17677669529663687f;   // 1/sqrt(32)
                const float4* vp = (const float4*)&Vs[s * 32];
                if (sc > m) {
                    float corr = __expf(m - sc);
                    m = sc;
                    den = den * corr + 1.f;
#pragma unroll
                    for (int d4 = 0; d4 < 8; d4++) {
                        float4 v4 = vp[d4];
                        ov4[d4].x = fmaf(ov4[d4].x, corr, v4.x);
                        ov4[d4].y = fmaf(ov4[d4].y, corr, v4.y);
                        ov4[d4].z = fmaf(ov4[d4].z, corr, v4.z);
                        ov4[d4].w = fmaf(ov4[d4].w, corr, v4.w);
                    }
                } else {
                    float p = __expf(sc - m);
                    den += p;
#pragma unroll
                    for (int d4 = 0; d4 < 8; d4++) {
                        float4 v4 = vp[d4];
                        ov4[d4].x = fmaf(p, v4.x, ov4[d4].x);
                        ov4[d4].y = fmaf(p, v4.y, ov4[d4].y);
                        ov4[d4].z = fmaf(p, v4.z, ov4[d4].z);
                        ov4[d4].w = fmaf(p, v4.w, ov4[d4].w);
                    }
                }
            }
        }
        __syncthreads();
    }
    if (active) {
        float inv = 1.f / den;
        float* op = g_attn + (size_t)(b * LMAX + q) * DD + h * 32;
#pragma unroll
        for (int d4 = 0; d4 < 8; d4++) {
            float4 o = make_float4(ov4[d4].x * inv, ov4[d4].y * inv,
                                   ov4[d4].z * inv, ov4[d4].w * inv);
            *(float4*)(op + d4 * 4) = o;
        }
    }
}

// ---------------- LayerNorm (fused residual): y = LN(y + t) ----------------
__global__ void ln_kernel(float* __restrict__ y, const float* __restrict__ t,
                          const float* __restrict__ gam, const float* __restrict__ bet,
                          int rows)
{
    int gid = blockIdx.x * blockDim.x + threadIdx.x;
    int row = gid >> 5, lane = gid & 31;
    if (row >= rows) return;
    size_t off = (size_t)row * DD + lane * 4;
    float4 v = *(float4*)(y + off);
    float4 tv = *(const float4*)(t + off);
    v.x += tv.x; v.y += tv.y; v.z += tv.z; v.w += tv.w;
    float s = v.x + v.y + v.z + v.w;
#pragma unroll
    for (int o = 16; o > 0; o >>= 1) s += __shfl_xor_sync(0xffffffffu, s, o);
    float mean = s * (1.f / DD);
    float dx = v.x - mean, dy = v.y - mean, dz = v.z - mean, dw = v.w - mean;
    float ss = dx * dx + dy * dy + dz * dz + dw * dw;
#pragma unroll
    for (int o = 16; o > 0; o >>= 1) ss += __shfl_xor_sync(0xffffffffu, ss, o);
    float inv = rsqrtf(ss * (1.f / DD) + 1e-5f);
    float4 gg = *(const float4*)(gam + lane * 4);
    float4 bb = *(const float4*)(bet + lane * 4);
    v.x = dx * inv * gg.x + bb.x;
    v.y = dy * inv * gg.y + bb.y;
    v.z = dz * inv * gg.z + bb.z;
    v.w = dw * inv * gg.w + bb.w;
    *(float4*)(y + off) = v;
}

// ---------------- pooling / fusion ----------------
__global__ void pool_kernel() {
    int g = blockIdx.x, d = threadIdx.x;
    int cnt = g_cnt[g];
    float s = 0.f;
    for (int t = 0; t < cnt; t++) s += g_y[(size_t)(g * LMAX + t) * DD + d];
    g_pooled[g * DD + d] = s / fmaxf((float)cnt, 1.f);
}

__global__ void pe_kernel(const float* __restrict__ fus_w) {
    int g = blockIdx.x, n = threadIdx.x;
    float s = 0.f;
    for (int k = 0; k < DD; k++)
        s += g_pooled[g * DD + k] * fus_w[n * 256 + 128 + k];
    g_pe[g * DD + n] = s;
}

__global__ void copy_out_kernel(float* __restrict__ out) {
    size_t i = (size_t)blockIdx.x * blockDim.x + threadIdx.x;
    if (i < (size_t)NN * DD / 4) ((float4*)out)[i] = ((const float4*)g_acc)[i];
}

__global__ void fuse_out_kernel(const int* __restrict__ movie_idx, const int* __restrict__ genre,
                                const float* __restrict__ fus_b, float* __restrict__ out)
{
    int t = blockIdx.x * blockDim.x + threadIdx.x;
    if (t >= NM * 32) return;
    int i = t >> 5, c4 = (t & 31) * 4;
    float4 v = *(const float4*)&g_tmp[(size_t)i * DD + c4];
    float4 p = *(const float4*)&g_pe[genre[i] * DD + c4];
    float4 bb = *(const float4*)(fus_b + c4);
    v.x = leakyf(v.x + p.x + bb.x, 0.01f);
    v.y = leakyf(v.y + p.y + bb.y, 0.01f);
    v.z = leakyf(v.z + p.z + bb.z, 0.01f);
    v.w = leakyf(v.w + p.w + bb.w, 0.01f);
    *(float4*)&out[(size_t)movie_idx[i] * DD + c4] = v;
}

// ---------------- launch ----------------
extern "C" void kernel_launch(void* const* d_in, const int* in_sizes, int n_in,
                              void* d_out, int out_size)
{
    const float* x        = (const float*)d_in[0];
    const int*   e[3]     = {(const int*)d_in[1], (const int*)d_in[2], (const int*)d_in[3]};
    const int*   movie_idx = (const int*)d_in[4];
    const int*   genre     = (const int*)d_in[5];
    const float* gat_W    = (const float*)d_in[6];
    const float* att_src  = (const float*)d_in[7];
    const float* att_dst  = (const float*)d_in[8];
    const float* gat_bias = (const float*)d_in[9];
    const float* dec_W    = (const float*)d_in[10];
    const float* dec_b    = (const float*)d_in[11];
    const float* qkv_w    = (const float*)d_in[12];
    const float* qkv_b    = (const float*)d_in[13];
    const float* out_w    = (const float*)d_in[14];
    const float* out_b    = (const float*)d_in[15];
    const float* ln1_g    = (const float*)d_in[16];
    const float* ln1_b    = (const float*)d_in[17];
    const float* ln2_g    = (const float*)d_in[18];
    const float* ln2_b    = (const float*)d_in[19];
    const float* ffn_w1   = (const float*)d_in[20];
    const float* ffn_b1   = (const float*)d_in[21];
    const float* ffn_w2   = (const float*)d_in[22];
    const float* ffn_b2   = (const float*)d_in[23];
    const float* fus_w    = (const float*)d_in[24];
    const float* fus_b    = (const float*)d_in[25];
    float* out = (float*)d_out;

    float *p_h, *p_gout, *p_acc, *p_y, *p_qkv, *p_attn, *p_tmp, *p_ffn, *p_xm;
    cudaGetSymbolAddress((void**)&p_h,    g_h);
    cudaGetSymbolAddress((void**)&p_gout, g_gout);
    cudaGetSymbolAddress((void**)&p_acc,  g_acc);
    cudaGetSymbolAddress((void**)&p_y,    g_y);
    cudaGetSymbolAddress((void**)&p_qkv,  g_qkv);
    cudaGetSymbolAddress((void**)&p_attn, g_attn);
    cudaGetSymbolAddress((void**)&p_tmp,  g_tmp);
    cudaGetSymbolAddress((void**)&p_ffn,  g_ffn);
    cudaGetSymbolAddress((void**)&p_xm,   g_xm);

    // -------- GAT (3 hops) --------
    zero_acc_kernel<<<(NN * DD / 4 + 255) / 256, 256>>>();
    for (int k = 0; k < 3; k++) {
        dim3 gh((DD + 127) / 128, (NN + 127) / 128);
        gemm128<<<gh, 256>>>(x, gat_W + (size_t)k * DD * DD, nullptr, p_h,
                             NN, DD, DD, DD, 0, 0.f);
        gat_prep_kernel<<<(NN * 32 + 255) / 256, 256>>>(att_src + k * DD, att_dst + k * DD,
                                                        gat_bias + k * DD);
        int items = NE + NN;
        edge_max_kernel<<<(items + 255) / 256, 256>>>(e[k]);
        edge_sum_kernel<<<(items + 255) / 256, 256>>>(e[k]);
        edge_aggr_kernel<<<((size_t)items * 32 + 255) / 256, 256>>>(e[k]);
        float scale = (float)exp(-0.1 * k);
        gemm128<<<gh, 256>>>(p_gout, dec_W + (size_t)k * DD * DD, dec_b + k * DD, p_acc,
                             NN, DD, DD, DD, 2, scale);
    }

    // -------- build genre sequences --------
    hist_kernel<<<NCHUNK, 128>>>(genre);
    scan_kernel<<<1, 32>>>();
    pos_kernel<<<1, 256>>>(genre);
    zero_y_kernel<<<(NM * DD / 4 + 255) / 256, 256>>>();
    gather_kernel<<<(NM * 32 + 255) / 256, 256>>>(movie_idx, genre);

    // -------- transformer (4 layers) --------
    for (int l = 0; l < NL; l++) {
        dim3 gq((3 * DD + 127) / 128, (NM + 127) / 128);
        gemm128<<<gq, 256>>>(p_y, qkv_w + (size_t)l * 3 * DD * DD, qkv_b + l * 3 * DD,
                             p_qkv, NM, 3 * DD, DD, DD, 0, 0.f);
        attn_kernel<<<dim3((LMAX + 127) / 128, NHEADS, NG), 128>>>();
        dim3 gp((DD + 127) / 128, (NM + 127) / 128);
        gemm128<<<gp, 256>>>(p_attn, out_w + (size_t)l * DD * DD, out_b + l * DD,
                             p_tmp, NM, DD, DD, DD, 0, 0.f);
        ln_kernel<<<(NM * 32 + 255) / 256, 256>>>(p_y, p_tmp, ln1_g + l * DD, ln1_b + l * DD, NM);
        dim3 gf1((FFD + 127) / 128, (NM + 127) / 128);
        gemm128<<<gf1, 256>>>(p_y, ffn_w1 + (size_t)l * FFD * DD, ffn_b1 + l * FFD,
                              p_ffn, NM, FFD, DD, DD, 1, 0.f);
        dim3 gf2((DD + 127) / 128, (NM + 127) / 128);
        gemm128<<<gf2, 256>>>(p_ffn, ffn_w2 + (size_t)l * DD * FFD, ffn_b2 + l * DD,
                              p_tmp, NM, DD, FFD, FFD, 0, 0.f);
        ln_kernel<<<(NM * 32 + 255) / 256, 256>>>(p_y, p_tmp, ln2_g + l * DD, ln2_b + l * DD, NM);
    }

    // -------- pool + fuse + write output --------
    pool_kernel<<<NG, DD>>>();
    pe_kernel<<<NG, DD>>>(fus_w);
    dim3 gfu((DD + 127) / 128, (NM + 127) / 128);
    gemm128<<<gfu, 256>>>(p_xm, fus_w, nullptr, p_tmp, NM, DD, DD, 256, 0, 0.f);
    copy_out_kernel<<<(NN * DD / 4 + 255) / 256, 256>>>(out);
    fuse_out_kernel<<<(NM * 32 + 255) / 256, 256>>>(movie_idx, genre, fus_b, out);
}

// round 3
// speedup vs baseline: 1.3868x; 1.3868x over previous
#include <cuda_runtime.h>
#include <math.h>
#include <stdint.h>

#define NN 50000
#define NE 400000
#define DD 128
#define NM 20400
#define NG 30
#define LMAX 680
#define NHEADS 4
#define NL 4
#define FFD 2048
#define NCHUNK 160   // ceil(20400/128)

// ---------------- scratch (device globals; no runtime allocation) ----------------
__device__ __align__(16) float g_h[(size_t)NN * DD];
__device__ __align__(16) float g_gout[(size_t)NN * DD];
__device__ __align__(16) float g_acc[(size_t)NN * DD];
__device__ __align__(16) float g_als[NN * NHEADS];
__device__ __align__(16) float g_ald[NN * NHEADS];
__device__ __align__(16) float g_mx[NN * NHEADS];
__device__ __align__(16) float g_den[NN * NHEADS];
__device__ __align__(16) float g_y[(size_t)NM * DD];
__device__ __align__(16) float g_qkv[(size_t)NM * 3 * DD];
__device__ __align__(16) float g_attn[(size_t)NM * DD];
__device__ __align__(16) float g_tmp[(size_t)NM * DD];
__device__ __align__(16) float g_ffn[(size_t)NM * FFD];
__device__ __align__(16) float g_xm[(size_t)NM * DD];
__device__ __align__(16) float g_pooled[NG * DD];
__device__ __align__(16) float g_pe[NG * DD];
__device__ int g_pos[NM];
__device__ int g_cnt[NG];
__device__ int g_chist[NCHUNK * NG];

// ---------------- small helpers ----------------
__device__ __forceinline__ float leakyf(float x, float s) { return x >= 0.f ? x : s * x; }

__device__ __forceinline__ void atomicMaxF(float* addr, float val) {
    if (!(__float_as_uint(val) >> 31)) {
        atomicMax((int*)addr, __float_as_int(val));
    } else {
        atomicMin((unsigned int*)addr, __float_as_uint(val));
    }
}

__device__ __forceinline__ float dot4(float4 a, float4 b) {
    return a.x * b.x + a.y * b.y + a.z * b.z + a.w * b.w;
}

__device__ __forceinline__ uint32_t f2tf32(float f) {
    uint32_t r;
    asm("cvt.rna.tf32.f32 %0, %1;" : "=r"(r) : "f"(f));
    return r;
}

// ---------------- mma.sync tf32 GEMM: C[M,N] = epi(A[M,K(lda)] * B[N,K(ldb)]^T + bias) ----------------
// epi: 0 = store (+bias if bias), 1 = relu(+bias)
// N multiple of 128, K multiple of 32. grid (N/128, ceil(M/128)), block 256.
// CTA tile 128x128, K-chunk 32. 8 warps: warp (wm, wn) computes rows [wm*64,+64), cols [wn*32,+32).
// SMEM holds fragment-ordered tf32 operands so each compute access is one lds.128/lds.64.
__global__ __launch_bounds__(256) void gemm_mma(
    const float* __restrict__ A, const float* __restrict__ B,
    const float* __restrict__ bias, float* __restrict__ C,
    int M, int N, int K, int lda, int ldb, int epi)
{
    __shared__ uint32_t Asm[4096];   // [ks4][mtile8][thr32][4 regs]
    __shared__ uint32_t Bsm[4096];   // [ks4][ntile16][thr32][2 regs]
    const int tid = threadIdx.x;
    const int wid = tid >> 5, lane = tid & 31;
    const int wm = wid & 1, wn = wid >> 1;
    const int row0 = blockIdx.y * 128, col0 = blockIdx.x * 128;

    float acc[4][4][4];
#pragma unroll
    for (int i = 0; i < 4; i++)
#pragma unroll
        for (int j = 0; j < 4; j++) {
            acc[i][j][0] = 0.f; acc[i][j][1] = 0.f;
            acc[i][j][2] = 0.f; acc[i][j][3] = 0.f;
        }

    for (int k0 = 0; k0 < K; k0 += 32) {
        __syncthreads();
        // ---- stage A chunk (128 rows x 32 k) into fragment order ----
#pragma unroll
        for (int it = 0; it < 4; it++) {
            int q = it * 256 + tid;              // 0..1023 float4 slots
            int row = q >> 3, c4 = (q & 7) * 4;
            float4 v = make_float4(0.f, 0.f, 0.f, 0.f);
            int gr = row0 + row;
            if (gr < M) v = *(const float4*)(A + (size_t)gr * lda + k0 + c4);
            float vv[4] = {v.x, v.y, v.z, v.w};
            int mt = row >> 4, g = row & 15;
#pragma unroll
            for (int e = 0; e < 4; e++) {
                int col = c4 + e;
                int ks = col >> 3, kc = col & 7;
                int t = (g & 7) * 4 + (kc & 3);
                int reg = ((kc >> 2) << 1) + (g >> 3);
                Asm[((ks * 8 + mt) * 32 + t) * 4 + reg] = f2tf32(vv[e]);
            }
        }
        // ---- stage B chunk (128 n-rows x 32 k) into fragment order ----
#pragma unroll
        for (int it = 0; it < 4; it++) {
            int q = it * 256 + tid;
            int nrow = q >> 3, c4 = (q & 7) * 4;
            int gc = col0 + nrow;
            float4 v = *(const float4*)(B + (size_t)gc * ldb + k0 + c4);
            float vv[4] = {v.x, v.y, v.z, v.w};
            int nt = nrow >> 3, n = nrow & 7;
#pragma unroll
            for (int e = 0; e < 4; e++) {
                int col = c4 + e;
                int ks = col >> 3, kc = col & 7;
                int t = n * 4 + (kc & 3);
                int reg = kc >> 2;
                Bsm[((ks * 16 + nt) * 32 + t) * 2 + reg] = f2tf32(vv[e]);
            }
        }
        __syncthreads();
        // ---- compute: 4 ksteps x (4 mtiles x 4 ntiles) mma ----
#pragma unroll
        for (int ks = 0; ks < 4; ks++) {
            uint2 bf[4];
#pragma unroll
            for (int nt = 0; nt < 4; nt++)
                bf[nt] = ((const uint2*)Bsm)[(ks * 16 + wn * 4 + nt) * 32 + lane];
#pragma unroll
            for (int mt = 0; mt < 4; mt++) {
                uint4 aa = ((const uint4*)Asm)[(ks * 8 + wm * 4 + mt) * 32 + lane];
#pragma unroll
                for (int nt = 0; nt < 4; nt++) {
                    asm volatile(
                        "mma.sync.aligned.m16n8k8.row.col.f32.tf32.tf32.f32 "
                        "{%0,%1,%2,%3}, {%4,%5,%6,%7}, {%8,%9}, {%0,%1,%2,%3};"
                        : "+f"(acc[mt][nt][0]), "+f"(acc[mt][nt][1]),
                          "+f"(acc[mt][nt][2]), "+f"(acc[mt][nt][3])
                        : "r"(aa.x), "r"(aa.y), "r"(aa.z), "r"(aa.w),
                          "r"(bf[nt].x), "r"(bf[nt].y));
                }
            }
        }
    }

    // ---- epilogue ----
    const int rbase = row0 + wm * 64;
    const int cbase = col0 + wn * 32;
#pragma unroll
    for (int mt = 0; mt < 4; mt++) {
        int r0 = rbase + mt * 16 + (lane >> 2);
#pragma unroll
        for (int half = 0; half < 2; half++) {
            int r = r0 + half * 8;
            if (r < M) {
#pragma unroll
                for (int nt = 0; nt < 4; nt++) {
                    int c = cbase + nt * 8 + (lane & 3) * 2;
                    float v0 = acc[mt][nt][half * 2 + 0];
                    float v1 = acc[mt][nt][half * 2 + 1];
                    if (bias) { v0 += bias[c]; v1 += bias[c + 1]; }
                    if (epi == 1) { v0 = fmaxf(v0, 0.f); v1 = fmaxf(v1, 0.f); }
                    *(float2*)(C + (size_t)r * N + c) = make_float2(v0, v1);
                }
            }
        }
    }
}

// ---------------- SIMT SGEMM (GAT + fuse, fp32 exact): C = epi(A[M,K] * B[N,K(ldb)]^T + bias) ----------------
__global__ __launch_bounds__(256) void gemm128(
    const float* __restrict__ A, const float* __restrict__ B,
    const float* __restrict__ bias, float* __restrict__ C,
    int M, int N, int K, int ldb, int epi, float scale)
{
    __shared__ float As[16][128];
    __shared__ float Bs[16][128];
    const int tid = threadIdx.x;
    const int tx = tid & 15, ty = tid >> 4;
    const int row0 = blockIdx.y * 128, col0 = blockIdx.x * 128;

    float acc[8][8];
#pragma unroll
    for (int i = 0; i < 8; i++)
#pragma unroll
        for (int j = 0; j < 8; j++) acc[i][j] = 0.f;

    for (int k0 = 0; k0 < K; k0 += 16) {
#pragma unroll
        for (int L = tid; L < 512; L += 256) {
            int ar = L >> 2;
            int kc = (L & 3) * 4;
            float4 v = make_float4(0.f, 0.f, 0.f, 0.f);
            int gr = row0 + ar;
            if (gr < M) v = *(const float4*)(A + (size_t)gr * K + k0 + kc);
            As[kc + 0][ar] = v.x; As[kc + 1][ar] = v.y;
            As[kc + 2][ar] = v.z; As[kc + 3][ar] = v.w;
        }
#pragma unroll
        for (int L = tid; L < 512; L += 256) {
            int br = L >> 2;
            int kc = (L & 3) * 4;
            float4 v = make_float4(0.f, 0.f, 0.f, 0.f);
            int gc = col0 + br;
            if (gc < N) v = *(const float4*)(B + (size_t)gc * ldb + k0 + kc);
            Bs[kc + 0][br] = v.x; Bs[kc + 1][br] = v.y;
            Bs[kc + 2][br] = v.z; Bs[kc + 3][br] = v.w;
        }
        __syncthreads();
#pragma unroll
        for (int k = 0; k < 16; k++) {
            float4 a0 = *(float4*)&As[k][ty * 8];
            float4 a1 = *(float4*)&As[k][ty * 8 + 4];
            float4 b0 = *(float4*)&Bs[k][tx * 8];
            float4 b1 = *(float4*)&Bs[k][tx * 8 + 4];
            float a[8] = {a0.x, a0.y, a0.z, a0.w, a1.x, a1.y, a1.z, a1.w};
            float b[8] = {b0.x, b0.y, b0.z, b0.w, b1.x, b1.y, b1.z, b1.w};
#pragma unroll
            for (int i = 0; i < 8; i++)
#pragma unroll
                for (int j = 0; j < 8; j++) acc[i][j] = fmaf(a[i], b[j], acc[i][j]);
        }
        __syncthreads();
    }

#pragma unroll
    for (int i = 0; i < 8; i++) {
        int r = row0 + ty * 8 + i;
        if (r < M) {
#pragma unroll
            for (int jj = 0; jj < 2; jj++) {
                int c = col0 + tx * 8 + jj * 4;
                if (c < N) {
                    float4 v = make_float4(acc[i][jj * 4 + 0], acc[i][jj * 4 + 1],
                                           acc[i][jj * 4 + 2], acc[i][jj * 4 + 3]);
                    if (bias) {
                        float4 bb = *(const float4*)(bias + c);
                        v.x += bb.x; v.y += bb.y; v.z += bb.z; v.w += bb.w;
                    }
                    float* cp = C + (size_t)r * N + c;
                    if (epi == 0) {
                        *(float4*)cp = v;
                    } else if (epi == 1) {
                        v.x = fmaxf(v.x, 0.f); v.y = fmaxf(v.y, 0.f);
                        v.z = fmaxf(v.z, 0.f); v.w = fmaxf(v.w, 0.f);
                        *(float4*)cp = v;
                    } else {
                        float4 o = *(float4*)cp;
                        o.x += scale * leakyf(v.x, 0.01f);
                        o.y += scale * leakyf(v.y, 0.01f);
                        o.z += scale * leakyf(v.z, 0.01f);
                        o.w += scale * leakyf(v.w, 0.01f);
                        *(float4*)cp = o;
                    }
                }
            }
        }
    }
}

// ---------------- GAT kernels ----------------
__global__ void zero_acc_kernel() {
    size_t i = (size_t)blockIdx.x * blockDim.x + threadIdx.x;
    if (i < (size_t)NN * DD / 4) ((float4*)g_acc)[i] = make_float4(0.f, 0.f, 0.f, 0.f);
}
__global__ void zero_y_kernel() {
    size_t i = (size_t)blockIdx.x * blockDim.x + threadIdx.x;
    if (i < (size_t)NM * DD / 4) ((float4*)g_y)[i] = make_float4(0.f, 0.f, 0.f, 0.f);
}

__global__ void gat_prep_kernel(const float* __restrict__ a_src,
                                const float* __restrict__ a_dst,
                                const float* __restrict__ bias)
{
    int gid = blockIdx.x * blockDim.x + threadIdx.x;
    int node = gid >> 5, lane = gid & 31;
    if (node >= NN) return;
    float s[4], d[4];
#pragma unroll
    for (int j = 0; j < 4; j++) {
        int c = j * 32 + lane;
        float hv = g_h[(size_t)node * DD + c];
        s[j] = hv * a_src[c];
        d[j] = hv * a_dst[c];
        g_gout[(size_t)node * DD + c] = bias[c];
    }
#pragma unroll
    for (int j = 0; j < 4; j++)
#pragma unroll
        for (int o = 16; o > 0; o >>= 1) {
            s[j] += __shfl_xor_sync(0xffffffffu, s[j], o);
            d[j] += __shfl_xor_sync(0xffffffffu, d[j], o);
        }
    if (lane == 0) {
        *(float4*)&g_als[node * 4] = make_float4(s[0], s[1], s[2], s[3]);
        *(float4*)&g_ald[node * 4] = make_float4(d[0], d[1], d[2], d[3]);
        *(float4*)&g_mx[node * 4] = make_float4(-INFINITY, -INFINITY, -INFINITY, -INFINITY);
        *(float4*)&g_den[node * 4] = make_float4(0.f, 0.f, 0.f, 0.f);
    }
}

__global__ void edge_max_kernel(const int* __restrict__ ei) {
    int t = blockIdx.x * blockDim.x + threadIdx.x;
    if (t >= NE + NN) return;
    int src, dst;
    if (t < NE) { src = ei[t]; dst = ei[NE + t]; }
    else { src = dst = t - NE; }
    float4 a = *(const float4*)&g_als[src * 4];
    float4 b = *(const float4*)&g_ald[dst * 4];
    atomicMaxF(&g_mx[dst * 4 + 0], leakyf(a.x + b.x, 0.2f));
    atomicMaxF(&g_mx[dst * 4 + 1], leakyf(a.y + b.y, 0.2f));
    atomicMaxF(&g_mx[dst * 4 + 2], leakyf(a.z + b.z, 0.2f));
    atomicMaxF(&g_mx[dst * 4 + 3], leakyf(a.w + b.w, 0.2f));
}

__global__ void edge_sum_kernel(const int* __restrict__ ei) {
    int t = blockIdx.x * blockDim.x + threadIdx.x;
    if (t >= NE + NN) return;
    int src, dst;
    if (t < NE) { src = ei[t]; dst = ei[NE + t]; }
    else { src = dst = t - NE; }
    float4 a = *(const float4*)&g_als[src * 4];
    float4 b = *(const float4*)&g_ald[dst * 4];
    float4 m = *(const float4*)&g_mx[dst * 4];
    atomicAdd(&g_den[dst * 4 + 0], expf(leakyf(a.x + b.x, 0.2f) - m.x));
    atomicAdd(&g_den[dst * 4 + 1], expf(leakyf(a.y + b.y, 0.2f) - m.y));
    atomicAdd(&g_den[dst * 4 + 2], expf(leakyf(a.z + b.z, 0.2f) - m.z));
    atomicAdd(&g_den[dst * 4 + 3], expf(leakyf(a.w + b.w, 0.2f) - m.w));
}

__global__ void edge_aggr_kernel(const int* __restrict__ ei) {
    int gid = blockIdx.x * blockDim.x + threadIdx.x;
    int item = gid >> 5, lane = gid & 31;
    if (item >= NE + NN) return;
    int src, dst;
    if (item < NE) { src = ei[item]; dst = ei[NE + item]; }
    else { src = dst = item - NE; }
    float4 a = *(const float4*)&g_als[src * 4];
    float4 b = *(const float4*)&g_ald[dst * 4];
    float4 m = *(const float4*)&g_mx[dst * 4];
    float4 dn = *(const float4*)&g_den[dst * 4];
    float al[4];
    al[0] = expf(leakyf(a.x + b.x, 0.2f) - m.x) / dn.x;
    al[1] = expf(leakyf(a.y + b.y, 0.2f) - m.y) / dn.y;
    al[2] = expf(leakyf(a.z + b.z, 0.2f) - m.z) / dn.z;
    al[3] = expf(leakyf(a.w + b.w, 0.2f) - m.w) / dn.w;
#pragma unroll
    for (int j = 0; j < 4; j++) {
        int c = j * 32 + lane;
        float v = g_h[(size_t)src * DD + c] * al[j];
        atomicAdd(&g_gout[(size_t)dst * DD + c], v);
    }
}

// ---------------- position / count kernels ----------------
__global__ void hist_kernel(const int* __restrict__ genre) {
    __shared__ int loc[NG];
    if (threadIdx.x < NG) loc[threadIdx.x] = 0;
    __syncthreads();
    int i = blockIdx.x * 128 + threadIdx.x;
    if (i < NM) atomicAdd(&loc[genre[i]], 1);
    __syncthreads();
    if (threadIdx.x < NG) g_chist[blockIdx.x * NG + threadIdx.x] = loc[threadIdx.x];
}
__global__ void scan_kernel() {
    int g = threadIdx.x;
    if (g >= NG) return;
    int run = 0;
    for (int c = 0; c < NCHUNK; c++) {
        int t = g_chist[c * NG + g];
        g_chist[c * NG + g] = run;
        run += t;
    }
    g_cnt[g] = run;
}
__global__ void pos_kernel(const int* __restrict__ genre) {
    int c = blockIdx.x * blockDim.x + threadIdx.x;
    if (c >= NCHUNK) return;
    int off[NG];
    for (int g = 0; g < NG; g++) off[g] = g_chist[c * NG + g];
    int base = c * 128;
    int end = base + 128; if (end > NM) end = NM;
    for (int i = base; i < end; i++) {
        int g = genre[i];
        g_pos[i] = off[g]++;
    }
}

__global__ void gather_kernel(const int* __restrict__ movie_idx, const int* __restrict__ genre) {
    int t = blockIdx.x * blockDim.x + threadIdx.x;
    if (t >= NM * 32) return;
    int i = t >> 5, c4 = (t & 31) * 4;
    float4 v = *(const float4*)&g_acc[(size_t)movie_idx[i] * DD + c4];
    *(float4*)&g_xm[(size_t)i * DD + c4] = v;
    int row = genre[i] * LMAX + g_pos[i];
    *(float4*)&g_y[(size_t)row * DD + c4] = v;
}

// ---------------- attention (flash-style, thread per query) ----------------
__global__ __launch_bounds__(128) void attn_kernel() {
    __shared__ float Ks[64 * 32];
    __shared__ float Vs[64 * 32];
    int b = blockIdx.z, h = blockIdx.y;
    int q = blockIdx.x * 128 + threadIdx.x;
    int S = g_cnt[b];
    bool active = q < LMAX;

    float4 qv4[8];
    if (active) {
        const float* qp = g_qkv + (size_t)(b * LMAX + q) * 3 * DD + h * 32;
#pragma unroll
        for (int d4 = 0; d4 < 8; d4++) qv4[d4] = *(const float4*)(qp + d4 * 4);
    }
    float m = -INFINITY, den = 0.f;
    float4 ov4[8];
#pragma unroll
    for (int d4 = 0; d4 < 8; d4++) ov4[d4] = make_float4(0.f, 0.f, 0.f, 0.f);

    for (int kb = 0; kb < LMAX; kb += 64) {
        int nk = LMAX - kb; if (nk > 64) nk = 64;
        for (int idx = threadIdx.x; idx < 64 * 8; idx += 128) {
            int s = idx >> 3;
            int d4 = (idx & 7) * 4;
            float4 kv = make_float4(0.f, 0.f, 0.f, 0.f);
            float4 vv = make_float4(0.f, 0.f, 0.f, 0.f);
            if (s < nk) {
                const float* base = g_qkv + (size_t)(b * LMAX + kb + s) * 3 * DD;
                kv = *(const float4*)(base + DD + h * 32 + d4);
                vv = *(const float4*)(base + 2 * DD + h * 32 + d4);
            }
            *(float4*)&Ks[s * 32 + d4] = kv;
            *(float4*)&Vs[s * 32 + d4] = vv;
        }
        __syncthreads();
        if (active) {
            int ns = S - kb; if (ns > 64) ns = 64;
            for (int s = 0; s < ns; s++) {
                const float4* kp = (const float4*)&Ks[s * 32];
                float sc = 0.f;
#pragma unroll
                for (int d4 = 0; d4 < 8; d4++) sc += dot4(qv4[d4], kp[d4]);
                sc *= 0.17677669529663687f;
                const float4* vp = (const float4*)&Vs[s * 32];
                if (sc > m) {
                    float corr = __expf(m - sc);
                    m = sc;
                    den = den * corr + 1.f;
#pragma unroll
                    for (int d4 = 0; d4 < 8; d4++) {
                        float4 v4 = vp[d4];
                        ov4[d4].x = fmaf(ov4[d4].x, corr, v4.x);
                        ov4[d4].y = fmaf(ov4[d4].y, corr, v4.y);
                        ov4[d4].z = fmaf(ov4[d4].z, corr, v4.z);
                        ov4[d4].w = fmaf(ov4[d4].w, corr, v4.w);
                    }
                } else {
                    float p = __expf(sc - m);
                    den += p;
#pragma unroll
                    for (int d4 = 0; d4 < 8; d4++) {
                        float4 v4 = vp[d4];
                        ov4[d4].x = fmaf(p, v4.x, ov4[d4].x);
                        ov4[d4].y = fmaf(p, v4.y, ov4[d4].y);
                        ov4[d4].z = fmaf(p, v4.z, ov4[d4].z);
                        ov4[d4].w = fmaf(p, v4.w, ov4[d4].w);
                    }
                }
            }
        }
        __syncthreads();
    }
    if (active) {
        float inv = 1.f / den;
        float* op = g_attn + (size_t)(b * LMAX + q) * DD + h * 32;
#pragma unroll
        for (int d4 = 0; d4 < 8; d4++) {
            float4 o = make_float4(ov4[d4].x * inv, ov4[d4].y * inv,
                                   ov4[d4].z * inv, ov4[d4].w * inv);
            *(float4*)(op + d4 * 4) = o;
        }
    }
}

// ---------------- LayerNorm (fused residual): y = LN(y + t) ----------------
__global__ void ln_kernel(float* __restrict__ y, const float* __restrict__ t,
                          const float* __restrict__ gam, const float* __restrict__ bet,
                          int rows)
{
    int gid = blockIdx.x * blockDim.x + threadIdx.x;
    int row = gid >> 5, lane = gid & 31;
    if (row >= rows) return;
    size_t off = (size_t)row * DD + lane * 4;
    float4 v = *(float4*)(y + off);
    float4 tv = *(const float4*)(t + off);
    v.x += tv.x; v.y += tv.y; v.z += tv.z; v.w += tv.w;
    float s = v.x + v.y + v.z + v.w;
#pragma unroll
    for (int o = 16; o > 0; o >>= 1) s += __shfl_xor_sync(0xffffffffu, s, o);
    float mean = s * (1.f / DD);
    float dx = v.x - mean, dy = v.y - mean, dz = v.z - mean, dw = v.w - mean;
    float ss = dx * dx + dy * dy + dz * dz + dw * dw;
#pragma unroll
    for (int o = 16; o > 0; o >>= 1) ss += __shfl_xor_sync(0xffffffffu, ss, o);
    float inv = rsqrtf(ss * (1.f / DD) + 1e-5f);
    float4 gg = *(const float4*)(gam + lane * 4);
    float4 bb = *(const float4*)(bet + lane * 4);
    v.x = dx * inv * gg.x + bb.x;
    v.y = dy * inv * gg.y + bb.y;
    v.z = dz * inv * gg.z + bb.z;
    v.w = dw * inv * gg.w + bb.w;
    *(float4*)(y + off) = v;
}

// ---------------- pooling / fusion ----------------
__global__ void pool_kernel() {
    int g = blockIdx.x, d = threadIdx.x;
    int cnt = g_cnt[g];
    float s = 0.f;
    for (int t = 0; t < cnt; t++) s += g_y[(size_t)(g * LMAX + t) * DD + d];
    g_pooled[g * DD + d] = s / fmaxf((float)cnt, 1.f);
}

__global__ void pe_kernel(const float* __restrict__ fus_w) {
    int g = blockIdx.x, n = threadIdx.x;
    float s = 0.f;
    for (int k = 0; k < DD; k++)
        s += g_pooled[g * DD + k] * fus_w[n * 256 + 128 + k];
    g_pe[g * DD + n] = s;
}

__global__ void copy_out_kernel(float* __restrict__ out) {
    size_t i = (size_t)blockIdx.x * blockDim.x + threadIdx.x;
    if (i < (size_t)NN * DD / 4) ((float4*)out)[i] = ((const float4*)g_acc)[i];
}

__global__ void fuse_out_kernel(const int* __restrict__ movie_idx, const int* __restrict__ genre,
                                const float* __restrict__ fus_b, float* __restrict__ out)
{
    int t = blockIdx.x * blockDim.x + threadIdx.x;
    if (t >= NM * 32) return;
    int i = t >> 5, c4 = (t & 31) * 4;
    float4 v = *(const float4*)&g_tmp[(size_t)i * DD + c4];
    float4 p = *(const float4*)&g_pe[genre[i] * DD + c4];
    float4 bb = *(const float4*)(fus_b + c4);
    v.x = leakyf(v.x + p.x + bb.x, 0.01f);
    v.y = leakyf(v.y + p.y + bb.y, 0.01f);
    v.z = leakyf(v.z + p.z + bb.z, 0.01f);
    v.w = leakyf(v.w + p.w + bb.w, 0.01f);
    *(float4*)&out[(size_t)movie_idx[i] * DD + c4] = v;
}

// ---------------- launch ----------------
extern "C" void kernel_launch(void* const* d_in, const int* in_sizes, int n_in,
                              void* d_out, int out_size)
{
    const float* x        = (const float*)d_in[0];
    const int*   e[3]     = {(const int*)d_in[1], (const int*)d_in[2], (const int*)d_in[3]};
    const int*   movie_idx = (const int*)d_in[4];
    const int*   genre     = (const int*)d_in[5];
    const float* gat_W    = (const float*)d_in[6];
    const float* att_src  = (const float*)d_in[7];
    const float* att_dst  = (const float*)d_in[8];
    const float* gat_bias = (const float*)d_in[9];
    const float* dec_W    = (const float*)d_in[10];
    const float* dec_b    = (const float*)d_in[11];
    const float* qkv_w    = (const float*)d_in[12];
    const float* qkv_b    = (const float*)d_in[13];
    const float* out_w    = (const float*)d_in[14];
    const float* out_b    = (const float*)d_in[15];
    const float* ln1_g    = (const float*)d_in[16];
    const float* ln1_b    = (const float*)d_in[17];
    const float* ln2_g    = (const float*)d_in[18];
    const float* ln2_b    = (const float*)d_in[19];
    const float* ffn_w1   = (const float*)d_in[20];
    const float* ffn_b1   = (const float*)d_in[21];
    const float* ffn_w2   = (const float*)d_in[22];
    const float* ffn_b2   = (const float*)d_in[23];
    const float* fus_w    = (const float*)d_in[24];
    const float* fus_b    = (const float*)d_in[25];
    float* out = (float*)d_out;

    float *p_h, *p_gout, *p_acc, *p_y, *p_qkv, *p_attn, *p_tmp, *p_ffn, *p_xm;
    cudaGetSymbolAddress((void**)&p_h,    g_h);
    cudaGetSymbolAddress((void**)&p_gout, g_gout);
    cudaGetSymbolAddress((void**)&p_acc,  g_acc);
    cudaGetSymbolAddress((void**)&p_y,    g_y);
    cudaGetSymbolAddress((void**)&p_qkv,  g_qkv);
    cudaGetSymbolAddress((void**)&p_attn, g_attn);
    cudaGetSymbolAddress((void**)&p_tmp,  g_tmp);
    cudaGetSymbolAddress((void**)&p_ffn,  g_ffn);
    cudaGetSymbolAddress((void**)&p_xm,   g_xm);

    // -------- GAT (3 hops, fp32 exact) --------
    zero_acc_kernel<<<(NN * DD / 4 + 255) / 256, 256>>>();
    for (int k = 0; k < 3; k++) {
        dim3 gh((DD + 127) / 128, (NN + 127) / 128);
        gemm128<<<gh, 256>>>(x, gat_W + (size_t)k * DD * DD, nullptr, p_h,
                             NN, DD, DD, DD, 0, 0.f);
        gat_prep_kernel<<<(NN * 32 + 255) / 256, 256>>>(att_src + k * DD, att_dst + k * DD,
                                                        gat_bias + k * DD);
        int items = NE + NN;
        edge_max_kernel<<<(items + 255) / 256, 256>>>(e[k]);
        edge_sum_kernel<<<(items + 255) / 256, 256>>>(e[k]);
        edge_aggr_kernel<<<((size_t)items * 32 + 255) / 256, 256>>>(e[k]);
        float scale = (float)exp(-0.1 * k);
        gemm128<<<gh, 256>>>(p_gout, dec_W + (size_t)k * DD * DD, dec_b + k * DD, p_acc,
                             NN, DD, DD, DD, 2, scale);
    }

    // -------- build genre sequences --------
    hist_kernel<<<NCHUNK, 128>>>(genre);
    scan_kernel<<<1, 32>>>();
    pos_kernel<<<1, 256>>>(genre);
    zero_y_kernel<<<(NM * DD / 4 + 255) / 256, 256>>>();
    gather_kernel<<<(NM * 32 + 255) / 256, 256>>>(movie_idx, genre);

    // -------- transformer (4 layers, tf32 mma.sync GEMMs) --------
    const int MT = (NM + 127) / 128;   // 160
    for (int l = 0; l < NL; l++) {
        gemm_mma<<<dim3(3 * DD / 128, MT), 256>>>(
            p_y, qkv_w + (size_t)l * 3 * DD * DD, qkv_b + l * 3 * DD, p_qkv,
            NM, 3 * DD, DD, DD, DD, 0);
        attn_kernel<<<dim3((LMAX + 127) / 128, NHEADS, NG), 128>>>();
        gemm_mma<<<dim3(1, MT), 256>>>(
            p_attn, out_w + (size_t)l * DD * DD, out_b + l * DD, p_tmp,
            NM, DD, DD, DD, DD, 0);
        ln_kernel<<<(NM * 32 + 255) / 256, 256>>>(p_y, p_tmp, ln1_g + l * DD, ln1_b + l * DD, NM);
        gemm_mma<<<dim3(FFD / 128, MT), 256>>>(
            p_y, ffn_w1 + (size_t)l * FFD * DD, ffn_b1 + l * FFD, p_ffn,
            NM, FFD, DD, DD, DD, 1);
        gemm_mma<<<dim3(1, MT), 256>>>(
            p_ffn, ffn_w2 + (size_t)l * DD * FFD, ffn_b2 + l * DD, p_tmp,
            NM, DD, FFD, FFD, FFD, 0);
        ln_kernel<<<(NM * 32 + 255) / 256, 256>>>(p_y, p_tmp, ln2_g + l * DD, ln2_b + l * DD, NM);
    }

    // -------- pool + fuse + write output --------
    pool_kernel<<<NG, DD>>>();
    pe_kernel<<<NG, DD>>>(fus_w);
    dim3 gfu(1, MT);
    gemm128<<<gfu, 256>>>(p_xm, fus_w, nullptr, p_tmp, NM, DD, DD, 256, 0, 0.f);
    copy_out_kernel<<<(NN * DD / 4 + 255) / 256, 256>>>(out);
    fuse_out_kernel<<<(NM * 32 + 255) / 256, 256>>>(movie_idx, genre, fus_b, out);
}

// round 4
// speedup vs baseline: 1.6725x; 1.2060x over previous
#include <cuda_runtime.h>
#include <math.h>
#include <stdint.h>

#define NN 50000
#define NE 400000
#define DD 128
#define NM 20400
#define NG 30
#define LMAX 680
#define NHEADS 4
#define NL 4
#define FFD 2048
#define NCHUNK 160   // ceil(20400/128)

// ---------------- scratch (device globals; no runtime allocation) ----------------
__device__ __align__(16) float g_h[(size_t)NN * DD];
__device__ __align__(16) float g_gout[(size_t)NN * DD];
__device__ __align__(16) float g_acc[(size_t)NN * DD];
__device__ __align__(16) float g_als[NN * NHEADS];
__device__ __align__(16) float g_ald[NN * NHEADS];
__device__ __align__(16) float g_mx[NN * NHEADS];
__device__ __align__(16) float g_den[NN * NHEADS];
__device__ __align__(16) float g_y[(size_t)NM * DD];
__device__ __align__(16) float g_qkv[(size_t)NM * 3 * DD];
__device__ __align__(16) float g_attn[(size_t)NM * DD];
__device__ __align__(16) float g_tmp[(size_t)NM * DD];
__device__ __align__(16) float g_ffn[(size_t)NM * FFD];
__device__ __align__(16) float g_xm[(size_t)NM * DD];
__device__ __align__(16) float g_pooled[NG * DD];
__device__ __align__(16) float g_pe[NG * DD];
__device__ int g_pos[NM];
__device__ int g_cnt[NG];
__device__ int g_chist[NCHUNK * NG];

// ---------------- small helpers ----------------
__device__ __forceinline__ float leakyf(float x, float s) { return x >= 0.f ? x : s * x; }

__device__ __forceinline__ void atomicMaxF(float* addr, float val) {
    if (!(__float_as_uint(val) >> 31)) {
        atomicMax((int*)addr, __float_as_int(val));
    } else {
        atomicMin((unsigned int*)addr, __float_as_uint(val));
    }
}

__device__ __forceinline__ float dot4(float4 a, float4 b) {
    return a.x * b.x + a.y * b.y + a.z * b.z + a.w * b.w;
}

__device__ __forceinline__ uint32_t f2tf32(float f) {
    uint32_t r;
    asm("cvt.rna.tf32.f32 %0, %1;" : "=r"(r) : "f"(f));
    return r;
}

// ---------------- mma.sync tf32 GEMM: C[M,N] = epi(A[M,K(lda)] * B[N,K(ldb)]^T + bias) ----------------
// epi: 0 = store (+bias if bias), 1 = relu(+bias), 2 = C += scale*leaky_{0.01}(v+bias)
// N multiple of 128, K multiple of 32. grid (N/128, ceil(M/128)), block 256.
// CTA tile 128x128, K-chunk 32. SMEM: padded row-major (stride 36 floats) so that
// all fragment lds.32 and all staging float4 stores are bank-conflict-free.
#define SROW 36
__global__ __launch_bounds__(256) void gemm_mma(
    const float* __restrict__ A, const float* __restrict__ B,
    const float* __restrict__ bias, float* __restrict__ C,
    int M, int N, int K, int lda, int ldb, int epi, float scale)
{
    __shared__ uint32_t As[128 * SROW];
    __shared__ uint32_t Bs[128 * SROW];
    const int tid = threadIdx.x;
    const int wid = tid >> 5, lane = tid & 31;
    const int wm = wid & 1, wn = wid >> 1;       // warp tile: 64 rows x 32 cols
    const int row0 = blockIdx.y * 128, col0 = blockIdx.x * 128;
    const int lq = lane >> 2, lr = lane & 3;     // quad index / col-in-quad

    float acc[4][4][4];
#pragma unroll
    for (int i = 0; i < 4; i++)
#pragma unroll
        for (int j = 0; j < 4; j++) {
            acc[i][j][0] = 0.f; acc[i][j][1] = 0.f;
            acc[i][j][2] = 0.f; acc[i][j][3] = 0.f;
        }

    const int s_row = tid >> 3;                  // staging: 8 threads per row
    const int s_c4 = (tid & 7) * 4;

    for (int k0 = 0; k0 < K; k0 += 32) {
        __syncthreads();
        // ---- stage A chunk (128 rows x 32 k) ----
#pragma unroll
        for (int it = 0; it < 4; it++) {
            int row = it * 32 + s_row;
            float4 v = make_float4(0.f, 0.f, 0.f, 0.f);
            int gr = row0 + row;
            if (gr < M) v = *(const float4*)(A + (size_t)gr * lda + k0 + s_c4);
            uint4 t = make_uint4(f2tf32(v.x), f2tf32(v.y), f2tf32(v.z), f2tf32(v.w));
            *(uint4*)&As[row * SROW + s_c4] = t;
        }
        // ---- stage B chunk (128 n-rows x 32 k) ----
#pragma unroll
        for (int it = 0; it < 4; it++) {
            int row = it * 32 + s_row;
            float4 v = *(const float4*)(B + (size_t)(col0 + row) * ldb + k0 + s_c4);
            uint4 t = make_uint4(f2tf32(v.x), f2tf32(v.y), f2tf32(v.z), f2tf32(v.w));
            *(uint4*)&Bs[row * SROW + s_c4] = t;
        }
        __syncthreads();
        // ---- compute: 4 ksteps x (4 mtiles x 4 ntiles) mma ----
#pragma unroll
        for (int ks = 0; ks < 4; ks++) {
            int kk = ks * 8 + lr;
            uint2 bf[4];
#pragma unroll
            for (int nt = 0; nt < 4; nt++) {
                int n = wn * 32 + nt * 8 + lq;
                bf[nt].x = Bs[n * SROW + kk];
                bf[nt].y = Bs[n * SROW + kk + 4];
            }
#pragma unroll
            for (int mt = 0; mt < 4; mt++) {
                int r = wm * 64 + mt * 16 + lq;
                uint32_t a0 = As[r * SROW + kk];
                uint32_t a1 = As[(r + 8) * SROW + kk];
                uint32_t a2 = As[r * SROW + kk + 4];
                uint32_t a3 = As[(r + 8) * SROW + kk + 4];
#pragma unroll
                for (int nt = 0; nt < 4; nt++) {
                    asm volatile(
                        "mma.sync.aligned.m16n8k8.row.col.f32.tf32.tf32.f32 "
                        "{%0,%1,%2,%3}, {%4,%5,%6,%7}, {%8,%9}, {%0,%1,%2,%3};"
                        : "+f"(acc[mt][nt][0]), "+f"(acc[mt][nt][1]),
                          "+f"(acc[mt][nt][2]), "+f"(acc[mt][nt][3])
                        : "r"(a0), "r"(a1), "r"(a2), "r"(a3),
                          "r"(bf[nt].x), "r"(bf[nt].y));
                }
            }
        }
    }

    // ---- epilogue ----
    const int rbase = row0 + wm * 64;
    const int cbase = col0 + wn * 32;
#pragma unroll
    for (int mt = 0; mt < 4; mt++) {
        int r0 = rbase + mt * 16 + lq;
#pragma unroll
        for (int half = 0; half < 2; half++) {
            int r = r0 + half * 8;
            if (r < M) {
#pragma unroll
                for (int nt = 0; nt < 4; nt++) {
                    int c = cbase + nt * 8 + lr * 2;
                    float v0 = acc[mt][nt][half * 2 + 0];
                    float v1 = acc[mt][nt][half * 2 + 1];
                    if (bias) { v0 += bias[c]; v1 += bias[c + 1]; }
                    float* cp = C + (size_t)r * N + c;
                    if (epi == 0) {
                        *(float2*)cp = make_float2(v0, v1);
                    } else if (epi == 1) {
                        *(float2*)cp = make_float2(fmaxf(v0, 0.f), fmaxf(v1, 0.f));
                    } else {
                        float2 o = *(float2*)cp;
                        o.x += scale * leakyf(v0, 0.01f);
                        o.y += scale * leakyf(v1, 0.01f);
                        *(float2*)cp = o;
                    }
                }
            }
        }
    }
}

// ---------------- GAT kernels ----------------
__global__ void zero_acc_kernel() {
    size_t i = (size_t)blockIdx.x * blockDim.x + threadIdx.x;
    if (i < (size_t)NN * DD / 4) ((float4*)g_acc)[i] = make_float4(0.f, 0.f, 0.f, 0.f);
}
__global__ void zero_y_kernel() {
    size_t i = (size_t)blockIdx.x * blockDim.x + threadIdx.x;
    if (i < (size_t)NM * DD / 4) ((float4*)g_y)[i] = make_float4(0.f, 0.f, 0.f, 0.f);
}

__global__ void gat_prep_kernel(const float* __restrict__ a_src,
                                const float* __restrict__ a_dst,
                                const float* __restrict__ bias)
{
    int gid = blockIdx.x * blockDim.x + threadIdx.x;
    int node = gid >> 5, lane = gid & 31;
    if (node >= NN) return;
    float s[4], d[4];
#pragma unroll
    for (int j = 0; j < 4; j++) {
        int c = j * 32 + lane;
        float hv = g_h[(size_t)node * DD + c];
        s[j] = hv * a_src[c];
        d[j] = hv * a_dst[c];
        g_gout[(size_t)node * DD + c] = bias[c];
    }
#pragma unroll
    for (int j = 0; j < 4; j++)
#pragma unroll
        for (int o = 16; o > 0; o >>= 1) {
            s[j] += __shfl_xor_sync(0xffffffffu, s[j], o);
            d[j] += __shfl_xor_sync(0xffffffffu, d[j], o);
        }
    if (lane == 0) {
        *(float4*)&g_als[node * 4] = make_float4(s[0], s[1], s[2], s[3]);
        *(float4*)&g_ald[node * 4] = make_float4(d[0], d[1], d[2], d[3]);
        *(float4*)&g_mx[node * 4] = make_float4(-INFINITY, -INFINITY, -INFINITY, -INFINITY);
        *(float4*)&g_den[node * 4] = make_float4(0.f, 0.f, 0.f, 0.f);
    }
}

__global__ void edge_max_kernel(const int* __restrict__ ei) {
    int t = blockIdx.x * blockDim.x + threadIdx.x;
    if (t >= NE + NN) return;
    int src, dst;
    if (t < NE) { src = ei[t]; dst = ei[NE + t]; }
    else { src = dst = t - NE; }
    float4 a = *(const float4*)&g_als[src * 4];
    float4 b = *(const float4*)&g_ald[dst * 4];
    atomicMaxF(&g_mx[dst * 4 + 0], leakyf(a.x + b.x, 0.2f));
    atomicMaxF(&g_mx[dst * 4 + 1], leakyf(a.y + b.y, 0.2f));
    atomicMaxF(&g_mx[dst * 4 + 2], leakyf(a.z + b.z, 0.2f));
    atomicMaxF(&g_mx[dst * 4 + 3], leakyf(a.w + b.w, 0.2f));
}

__global__ void edge_sum_kernel(const int* __restrict__ ei) {
    int t = blockIdx.x * blockDim.x + threadIdx.x;
    if (t >= NE + NN) return;
    int src, dst;
    if (t < NE) { src = ei[t]; dst = ei[NE + t]; }
    else { src = dst = t - NE; }
    float4 a = *(const float4*)&g_als[src * 4];
    float4 b = *(const float4*)&g_ald[dst * 4];
    float4 m = *(const float4*)&g_mx[dst * 4];
    atomicAdd(&g_den[dst * 4 + 0], expf(leakyf(a.x + b.x, 0.2f) - m.x));
    atomicAdd(&g_den[dst * 4 + 1], expf(leakyf(a.y + b.y, 0.2f) - m.y));
    atomicAdd(&g_den[dst * 4 + 2], expf(leakyf(a.z + b.z, 0.2f) - m.z));
    atomicAdd(&g_den[dst * 4 + 3], expf(leakyf(a.w + b.w, 0.2f) - m.w));
}

__global__ void edge_aggr_kernel(const int* __restrict__ ei) {
    int gid = blockIdx.x * blockDim.x + threadIdx.x;
    int item = gid >> 5, lane = gid & 31;
    if (item >= NE + NN) return;
    int src, dst;
    if (item < NE) { src = ei[item]; dst = ei[NE + item]; }
    else { src = dst = item - NE; }
    float4 a = *(const float4*)&g_als[src * 4];
    float4 b = *(const float4*)&g_ald[dst * 4];
    float4 m = *(const float4*)&g_mx[dst * 4];
    float4 dn = *(const float4*)&g_den[dst * 4];
    float al[4];
    al[0] = expf(leakyf(a.x + b.x, 0.2f) - m.x) / dn.x;
    al[1] = expf(leakyf(a.y + b.y, 0.2f) - m.y) / dn.y;
    al[2] = expf(leakyf(a.z + b.z, 0.2f) - m.z) / dn.z;
    al[3] = expf(leakyf(a.w + b.w, 0.2f) - m.w) / dn.w;
#pragma unroll
    for (int j = 0; j < 4; j++) {
        int c = j * 32 + lane;
        float v = g_h[(size_t)src * DD + c] * al[j];
        atomicAdd(&g_gout[(size_t)dst * DD + c], v);
    }
}

// ---------------- position / count kernels ----------------
__global__ void hist_kernel(const int* __restrict__ genre) {
    __shared__ int loc[NG];
    if (threadIdx.x < NG) loc[threadIdx.x] = 0;
    __syncthreads();
    int i = blockIdx.x * 128 + threadIdx.x;
    if (i < NM) atomicAdd(&loc[genre[i]], 1);
    __syncthreads();
    if (threadIdx.x < NG) g_chist[blockIdx.x * NG + threadIdx.x] = loc[threadIdx.x];
}
__global__ void scan_kernel() {
    int g = threadIdx.x;
    if (g >= NG) return;
    int run = 0;
    for (int c = 0; c < NCHUNK; c++) {
        int t = g_chist[c * NG + g];
        g_chist[c * NG + g] = run;
        run += t;
    }
    g_cnt[g] = run;
}
__global__ void pos_kernel(const int* __restrict__ genre) {
    int c = blockIdx.x * blockDim.x + threadIdx.x;
    if (c >= NCHUNK) return;
    int off[NG];
    for (int g = 0; g < NG; g++) off[g] = g_chist[c * NG + g];
    int base = c * 128;
    int end = base + 128; if (end > NM) end = NM;
    for (int i = base; i < end; i++) {
        int g = genre[i];
        g_pos[i] = off[g]++;
    }
}

__global__ void gather_kernel(const int* __restrict__ movie_idx, const int* __restrict__ genre) {
    int t = blockIdx.x * blockDim.x + threadIdx.x;
    if (t >= NM * 32) return;
    int i = t >> 5, c4 = (t & 31) * 4;
    float4 v = *(const float4*)&g_acc[(size_t)movie_idx[i] * DD + c4];
    *(float4*)&g_xm[(size_t)i * DD + c4] = v;
    int row = genre[i] * LMAX + g_pos[i];
    *(float4*)&g_y[(size_t)row * DD + c4] = v;
}

// ---------------- attention (flash-style, thread per query) ----------------
__global__ __launch_bounds__(128) void attn_kernel() {
    __shared__ float Ks[64 * 32];
    __shared__ float Vs[64 * 32];
    int b = blockIdx.z, h = blockIdx.y;
    int q = blockIdx.x * 128 + threadIdx.x;
    int S = g_cnt[b];
    bool active = q < LMAX;

    float4 qv4[8];
    if (active) {
        const float* qp = g_qkv + (size_t)(b * LMAX + q) * 3 * DD + h * 32;
#pragma unroll
        for (int d4 = 0; d4 < 8; d4++) qv4[d4] = *(const float4*)(qp + d4 * 4);
    }
    float m = -INFINITY, den = 0.f;
    float4 ov4[8];
#pragma unroll
    for (int d4 = 0; d4 < 8; d4++) ov4[d4] = make_float4(0.f, 0.f, 0.f, 0.f);

    for (int kb = 0; kb < LMAX; kb += 64) {
        int nk = LMAX - kb; if (nk > 64) nk = 64;
        for (int idx = threadIdx.x; idx < 64 * 8; idx += 128) {
            int s = idx >> 3;
            int d4 = (idx & 7) * 4;
            float4 kv = make_float4(0.f, 0.f, 0.f, 0.f);
            float4 vv = make_float4(0.f, 0.f, 0.f, 0.f);
            if (s < nk) {
                const float* base = g_qkv + (size_t)(b * LMAX + kb + s) * 3 * DD;
                kv = *(const float4*)(base + DD + h * 32 + d4);
                vv = *(const float4*)(base + 2 * DD + h * 32 + d4);
            }
            *(float4*)&Ks[s * 32 + d4] = kv;
            *(float4*)&Vs[s * 32 + d4] = vv;
        }
        __syncthreads();
        if (active) {
            int ns = S - kb; if (ns > 64) ns = 64;
            for (int s = 0; s < ns; s++) {
                const float4* kp = (const float4*)&Ks[s * 32];
                float sc = 0.f;
#pragma unroll
                for (int d4 = 0; d4 < 8; d4++) sc += dot4(qv4[d4], kp[d4]);
                sc *= 0.17677669529663687f;
                const float4* vp = (const float4*)&Vs[s * 32];
                if (sc > m) {
                    float corr = __expf(m - sc);
                    m = sc;
                    den = den * corr + 1.f;
#pragma unroll
                    for (int d4 = 0; d4 < 8; d4++) {
                        float4 v4 = vp[d4];
                        ov4[d4].x = fmaf(ov4[d4].x, corr, v4.x);
                        ov4[d4].y = fmaf(ov4[d4].y, corr, v4.y);
                        ov4[d4].z = fmaf(ov4[d4].z, corr, v4.z);
                        ov4[d4].w = fmaf(ov4[d4].w, corr, v4.w);
                    }
                } else {
                    float p = __expf(sc - m);
                    den += p;
#pragma unroll
                    for (int d4 = 0; d4 < 8; d4++) {
                        float4 v4 = vp[d4];
                        ov4[d4].x = fmaf(p, v4.x, ov4[d4].x);
                        ov4[d4].y = fmaf(p, v4.y, ov4[d4].y);
                        ov4[d4].z = fmaf(p, v4.z, ov4[d4].z);
                        ov4[d4].w = fmaf(p, v4.w, ov4[d4].w);
                    }
                }
            }
        }
        __syncthreads();
    }
    if (active) {
        float inv = 1.f / den;
        float* op = g_attn + (size_t)(b * LMAX + q) * DD + h * 32;
#pragma unroll
        for (int d4 = 0; d4 < 8; d4++) {
            float4 o = make_float4(ov4[d4].x * inv, ov4[d4].y * inv,
                                   ov4[d4].z * inv, ov4[d4].w * inv);
            *(float4*)(op + d4 * 4) = o;
        }
    }
}

// ---------------- LayerNorm (fused residual): y = LN(y + t) ----------------
__global__ void ln_kernel(float* __restrict__ y, const float* __restrict__ t,
                          const float* __restrict__ gam, const float* __restrict__ bet,
                          int rows)
{
    int gid = blockIdx.x * blockDim.x + threadIdx.x;
    int row = gid >> 5, lane = gid & 31;
    if (row >= rows) return;
    size_t off = (size_t)row * DD + lane * 4;
    float4 v = *(float4*)(y + off);
    float4 tv = *(const float4*)(t + off);
    v.x += tv.x; v.y += tv.y; v.z += tv.z; v.w += tv.w;
    float s = v.x + v.y + v.z + v.w;
#pragma unroll
    for (int o = 16; o > 0; o >>= 1) s += __shfl_xor_sync(0xffffffffu, s, o);
    float mean = s * (1.f / DD);
    float dx = v.x - mean, dy = v.y - mean, dz = v.z - mean, dw = v.w - mean;
    float ss = dx * dx + dy * dy + dz * dz + dw * dw;
#pragma unroll
    for (int o = 16; o > 0; o >>= 1) ss += __shfl_xor_sync(0xffffffffu, ss, o);
    float inv = rsqrtf(ss * (1.f / DD) + 1e-5f);
    float4 gg = *(const float4*)(gam + lane * 4);
    float4 bb = *(const float4*)(bet + lane * 4);
    v.x = dx * inv * gg.x + bb.x;
    v.y = dy * inv * gg.y + bb.y;
    v.z = dz * inv * gg.z + bb.z;
    v.w = dw * inv * gg.w + bb.w;
    *(float4*)(y + off) = v;
}

// ---------------- pooling / fusion ----------------
__global__ void pool_kernel() {
    int g = blockIdx.x, d = threadIdx.x;
    int cnt = g_cnt[g];
    float s = 0.f;
    for (int t = 0; t < cnt; t++) s += g_y[(size_t)(g * LMAX + t) * DD + d];
    g_pooled[g * DD + d] = s / fmaxf((float)cnt, 1.f);
}

__global__ void pe_kernel(const float* __restrict__ fus_w) {
    int g = blockIdx.x, n = threadIdx.x;
    float s = 0.f;
    for (int k = 0; k < DD; k++)
        s += g_pooled[g * DD + k] * fus_w[n * 256 + 128 + k];
    g_pe[g * DD + n] = s;
}

__global__ void copy_out_kernel(float* __restrict__ out) {
    size_t i = (size_t)blockIdx.x * blockDim.x + threadIdx.x;
    if (i < (size_t)NN * DD / 4) ((float4*)out)[i] = ((const float4*)g_acc)[i];
}

__global__ void fuse_out_kernel(const int* __restrict__ movie_idx, const int* __restrict__ genre,
                                const float* __restrict__ fus_b, float* __restrict__ out)
{
    int t = blockIdx.x * blockDim.x + threadIdx.x;
    if (t >= NM * 32) return;
    int i = t >> 5, c4 = (t & 31) * 4;
    float4 v = *(const float4*)&g_tmp[(size_t)i * DD + c4];
    float4 p = *(const float4*)&g_pe[genre[i] * DD + c4];
    float4 bb = *(const float4*)(fus_b + c4);
    v.x = leakyf(v.x + p.x + bb.x, 0.01f);
    v.y = leakyf(v.y + p.y + bb.y, 0.01f);
    v.z = leakyf(v.z + p.z + bb.z, 0.01f);
    v.w = leakyf(v.w + p.w + bb.w, 0.01f);
    *(float4*)&out[(size_t)movie_idx[i] * DD + c4] = v;
}

// ---------------- launch ----------------
extern "C" void kernel_launch(void* const* d_in, const int* in_sizes, int n_in,
                              void* d_out, int out_size)
{
    const float* x        = (const float*)d_in[0];
    const int*   e[3]     = {(const int*)d_in[1], (const int*)d_in[2], (const int*)d_in[3]};
    const int*   movie_idx = (const int*)d_in[4];
    const int*   genre     = (const int*)d_in[5];
    const float* gat_W    = (const float*)d_in[6];
    const float* att_src  = (const float*)d_in[7];
    const float* att_dst  = (const float*)d_in[8];
    const float* gat_bias = (const float*)d_in[9];
    const float* dec_W    = (const float*)d_in[10];
    const float* dec_b    = (const float*)d_in[11];
    const float* qkv_w    = (const float*)d_in[12];
    const float* qkv_b    = (const float*)d_in[13];
    const float* out_w    = (const float*)d_in[14];
    const float* out_b    = (const float*)d_in[15];
    const float* ln1_g    = (const float*)d_in[16];
    const float* ln1_b    = (const float*)d_in[17];
    const float* ln2_g    = (const float*)d_in[18];
    const float* ln2_b    = (const float*)d_in[19];
    const float* ffn_w1   = (const float*)d_in[20];
    const float* ffn_b1   = (const float*)d_in[21];
    const float* ffn_w2   = (const float*)d_in[22];
    const float* ffn_b2   = (const float*)d_in[23];
    const float* fus_w    = (const float*)d_in[24];
    const float* fus_b    = (const float*)d_in[25];
    float* out = (float*)d_out;

    float *p_h, *p_gout, *p_acc, *p_y, *p_qkv, *p_attn, *p_tmp, *p_ffn, *p_xm;
    cudaGetSymbolAddress((void**)&p_h,    g_h);
    cudaGetSymbolAddress((void**)&p_gout, g_gout);
    cudaGetSymbolAddress((void**)&p_acc,  g_acc);
    cudaGetSymbolAddress((void**)&p_y,    g_y);
    cudaGetSymbolAddress((void**)&p_qkv,  g_qkv);
    cudaGetSymbolAddress((void**)&p_attn, g_attn);
    cudaGetSymbolAddress((void**)&p_tmp,  g_tmp);
    cudaGetSymbolAddress((void**)&p_ffn,  g_ffn);
    cudaGetSymbolAddress((void**)&p_xm,   g_xm);

    const int MTN = (NN + 127) / 128;  // 391
    const int MT  = (NM + 127) / 128;  // 160

    // -------- GAT (3 hops, tf32 GEMMs + fp32 edge softmax) --------
    zero_acc_kernel<<<(NN * DD / 4 + 255) / 256, 256>>>();
    for (int k = 0; k < 3; k++) {
        gemm_mma<<<dim3(1, MTN), 256>>>(x, gat_W + (size_t)k * DD * DD, nullptr, p_h,
                                        NN, DD, DD, DD, DD, 0, 0.f);
        gat_prep_kernel<<<(NN * 32 + 255) / 256, 256>>>(att_src + k * DD, att_dst + k * DD,
                                                        gat_bias + k * DD);
        int items = NE + NN;
        edge_max_kernel<<<(items + 255) / 256, 256>>>(e[k]);
        edge_sum_kernel<<<(items + 255) / 256, 256>>>(e[k]);
        edge_aggr_kernel<<<((size_t)items * 32 + 255) / 256, 256>>>(e[k]);
        float scale = (float)exp(-0.1 * k);
        gemm_mma<<<dim3(1, MTN), 256>>>(p_gout, dec_W + (size_t)k * DD * DD, dec_b + k * DD,
                                        p_acc, NN, DD, DD, DD, DD, 2, scale);
    }

    // -------- build genre sequences --------
    hist_kernel<<<NCHUNK, 128>>>(genre);
    scan_kernel<<<1, 32>>>();
    pos_kernel<<<1, 256>>>(genre);
    zero_y_kernel<<<(NM * DD / 4 + 255) / 256, 256>>>();
    gather_kernel<<<(NM * 32 + 255) / 256, 256>>>(movie_idx, genre);

    // -------- transformer (4 layers, tf32 mma GEMMs) --------
    for (int l = 0; l < NL; l++) {
        gemm_mma<<<dim3(3 * DD / 128, MT), 256>>>(
            p_y, qkv_w + (size_t)l * 3 * DD * DD, qkv_b + l * 3 * DD, p_qkv,
            NM, 3 * DD, DD, DD, DD, 0, 0.f);
        attn_kernel<<<dim3((LMAX + 127) / 128, NHEADS, NG), 128>>>();
        gemm_mma<<<dim3(1, MT), 256>>>(
            p_attn, out_w + (size_t)l * DD * DD, out_b + l * DD, p_tmp,
            NM, DD, DD, DD, DD, 0, 0.f);
        ln_kernel<<<(NM * 32 + 255) / 256, 256>>>(p_y, p_tmp, ln1_g + l * DD, ln1_b + l * DD, NM);
        gemm_mma<<<dim3(FFD / 128, MT), 256>>>(
            p_y, ffn_w1 + (size_t)l * FFD * DD, ffn_b1 + l * FFD, p_ffn,
            NM, FFD, DD, DD, DD, 1, 0.f);
        gemm_mma<<<dim3(1, MT), 256>>>(
            p_ffn, ffn_w2 + (size_t)l * DD * FFD, ffn_b2 + l * DD, p_tmp,
            NM, DD, FFD, FFD, FFD, 0, 0.f);
        ln_kernel<<<(NM * 32 + 255) / 256, 256>>>(p_y, p_tmp, ln2_g + l * DD, ln2_b + l * DD, NM);
    }

    // -------- pool + fuse + write output --------
    pool_kernel<<<NG, DD>>>();
    pe_kernel<<<NG, DD>>>(fus_w);
    gemm_mma<<<dim3(1, MT), 256>>>(p_xm, fus_w, nullptr, p_tmp,
                                   NM, DD, DD, DD, 256, 0, 0.f);
    copy_out_kernel<<<(NN * DD / 4 + 255) / 256, 256>>>(out);
    fuse_out_kernel<<<(NM * 32 + 255) / 256, 256>>>(movie_idx, genre, fus_b, out);
}

// round 5
// speedup vs baseline: 2.4955x; 1.4920x over previous
#include <cuda_runtime.h>
#include <math.h>
#include <stdint.h>

#define NN 50000
#define NE 400000
#define DD 128
#define NM 20400
#define NG 30
#define LMAX 680
#define NHEADS 4
#define NL 4
#define FFD 2048
#define NCHUNK 160   // ceil(20400/128)

// ---------------- scratch (device globals; no runtime allocation) ----------------
__device__ __align__(16) float g_h[(size_t)NN * DD];
__device__ __align__(16) float g_gout[(size_t)NN * DD];
__device__ __align__(16) float g_acc[(size_t)NN * DD];
__device__ __align__(16) float g_als[NN * NHEADS];
__device__ __align__(16) float g_ald[NN * NHEADS];
__device__ __align__(16) float g_mx[NN * NHEADS];
__device__ __align__(16) float g_den[NN * NHEADS];
__device__ __align__(16) float g_y[(size_t)NM * DD];
__device__ __align__(16) float g_qkv[(size_t)NM * 3 * DD];
__device__ __align__(16) float g_attn[(size_t)NM * DD];
__device__ __align__(16) float g_tmp[(size_t)NM * DD];
__device__ __align__(16) float g_ffn[(size_t)NM * FFD];
__device__ __align__(16) float g_xm[(size_t)NM * DD];
__device__ __align__(16) float g_pooled[NG * DD];
__device__ __align__(16) float g_pe[NG * DD];
__device__ int g_pos[NM];
__device__ int g_cnt[NG];
__device__ int g_chist[NCHUNK * NG];

// ---------------- small helpers ----------------
__device__ __forceinline__ float leakyf(float x, float s) { return x >= 0.f ? x : s * x; }

__device__ __forceinline__ void atomicMaxF(float* addr, float val) {
    if (!(__float_as_uint(val) >> 31)) {
        atomicMax((int*)addr, __float_as_int(val));
    } else {
        atomicMin((unsigned int*)addr, __float_as_uint(val));
    }
}

__device__ __forceinline__ float dot4(float4 a, float4 b) {
    return a.x * b.x + a.y * b.y + a.z * b.z + a.w * b.w;
}

__device__ __forceinline__ uint32_t f2tf32(float f) {
    uint32_t r;
    asm("cvt.rna.tf32.f32 %0, %1;" : "=r"(r) : "f"(f));
    return r;
}

__device__ __forceinline__ void mma8(float* c, uint32_t a0, uint32_t a1, uint32_t a2,
                                     uint32_t a3, uint32_t b0, uint32_t b1) {
    asm volatile(
        "mma.sync.aligned.m16n8k8.row.col.f32.tf32.tf32.f32 "
        "{%0,%1,%2,%3}, {%4,%5,%6,%7}, {%8,%9}, {%0,%1,%2,%3};"
        : "+f"(c[0]), "+f"(c[1]), "+f"(c[2]), "+f"(c[3])
        : "r"(a0), "r"(a1), "r"(a2), "r"(a3), "r"(b0), "r"(b1));
}

// ---------------- mma.sync tf32 GEMM: C[M,N] = epi(A[M,K(lda)] * B[N,K(ldb)]^T + bias) ----------------
// epi: 0 = store (+bias if bias), 1 = relu(+bias), 2 = C += scale*leaky_{0.01}(v+bias)
// N multiple of 128, K multiple of 32. grid (N/128, ceil(M/128)), block 256.
// Register-prefetched: GMEM loads for chunk c+1 issued before compute of chunk c.
#define SROW 36
__global__ __launch_bounds__(256) void gemm_mma(
    const float* __restrict__ A, const float* __restrict__ B,
    const float* __restrict__ bias, float* __restrict__ C,
    int M, int N, int K, int lda, int ldb, int epi, float scale)
{
    __shared__ uint32_t As[128 * SROW];
    __shared__ uint32_t Bs[128 * SROW];
    const int tid = threadIdx.x;
    const int wid = tid >> 5, lane = tid & 31;
    const int wm = wid & 1, wn = wid >> 1;       // warp tile: 64 rows x 32 cols
    const int row0 = blockIdx.y * 128, col0 = blockIdx.x * 128;
    const int lq = lane >> 2, lr = lane & 3;

    float acc[4][4][4];
#pragma unroll
    for (int i = 0; i < 4; i++)
#pragma unroll
        for (int j = 0; j < 4; j++) {
            acc[i][j][0] = 0.f; acc[i][j][1] = 0.f;
            acc[i][j][2] = 0.f; acc[i][j][3] = 0.f;
        }

    const int s_row = tid >> 3;                  // staging: 8 threads per row
    const int s_c4 = (tid & 7) * 4;
    const int nC = K >> 5;

    float4 pa[4], pb[4];
    // prefetch chunk 0
#pragma unroll
    for (int it = 0; it < 4; it++) {
        int row = it * 32 + s_row;
        int gr = row0 + row;
        pa[it] = make_float4(0.f, 0.f, 0.f, 0.f);
        if (gr < M) pa[it] = *(const float4*)(A + (size_t)gr * lda + s_c4);
        pb[it] = *(const float4*)(B + (size_t)(col0 + row) * ldb + s_c4);
    }

    for (int c = 0; c < nC; c++) {
        if (c > 0) __syncthreads();
        // store prefetched regs -> smem (tf32)
#pragma unroll
        for (int it = 0; it < 4; it++) {
            int row = it * 32 + s_row;
            *(uint4*)&As[row * SROW + s_c4] =
                make_uint4(f2tf32(pa[it].x), f2tf32(pa[it].y), f2tf32(pa[it].z), f2tf32(pa[it].w));
            *(uint4*)&Bs[row * SROW + s_c4] =
                make_uint4(f2tf32(pb[it].x), f2tf32(pb[it].y), f2tf32(pb[it].z), f2tf32(pb[it].w));
        }
        __syncthreads();
        // prefetch chunk c+1 (overlaps compute below)
        if (c + 1 < nC) {
            int k0 = (c + 1) << 5;
#pragma unroll
            for (int it = 0; it < 4; it++) {
                int row = it * 32 + s_row;
                int gr = row0 + row;
                pa[it] = make_float4(0.f, 0.f, 0.f, 0.f);
                if (gr < M) pa[it] = *(const float4*)(A + (size_t)gr * lda + k0 + s_c4);
                pb[it] = *(const float4*)(B + (size_t)(col0 + row) * ldb + k0 + s_c4);
            }
        }
        // compute chunk c
#pragma unroll
        for (int ks = 0; ks < 4; ks++) {
            int kk = ks * 8 + lr;
            uint2 bf[4];
#pragma unroll
            for (int nt = 0; nt < 4; nt++) {
                int n = wn * 32 + nt * 8 + lq;
                bf[nt].x = Bs[n * SROW + kk];
                bf[nt].y = Bs[n * SROW + kk + 4];
            }
#pragma unroll
            for (int mt = 0; mt < 4; mt++) {
                int r = wm * 64 + mt * 16 + lq;
                uint32_t a0 = As[r * SROW + kk];
                uint32_t a1 = As[(r + 8) * SROW + kk];
                uint32_t a2 = As[r * SROW + kk + 4];
                uint32_t a3 = As[(r + 8) * SROW + kk + 4];
#pragma unroll
                for (int nt = 0; nt < 4; nt++)
                    mma8(acc[mt][nt], a0, a1, a2, a3, bf[nt].x, bf[nt].y);
            }
        }
    }

    // ---- epilogue ----
    const int rbase = row0 + wm * 64;
    const int cbase = col0 + wn * 32;
#pragma unroll
    for (int mt = 0; mt < 4; mt++) {
        int r0 = rbase + mt * 16 + lq;
#pragma unroll
        for (int half = 0; half < 2; half++) {
            int r = r0 + half * 8;
            if (r < M) {
#pragma unroll
                for (int nt = 0; nt < 4; nt++) {
                    int c = cbase + nt * 8 + lr * 2;
                    float v0 = acc[mt][nt][half * 2 + 0];
                    float v1 = acc[mt][nt][half * 2 + 1];
                    if (bias) { v0 += bias[c]; v1 += bias[c + 1]; }
                    float* cp = C + (size_t)r * N + c;
                    if (epi == 0) {
                        *(float2*)cp = make_float2(v0, v1);
                    } else if (epi == 1) {
                        *(float2*)cp = make_float2(fmaxf(v0, 0.f), fmaxf(v1, 0.f));
                    } else {
                        float2 o = *(float2*)cp;
                        o.x += scale * leakyf(v0, 0.01f);
                        o.y += scale * leakyf(v1, 0.01f);
                        *(float2*)cp = o;
                    }
                }
            }
        }
    }
}

// ---------------- tensor-core flash attention ----------------
// grid (6 qtiles, NHEADS, NG), block 256 (8 warps x 16 query rows).
// Per 128-key block: S = Q·K^T (mma), quad-shfl online softmax, O += P·V (mma).
#define QKS 36
#define VTS 132
__global__ __launch_bounds__(256) void attn_tc() {
    __shared__ uint32_t QK[128 * QKS];   // Q first, then reused for K blocks
    __shared__ uint32_t VT[32 * VTS];    // V transposed [dim][key], tf32
    const int b = blockIdx.z, h = blockIdx.y, qt = blockIdx.x;
    const int cnt = g_cnt[b];
    const int tid = threadIdx.x, wid = tid >> 5, lane = tid & 31;
    const int lq = lane >> 2, lr = lane & 3;
    const float qscale = 0.17677669529663687f;   // 1/sqrt(32)

    // ---- stage Q (scaled, tf32) ----
#pragma unroll
    for (int it = 0; it < 4; it++) {
        int idx = it * 256 + tid;
        int row = idx >> 3, c4 = (idx & 7) * 4;
        int q = qt * 128 + row;
        float4 v = make_float4(0.f, 0.f, 0.f, 0.f);
        if (q < LMAX) v = *(const float4*)(g_qkv + (size_t)(b * LMAX + q) * 384 + h * 32 + c4);
        *(uint4*)&QK[row * QKS + c4] = make_uint4(
            f2tf32(v.x * qscale), f2tf32(v.y * qscale),
            f2tf32(v.z * qscale), f2tf32(v.w * qscale));
    }
    __syncthreads();
    // ---- Q A-fragments to registers ----
    uint32_t qa[4][4];
    {
        int r = wid * 16 + lq;
#pragma unroll
        for (int ks = 0; ks < 4; ks++) {
            int kk = ks * 8 + lr;
            qa[ks][0] = QK[r * QKS + kk];
            qa[ks][1] = QK[(r + 8) * QKS + kk];
            qa[ks][2] = QK[r * QKS + kk + 4];
            qa[ks][3] = QK[(r + 8) * QKS + kk + 4];
        }
    }

    float m0 = -INFINITY, m1 = -INFINITY, den0 = 0.f, den1 = 0.f;
    float of[4][4];
#pragma unroll
    for (int nt = 0; nt < 4; nt++) {
        of[nt][0] = 0.f; of[nt][1] = 0.f; of[nt][2] = 0.f; of[nt][3] = 0.f;
    }

    for (int kb = 0; kb < LMAX; kb += 128) {
        __syncthreads();   // prior reads of QK/VT complete
        // ---- stage K (tf32) + V^T (tf32) ----
#pragma unroll
        for (int it = 0; it < 4; it++) {
            int idx = it * 256 + tid;
            int row = idx >> 3, c4 = (idx & 7) * 4;
            int key = kb + row;
            float4 kv = make_float4(0.f, 0.f, 0.f, 0.f);
            float4 vv = make_float4(0.f, 0.f, 0.f, 0.f);
            if (key < LMAX) {
                const float* base = g_qkv + (size_t)(b * LMAX + key) * 384 + h * 32;
                kv = *(const float4*)(base + 128 + c4);
                vv = *(const float4*)(base + 256 + c4);
            }
            *(uint4*)&QK[row * QKS + c4] = make_uint4(
                f2tf32(kv.x), f2tf32(kv.y), f2tf32(kv.z), f2tf32(kv.w));
            VT[(c4 + 0) * VTS + row] = f2tf32(vv.x);
            VT[(c4 + 1) * VTS + row] = f2tf32(vv.y);
            VT[(c4 + 2) * VTS + row] = f2tf32(vv.z);
            VT[(c4 + 3) * VTS + row] = f2tf32(vv.w);
        }
        __syncthreads();

        // ---- S = Q·K^T : sf[16 key-tiles][4] ----
        float sf[16][4];
#pragma unroll
        for (int nt = 0; nt < 16; nt++) {
            sf[nt][0] = 0.f; sf[nt][1] = 0.f; sf[nt][2] = 0.f; sf[nt][3] = 0.f;
        }
#pragma unroll
        for (int ks = 0; ks < 4; ks++) {
            int kk = ks * 8 + lr;
#pragma unroll
            for (int nt = 0; nt < 16; nt++) {
                uint32_t b0 = QK[(nt * 8 + lq) * QKS + kk];
                uint32_t b1 = QK[(nt * 8 + lq) * QKS + kk + 4];
                mma8(sf[nt], qa[ks][0], qa[ks][1], qa[ks][2], qa[ks][3], b0, b1);
            }
        }
        // ---- mask + block row-max ----
        float bm0 = -INFINITY, bm1 = -INFINITY;
#pragma unroll
        for (int nt = 0; nt < 16; nt++) {
            int c = kb + nt * 8 + lr * 2;
            if (c >= cnt) { sf[nt][0] = -1e30f; sf[nt][2] = -1e30f; }
            if (c + 1 >= cnt) { sf[nt][1] = -1e30f; sf[nt][3] = -1e30f; }
            bm0 = fmaxf(bm0, fmaxf(sf[nt][0], sf[nt][1]));
            bm1 = fmaxf(bm1, fmaxf(sf[nt][2], sf[nt][3]));
        }
        bm0 = fmaxf(bm0, __shfl_xor_sync(0xffffffffu, bm0, 1));
        bm0 = fmaxf(bm0, __shfl_xor_sync(0xffffffffu, bm0, 2));
        bm1 = fmaxf(bm1, __shfl_xor_sync(0xffffffffu, bm1, 1));
        bm1 = fmaxf(bm1, __shfl_xor_sync(0xffffffffu, bm1, 2));
        float nm0 = fmaxf(m0, bm0), nm1 = fmaxf(m1, bm1);
        float cor0 = __expf(m0 - nm0), cor1 = __expf(m1 - nm1);
        m0 = nm0; m1 = nm1;
        // ---- exp + row sum + tf32 P ----
        float s0 = 0.f, s1 = 0.f;
        uint32_t pf[16][4];
#pragma unroll
        for (int nt = 0; nt < 16; nt++) {
            float p0 = __expf(sf[nt][0] - nm0), p1 = __expf(sf[nt][1] - nm0);
            float p2 = __expf(sf[nt][2] - nm1), p3 = __expf(sf[nt][3] - nm1);
            s0 += p0 + p1; s1 += p2 + p3;
            pf[nt][0] = f2tf32(p0); pf[nt][1] = f2tf32(p1);
            pf[nt][2] = f2tf32(p2); pf[nt][3] = f2tf32(p3);
        }
        s0 += __shfl_xor_sync(0xffffffffu, s0, 1);
        s0 += __shfl_xor_sync(0xffffffffu, s0, 2);
        s1 += __shfl_xor_sync(0xffffffffu, s1, 1);
        s1 += __shfl_xor_sync(0xffffffffu, s1, 2);
        den0 = den0 * cor0 + s0;
        den1 = den1 * cor1 + s1;
#pragma unroll
        for (int nt = 0; nt < 4; nt++) {
            of[nt][0] *= cor0; of[nt][1] *= cor0;
            of[nt][2] *= cor1; of[nt][3] *= cor1;
        }
        // ---- O += P·V : shfl C-frag -> A-frag, then mma ----
        const int src0 = (lane & 0x1C) | (lr >> 1);
        const int src1 = src0 + 2;
        const bool oddc = (lr & 1);
#pragma unroll
        for (int ks = 0; ks < 16; ks++) {
            uint32_t x0 = __shfl_sync(0xffffffffu, pf[ks][0], src0);
            uint32_t x1 = __shfl_sync(0xffffffffu, pf[ks][1], src0);
            uint32_t a0 = oddc ? x1 : x0;
            x0 = __shfl_sync(0xffffffffu, pf[ks][2], src0);
            x1 = __shfl_sync(0xffffffffu, pf[ks][3], src0);
            uint32_t a1 = oddc ? x1 : x0;
            x0 = __shfl_sync(0xffffffffu, pf[ks][0], src1);
            x1 = __shfl_sync(0xffffffffu, pf[ks][1], src1);
            uint32_t a2 = oddc ? x1 : x0;
            x0 = __shfl_sync(0xffffffffu, pf[ks][2], src1);
            x1 = __shfl_sync(0xffffffffu, pf[ks][3], src1);
            uint32_t a3 = oddc ? x1 : x0;
#pragma unroll
            for (int nt = 0; nt < 4; nt++) {
                uint32_t b0 = VT[(nt * 8 + lq) * VTS + ks * 8 + lr];
                uint32_t b1 = VT[(nt * 8 + lq) * VTS + ks * 8 + lr + 4];
                mma8(of[nt], a0, a1, a2, a3, b0, b1);
            }
        }
    }

    // ---- write O / den ----
    float i0 = 1.f / den0, i1 = 1.f / den1;
    int q_lo = qt * 128 + wid * 16 + lq, q_hi = q_lo + 8;
#pragma unroll
    for (int nt = 0; nt < 4; nt++) {
        int col = h * 32 + nt * 8 + lr * 2;
        if (q_lo < LMAX)
            *(float2*)(g_attn + (size_t)(b * LMAX + q_lo) * DD + col) =
                make_float2(of[nt][0] * i0, of[nt][1] * i0);
        if (q_hi < LMAX)
            *(float2*)(g_attn + (size_t)(b * LMAX + q_hi) * DD + col) =
                make_float2(of[nt][2] * i1, of[nt][3] * i1);
    }
}

// ---------------- GAT kernels ----------------
__global__ void zero_acc_kernel() {
    size_t i = (size_t)blockIdx.x * blockDim.x + threadIdx.x;
    if (i < (size_t)NN * DD / 4) ((float4*)g_acc)[i] = make_float4(0.f, 0.f, 0.f, 0.f);
}
__global__ void zero_y_kernel() {
    size_t i = (size_t)blockIdx.x * blockDim.x + threadIdx.x;
    if (i < (size_t)NM * DD / 4) ((float4*)g_y)[i] = make_float4(0.f, 0.f, 0.f, 0.f);
}

__global__ void gat_prep_kernel(const float* __restrict__ a_src,
                                const float* __restrict__ a_dst,
                                const float* __restrict__ bias)
{
    int gid = blockIdx.x * blockDim.x + threadIdx.x;
    int node = gid >> 5, lane = gid & 31;
    if (node >= NN) return;
    float s[4], d[4];
#pragma unroll
    for (int j = 0; j < 4; j++) {
        int c = j * 32 + lane;
        float hv = g_h[(size_t)node * DD + c];
        s[j] = hv * a_src[c];
        d[j] = hv * a_dst[c];
        g_gout[(size_t)node * DD + c] = bias[c];
    }
#pragma unroll
    for (int j = 0; j < 4; j++)
#pragma unroll
        for (int o = 16; o > 0; o >>= 1) {
            s[j] += __shfl_xor_sync(0xffffffffu, s[j], o);
            d[j] += __shfl_xor_sync(0xffffffffu, d[j], o);
        }
    if (lane == 0) {
        *(float4*)&g_als[node * 4] = make_float4(s[0], s[1], s[2], s[3]);
        *(float4*)&g_ald[node * 4] = make_float4(d[0], d[1], d[2], d[3]);
        *(float4*)&g_mx[node * 4] = make_float4(-INFINITY, -INFINITY, -INFINITY, -INFINITY);
        *(float4*)&g_den[node * 4] = make_float4(0.f, 0.f, 0.f, 0.f);
    }
}

__global__ void edge_max_kernel(const int* __restrict__ ei) {
    int t = blockIdx.x * blockDim.x + threadIdx.x;
    if (t >= NE + NN) return;
    int src, dst;
    if (t < NE) { src = ei[t]; dst = ei[NE + t]; }
    else { src = dst = t - NE; }
    float4 a = *(const float4*)&g_als[src * 4];
    float4 b = *(const float4*)&g_ald[dst * 4];
    atomicMaxF(&g_mx[dst * 4 + 0], leakyf(a.x + b.x, 0.2f));
    atomicMaxF(&g_mx[dst * 4 + 1], leakyf(a.y + b.y, 0.2f));
    atomicMaxF(&g_mx[dst * 4 + 2], leakyf(a.z + b.z, 0.2f));
    atomicMaxF(&g_mx[dst * 4 + 3], leakyf(a.w + b.w, 0.2f));
}

__global__ void edge_sum_kernel(const int* __restrict__ ei) {
    int t = blockIdx.x * blockDim.x + threadIdx.x;
    if (t >= NE + NN) return;
    int src, dst;
    if (t < NE) { src = ei[t]; dst = ei[NE + t]; }
    else { src = dst = t - NE; }
    float4 a = *(const float4*)&g_als[src * 4];
    float4 b = *(const float4*)&g_ald[dst * 4];
    float4 m = *(const float4*)&g_mx[dst * 4];
    atomicAdd(&g_den[dst * 4 + 0], expf(leakyf(a.x + b.x, 0.2f) - m.x));
    atomicAdd(&g_den[dst * 4 + 1], expf(leakyf(a.y + b.y, 0.2f) - m.y));
    atomicAdd(&g_den[dst * 4 + 2], expf(leakyf(a.z + b.z, 0.2f) - m.z));
    atomicAdd(&g_den[dst * 4 + 3], expf(leakyf(a.w + b.w, 0.2f) - m.w));
}

__global__ void edge_aggr_kernel(const int* __restrict__ ei) {
    int gid = blockIdx.x * blockDim.x + threadIdx.x;
    int item = gid >> 5, lane = gid & 31;
    if (item >= NE + NN) return;
    int src, dst;
    if (item < NE) { src = ei[item]; dst = ei[NE + item]; }
    else { src = dst = item - NE; }
    float4 a = *(const float4*)&g_als[src * 4];
    float4 b = *(const float4*)&g_ald[dst * 4];
    float4 m = *(const float4*)&g_mx[dst * 4];
    float4 dn = *(const float4*)&g_den[dst * 4];
    float al[4];
    al[0] = expf(leakyf(a.x + b.x, 0.2f) - m.x) / dn.x;
    al[1] = expf(leakyf(a.y + b.y, 0.2f) - m.y) / dn.y;
    al[2] = expf(leakyf(a.z + b.z, 0.2f) - m.z) / dn.z;
    al[3] = expf(leakyf(a.w + b.w, 0.2f) - m.w) / dn.w;
#pragma unroll
    for (int j = 0; j < 4; j++) {
        int c = j * 32 + lane;
        float v = g_h[(size_t)src * DD + c] * al[j];
        atomicAdd(&g_gout[(size_t)dst * DD + c], v);
    }
}

// ---------------- position / count kernels ----------------
__global__ void hist_kernel(const int* __restrict__ genre) {
    __shared__ int loc[NG];
    if (threadIdx.x < NG) loc[threadIdx.x] = 0;
    __syncthreads();
    int i = blockIdx.x * 128 + threadIdx.x;
    if (i < NM) atomicAdd(&loc[genre[i]], 1);
    __syncthreads();
    if (threadIdx.x < NG) g_chist[blockIdx.x * NG + threadIdx.x] = loc[threadIdx.x];
}
__global__ void scan_kernel() {
    int g = threadIdx.x;
    if (g >= NG) return;
    int run = 0;
    for (int c = 0; c < NCHUNK; c++) {
        int t = g_chist[c * NG + g];
        g_chist[c * NG + g] = run;
        run += t;
    }
    g_cnt[g] = run;
}
__global__ void pos_kernel(const int* __restrict__ genre) {
    int c = blockIdx.x * blockDim.x + threadIdx.x;
    if (c >= NCHUNK) return;
    int off[NG];
    for (int g = 0; g < NG; g++) off[g] = g_chist[c * NG + g];
    int base = c * 128;
    int end = base + 128; if (end > NM) end = NM;
    for (int i = base; i < end; i++) {
        int g = genre[i];
        g_pos[i] = off[g]++;
    }
}

__global__ void gather_kernel(const int* __restrict__ movie_idx, const int* __restrict__ genre) {
    int t = blockIdx.x * blockDim.x + threadIdx.x;
    if (t >= NM * 32) return;
    int i = t >> 5, c4 = (t & 31) * 4;
    float4 v = *(const float4*)&g_acc[(size_t)movie_idx[i] * DD + c4];
    *(float4*)&g_xm[(size_t)i * DD + c4] = v;
    int row = genre[i] * LMAX + g_pos[i];
    *(float4*)&g_y[(size_t)row * DD + c4] = v;
}

// ---------------- LayerNorm (fused residual): y = LN(y + t) ----------------
__global__ void ln_kernel(float* __restrict__ y, const float* __restrict__ t,
                          const float* __restrict__ gam, const float* __restrict__ bet,
                          int rows)
{
    int gid = blockIdx.x * blockDim.x + threadIdx.x;
    int row = gid >> 5, lane = gid & 31;
    if (row >= rows) return;
    size_t off = (size_t)row * DD + lane * 4;
    float4 v = *(float4*)(y + off);
    float4 tv = *(const float4*)(t + off);
    v.x += tv.x; v.y += tv.y; v.z += tv.z; v.w += tv.w;
    float s = v.x + v.y + v.z + v.w;
#pragma unroll
    for (int o = 16; o > 0; o >>= 1) s += __shfl_xor_sync(0xffffffffu, s, o);
    float mean = s * (1.f / DD);
    float dx = v.x - mean, dy = v.y - mean, dz = v.z - mean, dw = v.w - mean;
    float ss = dx * dx + dy * dy + dz * dz + dw * dw;
#pragma unroll
    for (int o = 16; o > 0; o >>= 1) ss += __shfl_xor_sync(0xffffffffu, ss, o);
    float inv = rsqrtf(ss * (1.f / DD) + 1e-5f);
    float4 gg = *(const float4*)(gam + lane * 4);
    float4 bb = *(const float4*)(bet + lane * 4);
    v.x = dx * inv * gg.x + bb.x;
    v.y = dy * inv * gg.y + bb.y;
    v.z = dz * inv * gg.z + bb.z;
    v.w = dw * inv * gg.w + bb.w;
    *(float4*)(y + off) = v;
}

// ---------------- pooling / fusion ----------------
__global__ void pool_kernel() {
    int g = blockIdx.x, d = threadIdx.x;
    int cnt = g_cnt[g];
    float s = 0.f;
    for (int t = 0; t < cnt; t++) s += g_y[(size_t)(g * LMAX + t) * DD + d];
    g_pooled[g * DD + d] = s / fmaxf((float)cnt, 1.f);
}

__global__ void pe_kernel(const float* __restrict__ fus_w) {
    int g = blockIdx.x, n = threadIdx.x;
    float s = 0.f;
    for (int k = 0; k < DD; k++)
        s += g_pooled[g * DD + k] * fus_w[n * 256 + 128 + k];
    g_pe[g * DD + n] = s;
}

__global__ void copy_out_kernel(float* __restrict__ out) {
    size_t i = (size_t)blockIdx.x * blockDim.x + threadIdx.x;
    if (i < (size_t)NN * DD / 4) ((float4*)out)[i] = ((const float4*)g_acc)[i];
}

__global__ void fuse_out_kernel(const int* __restrict__ movie_idx, const int* __restrict__ genre,
                                const float* __restrict__ fus_b, float* __restrict__ out)
{
    int t = blockIdx.x * blockDim.x + threadIdx.x;
    if (t >= NM * 32) return;
    int i = t >> 5, c4 = (t & 31) * 4;
    float4 v = *(const float4*)&g_tmp[(size_t)i * DD + c4];
    float4 p = *(const float4*)&g_pe[genre[i] * DD + c4];
    float4 bb = *(const float4*)(fus_b + c4);
    v.x = leakyf(v.x + p.x + bb.x, 0.01f);
    v.y = leakyf(v.y + p.y + bb.y, 0.01f);
    v.z = leakyf(v.z + p.z + bb.z, 0.01f);
    v.w = leakyf(v.w + p.w + bb.w, 0.01f);
    *(float4*)&out[(size_t)movie_idx[i] * DD + c4] = v;
}

// ---------------- launch ----------------
extern "C" void kernel_launch(void* const* d_in, const int* in_sizes, int n_in,
                              void* d_out, int out_size)
{
    const float* x        = (const float*)d_in[0];
    const int*   e[3]     = {(const int*)d_in[1], (const int*)d_in[2], (const int*)d_in[3]};
    const int*   movie_idx = (const int*)d_in[4];
    const int*   genre     = (const int*)d_in[5];
    const float* gat_W    = (const float*)d_in[6];
    const float* att_src  = (const float*)d_in[7];
    const float* att_dst  = (const float*)d_in[8];
    const float* gat_bias = (const float*)d_in[9];
    const float* dec_W    = (const float*)d_in[10];
    const float* dec_b    = (const float*)d_in[11];
    const float* qkv_w    = (const float*)d_in[12];
    const float* qkv_b    = (const float*)d_in[13];
    const float* out_w    = (const float*)d_in[14];
    const float* out_b    = (const float*)d_in[15];
    const float* ln1_g    = (const float*)d_in[16];
    const float* ln1_b    = (const float*)d_in[17];
    const float* ln2_g    = (const float*)d_in[18];
    const float* ln2_b    = (const float*)d_in[19];
    const float* ffn_w1   = (const float*)d_in[20];
    const float* ffn_b1   = (const float*)d_in[21];
    const float* ffn_w2   = (const float*)d_in[22];
    const float* ffn_b2   = (const float*)d_in[23];
    const float* fus_w    = (const float*)d_in[24];
    const float* fus_b    = (const float*)d_in[25];
    float* out = (float*)d_out;

    float *p_h, *p_gout, *p_acc, *p_y, *p_qkv, *p_attn, *p_tmp, *p_ffn, *p_xm;
    cudaGetSymbolAddress((void**)&p_h,    g_h);
    cudaGetSymbolAddress((void**)&p_gout, g_gout);
    cudaGetSymbolAddress((void**)&p_acc,  g_acc);
    cudaGetSymbolAddress((void**)&p_y,    g_y);
    cudaGetSymbolAddress((void**)&p_qkv,  g_qkv);
    cudaGetSymbolAddress((void**)&p_attn, g_attn);
    cudaGetSymbolAddress((void**)&p_tmp,  g_tmp);
    cudaGetSymbolAddress((void**)&p_ffn,  g_ffn);
    cudaGetSymbolAddress((void**)&p_xm,   g_xm);

    const int MTN = (NN + 127) / 128;  // 391
    const int MT  = (NM + 127) / 128;  // 160

    // -------- GAT (3 hops, tf32 GEMMs + fp32 edge softmax) --------
    zero_acc_kernel<<<(NN * DD / 4 + 255) / 256, 256>>>();
    for (int k = 0; k < 3; k++) {
        gemm_mma<<<dim3(1, MTN), 256>>>(x, gat_W + (size_t)k * DD * DD, nullptr, p_h,
                                        NN, DD, DD, DD, DD, 0, 0.f);
        gat_prep_kernel<<<(NN * 32 + 255) / 256, 256>>>(att_src + k * DD, att_dst + k * DD,
                                                        gat_bias + k * DD);
        int items = NE + NN;
        edge_max_kernel<<<(items + 255) / 256, 256>>>(e[k]);
        edge_sum_kernel<<<(items + 255) / 256, 256>>>(e[k]);
        edge_aggr_kernel<<<((size_t)items * 32 + 255) / 256, 256>>>(e[k]);
        float scale = (float)exp(-0.1 * k);
        gemm_mma<<<dim3(1, MTN), 256>>>(p_gout, dec_W + (size_t)k * DD * DD, dec_b + k * DD,
                                        p_acc, NN, DD, DD, DD, DD, 2, scale);
    }

    // -------- build genre sequences --------
    hist_kernel<<<NCHUNK, 128>>>(genre);
    scan_kernel<<<1, 32>>>();
    pos_kernel<<<1, 256>>>(genre);
    zero_y_kernel<<<(NM * DD / 4 + 255) / 256, 256>>>();
    gather_kernel<<<(NM * 32 + 255) / 256, 256>>>(movie_idx, genre);

    // -------- transformer (4 layers, tf32 mma GEMMs + TC flash attention) --------
    for (int l = 0; l < NL; l++) {
        gemm_mma<<<dim3(3 * DD / 128, MT), 256>>>(
            p_y, qkv_w + (size_t)l * 3 * DD * DD, qkv_b + l * 3 * DD, p_qkv,
            NM, 3 * DD, DD, DD, DD, 0, 0.f);
        attn_tc<<<dim3((LMAX + 127) / 128, NHEADS, NG), 256>>>();
        gemm_mma<<<dim3(1, MT), 256>>>(
            p_attn, out_w + (size_t)l * DD * DD, out_b + l * DD, p_tmp,
            NM, DD, DD, DD, DD, 0, 0.f);
        ln_kernel<<<(NM * 32 + 255) / 256, 256>>>(p_y, p_tmp, ln1_g + l * DD, ln1_b + l * DD, NM);
        gemm_mma<<<dim3(FFD / 128, MT), 256>>>(
            p_y, ffn_w1 + (size_t)l * FFD * DD, ffn_b1 + l * FFD, p_ffn,
            NM, FFD, DD, DD, DD, 1, 0.f);
        gemm_mma<<<dim3(1, MT), 256>>>(
            p_ffn, ffn_w2 + (size_t)l * DD * FFD, ffn_b2 + l * DD, p_tmp,
            NM, DD, FFD, FFD, FFD, 0, 0.f);
        ln_kernel<<<(NM * 32 + 255) / 256, 256>>>(p_y, p_tmp, ln2_g + l * DD, ln2_b + l * DD, NM);
    }

    // -------- pool + fuse + write output --------
    pool_kernel<<<NG, DD>>>();
    pe_kernel<<<NG, DD>>>(fus_w);
    gemm_mma<<<dim3(1, MT), 256>>>(p_xm, fus_w, nullptr, p_tmp,
                                   NM, DD, DD, DD, 256, 0, 0.f);
    copy_out_kernel<<<(NN * DD / 4 + 255) / 256, 256>>>(out);
    fuse_out_kernel<<<(NM * 32 + 255) / 256, 256>>>(movie_idx, genre, fus_b, out);
}

// round 6
// speedup vs baseline: 2.5327x; 1.0149x over previous
#include <cuda_runtime.h>
#include <math.h>
#include <stdint.h>

#define NN 50000
#define NE 400000
#define DD 128
#define NM 20400
#define NG 30
#define LMAX 680
#define NHEADS 4
#define NL 4
#define FFD 2048
#define NCHUNK 160   // ceil(20400/128)
#define NITEMS (NE + NN)

// ---------------- scratch (device globals; no runtime allocation) ----------------
__device__ __align__(16) float g_h3[(size_t)NN * 384];     // per-hop GAT features
__device__ __align__(16) float g_gout3[(size_t)NN * 384];  // per-hop aggregation
__device__ __align__(16) float g_acc[(size_t)NN * DD];
__device__ __align__(16) float g_als3[NN * 3 * NHEADS];
__device__ __align__(16) float g_ald3[NN * 3 * NHEADS];
__device__ __align__(16) float g_den3[NN * 3 * NHEADS];
__device__ __align__(16) float g_ew[(size_t)3 * NITEMS * NHEADS];
__device__ __align__(16) float g_y[(size_t)NM * DD];
__device__ __align__(16) float g_qkv[(size_t)NM * 3 * DD];
__device__ __align__(16) float g_attn[(size_t)NM * DD];
__device__ __align__(16) float g_tmp[(size_t)NM * DD];
__device__ __align__(16) float g_ffn[(size_t)NM * FFD];
__device__ __align__(16) float g_xm[(size_t)NM * DD];
__device__ __align__(16) float g_pooled[NG * DD];
__device__ __align__(16) float g_pe[NG * DD];
__device__ int g_pos[NM];
__device__ int g_cnt[NG];
__device__ int g_chist[NCHUNK * NG];

// ---------------- small helpers ----------------
__device__ __forceinline__ float leakyf(float x, float s) { return x >= 0.f ? x : s * x; }

__device__ __forceinline__ float dot4(float4 a, float4 b) {
    return a.x * b.x + a.y * b.y + a.z * b.z + a.w * b.w;
}

__device__ __forceinline__ uint32_t f2tf32(float f) {
    uint32_t r;
    asm("cvt.rna.tf32.f32 %0, %1;" : "=r"(r) : "f"(f));
    return r;
}

__device__ __forceinline__ void mma8(float* c, uint32_t a0, uint32_t a1, uint32_t a2,
                                     uint32_t a3, uint32_t b0, uint32_t b1) {
    asm volatile(
        "mma.sync.aligned.m16n8k8.row.col.f32.tf32.tf32.f32 "
        "{%0,%1,%2,%3}, {%4,%5,%6,%7}, {%8,%9}, {%0,%1,%2,%3};"
        : "+f"(c[0]), "+f"(c[1]), "+f"(c[2]), "+f"(c[3])
        : "r"(a0), "r"(a1), "r"(a2), "r"(a3), "r"(b0), "r"(b1));
}

// ---------------- pipelined mma.sync tf32 GEMM ----------------
// C[M,N] = epi(A[M,K(lda)] * B[N,K(ldb)]^T + bias)
// epi: 0 = store (+bias), 1 = relu(+bias), 2 = C += scale*leaky_{0.01}(v+bias)
// N multiple of 128, K multiple of 32. grid (N/128, ceil(M/128)), block 256,
// dynamic smem = 4*128*SROW*4 bytes (double-buffered A+B tiles).
#define SROW 36
#define TBUF (128 * SROW)
__global__ __launch_bounds__(256) void gemm_mma(
    const float* __restrict__ A, const float* __restrict__ B,
    const float* __restrict__ bias, float* __restrict__ C,
    int M, int N, int K, int lda, int ldb, int epi, float scale)
{
    extern __shared__ uint32_t sm[];
    const int tid = threadIdx.x;
    const int wid = tid >> 5, lane = tid & 31;
    const int wm = wid & 1, wn = wid >> 1;       // warp tile: 64 rows x 32 cols
    const int row0 = blockIdx.y * 128, col0 = blockIdx.x * 128;
    const int lq = lane >> 2, lr = lane & 3;

    float acc[4][4][4];
#pragma unroll
    for (int i = 0; i < 4; i++)
#pragma unroll
        for (int j = 0; j < 4; j++) {
            acc[i][j][0] = 0.f; acc[i][j][1] = 0.f;
            acc[i][j][2] = 0.f; acc[i][j][3] = 0.f;
        }

    const int s_row = tid >> 3;                  // staging: 8 threads per row
    const int s_c4 = (tid & 7) * 4;
    const int nC = K >> 5;

    float4 pa[4], pb[4];

#define LDG_CHUNK(cc)                                                              \
    {                                                                              \
        int k0 = (cc) << 5;                                                        \
        _Pragma("unroll")                                                          \
        for (int it = 0; it < 4; it++) {                                           \
            int row = it * 32 + s_row;                                             \
            int gr = row0 + row;                                                   \
            pa[it] = make_float4(0.f, 0.f, 0.f, 0.f);                              \
            if (gr < M) pa[it] = *(const float4*)(A + (size_t)gr * lda + k0 + s_c4); \
            pb[it] = *(const float4*)(B + (size_t)(col0 + row) * ldb + k0 + s_c4); \
        }                                                                          \
    }
#define STS_CHUNK(Ad, Bd)                                                          \
    {                                                                              \
        _Pragma("unroll")                                                          \
        for (int it = 0; it < 4; it++) {                                           \
            int row = it * 32 + s_row;                                             \
            *(uint4*)&(Ad)[row * SROW + s_c4] = make_uint4(                        \
                f2tf32(pa[it].x), f2tf32(pa[it].y), f2tf32(pa[it].z), f2tf32(pa[it].w)); \
            *(uint4*)&(Bd)[row * SROW + s_c4] = make_uint4(                        \
                f2tf32(pb[it].x), f2tf32(pb[it].y), f2tf32(pb[it].z), f2tf32(pb[it].w)); \
        }                                                                          \
    }
#define COMPUTE_HALF(Asb, Bsb, KS0)                                                \
    {                                                                              \
        _Pragma("unroll")                                                          \
        for (int ks = (KS0); ks < (KS0) + 2; ks++) {                               \
            int kk = ks * 8 + lr;                                                  \
            uint2 bf[4];                                                           \
            _Pragma("unroll")                                                      \
            for (int nt = 0; nt < 4; nt++) {                                       \
                int n = wn * 32 + nt * 8 + lq;                                     \
                bf[nt].x = (Bsb)[n * SROW + kk];                                   \
                bf[nt].y = (Bsb)[n * SROW + kk + 4];                               \
            }                                                                      \
            _Pragma("unroll")                                                      \
            for (int mt = 0; mt < 4; mt++) {                                       \
                int r = wm * 64 + mt * 16 + lq;                                    \
                uint32_t a0 = (Asb)[r * SROW + kk];                                \
                uint32_t a1 = (Asb)[(r + 8) * SROW + kk];                          \
                uint32_t a2 = (Asb)[r * SROW + kk + 4];                            \
                uint32_t a3 = (Asb)[(r + 8) * SROW + kk + 4];                      \
                _Pragma("unroll")                                                  \
                for (int nt = 0; nt < 4; nt++)                                     \
                    mma8(acc[mt][nt], a0, a1, a2, a3, bf[nt].x, bf[nt].y);         \
            }                                                                      \
        }                                                                          \
    }

    uint32_t* A0 = sm;
    uint32_t* B0 = sm + TBUF;
    uint32_t* A1 = sm + 2 * TBUF;
    uint32_t* B1 = sm + 3 * TBUF;

    LDG_CHUNK(0);
    STS_CHUNK(A0, B0);
    if (nC > 1) LDG_CHUNK(1);
    __syncthreads();

    for (int c = 0; c < nC; c++) {
        uint32_t* Asb = (c & 1) ? A1 : A0;
        uint32_t* Bsb = (c & 1) ? B1 : B0;
        uint32_t* Asn = (c & 1) ? A0 : A1;
        uint32_t* Bsn = (c & 1) ? B0 : B1;
        COMPUTE_HALF(Asb, Bsb, 0);
        if (c + 1 < nC) STS_CHUNK(Asn, Bsn);
        COMPUTE_HALF(Asb, Bsb, 2);
        if (c + 2 < nC) LDG_CHUNK(c + 2);
        __syncthreads();
    }

    // ---- epilogue ----
    const int rbase = row0 + wm * 64;
    const int cbase = col0 + wn * 32;
#pragma unroll
    for (int mt = 0; mt < 4; mt++) {
        int r0 = rbase + mt * 16 + lq;
#pragma unroll
        for (int half = 0; half < 2; half++) {
            int r = r0 + half * 8;
            if (r < M) {
#pragma unroll
                for (int nt = 0; nt < 4; nt++) {
                    int c = cbase + nt * 8 + lr * 2;
                    float v0 = acc[mt][nt][half * 2 + 0];
                    float v1 = acc[mt][nt][half * 2 + 1];
                    if (bias) { v0 += bias[c]; v1 += bias[c + 1]; }
                    float* cp = C + (size_t)r * N + c;
                    if (epi == 0) {
                        *(float2*)cp = make_float2(v0, v1);
                    } else if (epi == 1) {
                        *(float2*)cp = make_float2(fmaxf(v0, 0.f), fmaxf(v1, 0.f));
                    } else {
                        float2 o = *(float2*)cp;
                        o.x += scale * leakyf(v0, 0.01f);
                        o.y += scale * leakyf(v1, 0.01f);
                        *(float2*)cp = o;
                    }
                }
            }
        }
    }
}

// ---------------- tensor-core flash attention ----------------
#define QKS 36
#define VTS 132
__global__ __launch_bounds__(256) void attn_tc() {
    __shared__ uint32_t QK[128 * QKS];
    __shared__ uint32_t VT[32 * VTS];
    const int b = blockIdx.z, h = blockIdx.y, qt = blockIdx.x;
    const int cnt = g_cnt[b];
    const int tid = threadIdx.x, wid = tid >> 5, lane = tid & 31;
    const int lq = lane >> 2, lr = lane & 3;
    const float qscale = 0.17677669529663687f;   // 1/sqrt(32)

#pragma unroll
    for (int it = 0; it < 4; it++) {
        int idx = it * 256 + tid;
        int row = idx >> 3, c4 = (idx & 7) * 4;
        int q = qt * 128 + row;
        float4 v = make_float4(0.f, 0.f, 0.f, 0.f);
        if (q < LMAX) v = *(const float4*)(g_qkv + (size_t)(b * LMAX + q) * 384 + h * 32 + c4);
        *(uint4*)&QK[row * QKS + c4] = make_uint4(
            f2tf32(v.x * qscale), f2tf32(v.y * qscale),
            f2tf32(v.z * qscale), f2tf32(v.w * qscale));
    }
    __syncthreads();
    uint32_t qa[4][4];
    {
        int r = wid * 16 + lq;
#pragma unroll
        for (int ks = 0; ks < 4; ks++) {
            int kk = ks * 8 + lr;
            qa[ks][0] = QK[r * QKS + kk];
            qa[ks][1] = QK[(r + 8) * QKS + kk];
            qa[ks][2] = QK[r * QKS + kk + 4];
            qa[ks][3] = QK[(r + 8) * QKS + kk + 4];
        }
    }

    float m0 = -INFINITY, m1 = -INFINITY, den0 = 0.f, den1 = 0.f;
    float of[4][4];
#pragma unroll
    for (int nt = 0; nt < 4; nt++) {
        of[nt][0] = 0.f; of[nt][1] = 0.f; of[nt][2] = 0.f; of[nt][3] = 0.f;
    }

    for (int kb = 0; kb < LMAX; kb += 128) {
        __syncthreads();
#pragma unroll
        for (int it = 0; it < 4; it++) {
            int idx = it * 256 + tid;
            int row = idx >> 3, c4 = (idx & 7) * 4;
            int key = kb + row;
            float4 kv = make_float4(0.f, 0.f, 0.f, 0.f);
            float4 vv = make_float4(0.f, 0.f, 0.f, 0.f);
            if (key < LMAX) {
                const float* base = g_qkv + (size_t)(b * LMAX + key) * 384 + h * 32;
                kv = *(const float4*)(base + 128 + c4);
                vv = *(const float4*)(base + 256 + c4);
            }
            *(uint4*)&QK[row * QKS + c4] = make_uint4(
                f2tf32(kv.x), f2tf32(kv.y), f2tf32(kv.z), f2tf32(kv.w));
            VT[(c4 + 0) * VTS + row] = f2tf32(vv.x);
            VT[(c4 + 1) * VTS + row] = f2tf32(vv.y);
            VT[(c4 + 2) * VTS + row] = f2tf32(vv.z);
            VT[(c4 + 3) * VTS + row] = f2tf32(vv.w);
        }
        __syncthreads();

        float sf[16][4];
#pragma unroll
        for (int nt = 0; nt < 16; nt++) {
            sf[nt][0] = 0.f; sf[nt][1] = 0.f; sf[nt][2] = 0.f; sf[nt][3] = 0.f;
        }
#pragma unroll
        for (int ks = 0; ks < 4; ks++) {
            int kk = ks * 8 + lr;
#pragma unroll
            for (int nt = 0; nt < 16; nt++) {
                uint32_t b0 = QK[(nt * 8 + lq) * QKS + kk];
                uint32_t b1 = QK[(nt * 8 + lq) * QKS + kk + 4];
                mma8(sf[nt], qa[ks][0], qa[ks][1], qa[ks][2], qa[ks][3], b0, b1);
            }
        }
        float bm0 = -INFINITY, bm1 = -INFINITY;
#pragma unroll
        for (int nt = 0; nt < 16; nt++) {
            int c = kb + nt * 8 + lr * 2;
            if (c >= cnt) { sf[nt][0] = -1e30f; sf[nt][2] = -1e30f; }
            if (c + 1 >= cnt) { sf[nt][1] = -1e30f; sf[nt][3] = -1e30f; }
            bm0 = fmaxf(bm0, fmaxf(sf[nt][0], sf[nt][1]));
            bm1 = fmaxf(bm1, fmaxf(sf[nt][2], sf[nt][3]));
        }
        bm0 = fmaxf(bm0, __shfl_xor_sync(0xffffffffu, bm0, 1));
        bm0 = fmaxf(bm0, __shfl_xor_sync(0xffffffffu, bm0, 2));
        bm1 = fmaxf(bm1, __shfl_xor_sync(0xffffffffu, bm1, 1));
        bm1 = fmaxf(bm1, __shfl_xor_sync(0xffffffffu, bm1, 2));
        float nm0 = fmaxf(m0, bm0), nm1 = fmaxf(m1, bm1);
        float cor0 = __expf(m0 - nm0), cor1 = __expf(m1 - nm1);
        m0 = nm0; m1 = nm1;
        float s0 = 0.f, s1 = 0.f;
        uint32_t pf[16][4];
#pragma unroll
        for (int nt = 0; nt < 16; nt++) {
            float p0 = __expf(sf[nt][0] - nm0), p1 = __expf(sf[nt][1] - nm0);
            float p2 = __expf(sf[nt][2] - nm1), p3 = __expf(sf[nt][3] - nm1);
            s0 += p0 + p1; s1 += p2 + p3;
            pf[nt][0] = f2tf32(p0); pf[nt][1] = f2tf32(p1);
            pf[nt][2] = f2tf32(p2); pf[nt][3] = f2tf32(p3);
        }
        s0 += __shfl_xor_sync(0xffffffffu, s0, 1);
        s0 += __shfl_xor_sync(0xffffffffu, s0, 2);
        s1 += __shfl_xor_sync(0xffffffffu, s1, 1);
        s1 += __shfl_xor_sync(0xffffffffu, s1, 2);
        den0 = den0 * cor0 + s0;
        den1 = den1 * cor1 + s1;
#pragma unroll
        for (int nt = 0; nt < 4; nt++) {
            of[nt][0] *= cor0; of[nt][1] *= cor0;
            of[nt][2] *= cor1; of[nt][3] *= cor1;
        }
        const int src0 = (lane & 0x1C) | (lr >> 1);
        const int src1 = src0 + 2;
        const bool oddc = (lr & 1);
#pragma unroll
        for (int ks = 0; ks < 16; ks++) {
            uint32_t x0 = __shfl_sync(0xffffffffu, pf[ks][0], src0);
            uint32_t x1 = __shfl_sync(0xffffffffu, pf[ks][1], src0);
            uint32_t a0 = oddc ? x1 : x0;
            x0 = __shfl_sync(0xffffffffu, pf[ks][2], src0);
            x1 = __shfl_sync(0xffffffffu, pf[ks][3], src0);
            uint32_t a1 = oddc ? x1 : x0;
            x0 = __shfl_sync(0xffffffffu, pf[ks][0], src1);
            x1 = __shfl_sync(0xffffffffu, pf[ks][1], src1);
            uint32_t a2 = oddc ? x1 : x0;
            x0 = __shfl_sync(0xffffffffu, pf[ks][2], src1);
            x1 = __shfl_sync(0xffffffffu, pf[ks][3], src1);
            uint32_t a3 = oddc ? x1 : x0;
#pragma unroll
            for (int nt = 0; nt < 4; nt++) {
                uint32_t b0 = VT[(nt * 8 + lq) * VTS + ks * 8 + lr];
                uint32_t b1 = VT[(nt * 8 + lq) * VTS + ks * 8 + lr + 4];
                mma8(of[nt], a0, a1, a2, a3, b0, b1);
            }
        }
    }

    float i0 = 1.f / den0, i1 = 1.f / den1;
    int q_lo = qt * 128 + wid * 16 + lq, q_hi = q_lo + 8;
#pragma unroll
    for (int nt = 0; nt < 4; nt++) {
        int col = h * 32 + nt * 8 + lr * 2;
        if (q_lo < LMAX)
            *(float2*)(g_attn + (size_t)(b * LMAX + q_lo) * DD + col) =
                make_float2(of[nt][0] * i0, of[nt][1] * i0);
        if (q_hi < LMAX)
            *(float2*)(g_attn + (size_t)(b * LMAX + q_hi) * DD + col) =
                make_float2(of[nt][2] * i1, of[nt][3] * i1);
    }
}

// ---------------- GAT kernels (batched over hops) ----------------
__global__ void zero_acc_kernel() {
    size_t i = (size_t)blockIdx.x * blockDim.x + threadIdx.x;
    if (i < (size_t)NN * DD / 4) ((float4*)g_acc)[i] = make_float4(0.f, 0.f, 0.f, 0.f);
}
__global__ void zero_y_kernel() {
    size_t i = (size_t)blockIdx.x * blockDim.x + threadIdx.x;
    if (i < (size_t)NM * DD / 4) ((float4*)g_y)[i] = make_float4(0.f, 0.f, 0.f, 0.f);
}

// warp per node, blockIdx.y = hop: al reductions + gout3=bias + den3=0
__global__ void gat_prep3(const float* __restrict__ a_src,
                          const float* __restrict__ a_dst,
                          const float* __restrict__ bias)
{
    int gid = blockIdx.x * blockDim.x + threadIdx.x;
    int node = gid >> 5, lane = gid & 31;
    int hop = blockIdx.y;
    if (node >= NN) return;
    float s[4], d[4];
#pragma unroll
    for (int j = 0; j < 4; j++) {
        int c = j * 32 + lane;
        float hv = g_h3[(size_t)node * 384 + hop * 128 + c];
        s[j] = hv * a_src[hop * DD + c];
        d[j] = hv * a_dst[hop * DD + c];
        g_gout3[(size_t)node * 384 + hop * 128 + c] = bias[hop * DD + c];
    }
#pragma unroll
    for (int j = 0; j < 4; j++)
#pragma unroll
        for (int o = 16; o > 0; o >>= 1) {
            s[j] += __shfl_xor_sync(0xffffffffu, s[j], o);
            d[j] += __shfl_xor_sync(0xffffffffu, d[j], o);
        }
    if (lane == 0) {
        int idx = (node * 3 + hop) * 4;
        *(float4*)&g_als3[idx] = make_float4(s[0], s[1], s[2], s[3]);
        *(float4*)&g_ald3[idx] = make_float4(d[0], d[1], d[2], d[3]);
        *(float4*)&g_den3[idx] = make_float4(0.f, 0.f, 0.f, 0.f);
    }
}

// pass 1: ew = exp(leaky(als+ald)) stored; den += ew. blockIdx.y = hop.
// (no max subtraction: alpha = ew/den is mathematically identical, |e| small)
__global__ void edge_exp3(const int* __restrict__ e0, const int* __restrict__ e1,
                          const int* __restrict__ e2)
{
    int hop = blockIdx.y;
    const int* ei = (hop == 0) ? e0 : (hop == 1) ? e1 : e2;
    int t = blockIdx.x * blockDim.x + threadIdx.x;
    if (t >= NITEMS) return;
    int src, dst;
    if (t < NE) { src = ei[t]; dst = ei[NE + t]; }
    else { src = dst = t - NE; }
    float4 a = *(const float4*)&g_als3[(src * 3 + hop) * 4];
    float4 b = *(const float4*)&g_ald3[(dst * 3 + hop) * 4];
    float4 ew;
    ew.x = expf(leakyf(a.x + b.x, 0.2f));
    ew.y = expf(leakyf(a.y + b.y, 0.2f));
    ew.z = expf(leakyf(a.z + b.z, 0.2f));
    ew.w = expf(leakyf(a.w + b.w, 0.2f));
    *(float4*)&g_ew[((size_t)hop * NITEMS + t) * 4] = ew;
    float* dn = &g_den3[(dst * 3 + hop) * 4];
    atomicAdd(dn + 0, ew.x);
    atomicAdd(dn + 1, ew.y);
    atomicAdd(dn + 2, ew.z);
    atomicAdd(dn + 3, ew.w);
}

// pass 2: warp per item, gout3[dst] += (ew/den) * h3[src]. blockIdx.y = hop.
__global__ void edge_aggr3(const int* __restrict__ e0, const int* __restrict__ e1,
                           const int* __restrict__ e2)
{
    int hop = blockIdx.y;
    const int* ei = (hop == 0) ? e0 : (hop == 1) ? e1 : e2;
    int gid = blockIdx.x * blockDim.x + threadIdx.x;
    int item = gid >> 5, lane = gid & 31;
    if (item >= NITEMS) return;
    int src, dst;
    if (item < NE) { src = ei[item]; dst = ei[NE + item]; }
    else { src = dst = item - NE; }
    float4 ew = *(const float4*)&g_ew[((size_t)hop * NITEMS + item) * 4];
    float4 dn = *(const float4*)&g_den3[(dst * 3 + hop) * 4];
    float al[4] = {ew.x / dn.x, ew.y / dn.y, ew.z / dn.z, ew.w / dn.w};
    const float* hsrc = g_h3 + (size_t)src * 384 + hop * 128;
    float* gd = g_gout3 + (size_t)dst * 384 + hop * 128;
#pragma unroll
    for (int j = 0; j < 4; j++) {
        int c = j * 32 + lane;
        atomicAdd(gd + c, hsrc[c] * al[j]);
    }
}

// ---------------- position / count kernels ----------------
__global__ void hist_kernel(const int* __restrict__ genre) {
    __shared__ int loc[NG];
    if (threadIdx.x < NG) loc[threadIdx.x] = 0;
    __syncthreads();
    int i = blockIdx.x * 128 + threadIdx.x;
    if (i < NM) atomicAdd(&loc[genre[i]], 1);
    __syncthreads();
    if (threadIdx.x < NG) g_chist[blockIdx.x * NG + threadIdx.x] = loc[threadIdx.x];
}
__global__ void scan_kernel() {
    int g = threadIdx.x;
    if (g >= NG) return;
    int run = 0;
    for (int c = 0; c < NCHUNK; c++) {
        int t = g_chist[c * NG + g];
        g_chist[c * NG + g] = run;
        run += t;
    }
    g_cnt[g] = run;
}
__global__ void pos_kernel(const int* __restrict__ genre) {
    int c = blockIdx.x * blockDim.x + threadIdx.x;
    if (c >= NCHUNK) return;
    int off[NG];
    for (int g = 0; g < NG; g++) off[g] = g_chist[c * NG + g];
    int base = c * 128;
    int end = base + 128; if (end > NM) end = NM;
    for (int i = base; i < end; i++) {
        int g = genre[i];
        g_pos[i] = off[g]++;
    }
}

__global__ void gather_kernel(const int* __restrict__ movie_idx, const int* __restrict__ genre) {
    int t = blockIdx.x * blockDim.x + threadIdx.x;
    if (t >= NM * 32) return;
    int i = t >> 5, c4 = (t & 31) * 4;
    float4 v = *(const float4*)&g_acc[(size_t)movie_idx[i] * DD + c4];
    *(float4*)&g_xm[(size_t)i * DD + c4] = v;
    int row = genre[i] * LMAX + g_pos[i];
    *(float4*)&g_y[(size_t)row * DD + c4] = v;
}

// ---------------- LayerNorm (fused residual): y = LN(y + t) ----------------
__global__ void ln_kernel(float* __restrict__ y, const float* __restrict__ t,
                          const float* __restrict__ gam, const float* __restrict__ bet,
                          int rows)
{
    int gid = blockIdx.x * blockDim.x + threadIdx.x;
    int row = gid >> 5, lane = gid & 31;
    if (row >= rows) return;
    size_t off = (size_t)row * DD + lane * 4;
    float4 v = *(float4*)(y + off);
    float4 tv = *(const float4*)(t + off);
    v.x += tv.x; v.y += tv.y; v.z += tv.z; v.w += tv.w;
    float s = v.x + v.y + v.z + v.w;
#pragma unroll
    for (int o = 16; o > 0; o >>= 1) s += __shfl_xor_sync(0xffffffffu, s, o);
    float mean = s * (1.f / DD);
    float dx = v.x - mean, dy = v.y - mean, dz = v.z - mean, dw = v.w - mean;
    float ss = dx * dx + dy * dy + dz * dz + dw * dw;
#pragma unroll
    for (int o = 16; o > 0; o >>= 1) ss += __shfl_xor_sync(0xffffffffu, ss, o);
    float inv = rsqrtf(ss * (1.f / DD) + 1e-5f);
    float4 gg = *(const float4*)(gam + lane * 4);
    float4 bb = *(const float4*)(bet + lane * 4);
    v.x = dx * inv * gg.x + bb.x;
    v.y = dy * inv * gg.y + bb.y;
    v.z = dz * inv * gg.z + bb.z;
    v.w = dw * inv * gg.w + bb.w;
    *(float4*)(y + off) = v;
}

// ---------------- pooling / fusion ----------------
__global__ void pool_kernel() {
    int g = blockIdx.x, d = threadIdx.x;
    int cnt = g_cnt[g];
    float s = 0.f;
    for (int t = 0; t < cnt; t++) s += g_y[(size_t)(g * LMAX + t) * DD + d];
    g_pooled[g * DD + d] = s / fmaxf((float)cnt, 1.f);
}

__global__ void pe_kernel(const float* __restrict__ fus_w) {
    int g = blockIdx.x, n = threadIdx.x;
    float s = 0.f;
    for (int k = 0; k < DD; k++)
        s += g_pooled[g * DD + k] * fus_w[n * 256 + 128 + k];
    g_pe[g * DD + n] = s;
}

__global__ void copy_out_kernel(float* __restrict__ out) {
    size_t i = (size_t)blockIdx.x * blockDim.x + threadIdx.x;
    if (i < (size_t)NN * DD / 4) ((float4*)out)[i] = ((const float4*)g_acc)[i];
}

__global__ void fuse_out_kernel(const int* __restrict__ movie_idx, const int* __restrict__ genre,
                                const float* __restrict__ fus_b, float* __restrict__ out)
{
    int t = blockIdx.x * blockDim.x + threadIdx.x;
    if (t >= NM * 32) return;
    int i = t >> 5, c4 = (t & 31) * 4;
    float4 v = *(const float4*)&g_tmp[(size_t)i * DD + c4];
    float4 p = *(const float4*)&g_pe[genre[i] * DD + c4];
    float4 bb = *(const float4*)(fus_b + c4);
    v.x = leakyf(v.x + p.x + bb.x, 0.01f);
    v.y = leakyf(v.y + p.y + bb.y, 0.01f);
    v.z = leakyf(v.z + p.z + bb.z, 0.01f);
    v.w = leakyf(v.w + p.w + bb.w, 0.01f);
    *(float4*)&out[(size_t)movie_idx[i] * DD + c4] = v;
}

// ---------------- launch ----------------
extern "C" void kernel_launch(void* const* d_in, const int* in_sizes, int n_in,
                              void* d_out, int out_size)
{
    const float* x        = (const float*)d_in[0];
    const int*   e0       = (const int*)d_in[1];
    const int*   e1       = (const int*)d_in[2];
    const int*   e2       = (const int*)d_in[3];
    const int*   movie_idx = (const int*)d_in[4];
    const int*   genre     = (const int*)d_in[5];
    const float* gat_W    = (const float*)d_in[6];
    const float* att_src  = (const float*)d_in[7];
    const float* att_dst  = (const float*)d_in[8];
    const float* gat_bias = (const float*)d_in[9];
    const float* dec_W    = (const float*)d_in[10];
    const float* dec_b    = (const float*)d_in[11];
    const float* qkv_w    = (const float*)d_in[12];
    const float* qkv_b    = (const float*)d_in[13];
    const float* out_w    = (const float*)d_in[14];
    const float* out_b    = (const float*)d_in[15];
    const float* ln1_g    = (const float*)d_in[16];
    const float* ln1_b    = (const float*)d_in[17];
    const float* ln2_g    = (const float*)d_in[18];
    const float* ln2_b    = (const float*)d_in[19];
    const float* ffn_w1   = (const float*)d_in[20];
    const float* ffn_b1   = (const float*)d_in[21];
    const float* ffn_w2   = (const float*)d_in[22];
    const float* ffn_b2   = (const float*)d_in[23];
    const float* fus_w    = (const float*)d_in[24];
    const float* fus_b    = (const float*)d_in[25];
    float* out = (float*)d_out;

    float *p_h3, *p_gout3, *p_acc, *p_y, *p_qkv, *p_attn, *p_tmp, *p_ffn, *p_xm;
    cudaGetSymbolAddress((void**)&p_h3,    g_h3);
    cudaGetSymbolAddress((void**)&p_gout3, g_gout3);
    cudaGetSymbolAddress((void**)&p_acc,   g_acc);
    cudaGetSymbolAddress((void**)&p_y,     g_y);
    cudaGetSymbolAddress((void**)&p_qkv,   g_qkv);
    cudaGetSymbolAddress((void**)&p_attn,  g_attn);
    cudaGetSymbolAddress((void**)&p_tmp,   g_tmp);
    cudaGetSymbolAddress((void**)&p_ffn,   g_ffn);
    cudaGetSymbolAddress((void**)&p_xm,    g_xm);

    const int GSMEM = 4 * TBUF * 4;   // 73728 B double-buffered tiles
    cudaFuncSetAttribute(gemm_mma, cudaFuncAttributeMaxDynamicSharedMemorySize, GSMEM);

    const int MTN = (NN + 127) / 128;  // 391
    const int MT  = (NM + 127) / 128;  // 160

    // -------- GAT: h3 = x @ [W0;W1;W2]^T in one GEMM --------
    zero_acc_kernel<<<(NN * DD / 4 + 255) / 256, 256>>>();
    gemm_mma<<<dim3(3, MTN), 256, GSMEM>>>(x, gat_W, nullptr, p_h3,
                                           NN, 384, DD, DD, DD, 0, 0.f);
    gat_prep3<<<dim3((NN * 32 + 255) / 256, 3), 256>>>(att_src, att_dst, gat_bias);
    edge_exp3<<<dim3((NITEMS + 255) / 256, 3), 256>>>(e0, e1, e2);
    edge_aggr3<<<dim3(((size_t)NITEMS * 32 + 255) / 256, 3), 256>>>(e0, e1, e2);
    for (int k = 0; k < 3; k++) {
        float scale = (float)exp(-0.1 * k);
        gemm_mma<<<dim3(1, MTN), 256, GSMEM>>>(
            p_gout3 + k * 128, dec_W + (size_t)k * DD * DD, dec_b + k * DD,
            p_acc, NN, DD, DD, 384, DD, 2, scale);
    }

    // -------- build genre sequences --------
    hist_kernel<<<NCHUNK, 128>>>(genre);
    scan_kernel<<<1, 32>>>();
    pos_kernel<<<1, 256>>>(genre);
    zero_y_kernel<<<(NM * DD / 4 + 255) / 256, 256>>>();
    gather_kernel<<<(NM * 32 + 255) / 256, 256>>>(movie_idx, genre);

    // -------- transformer (4 layers) --------
    for (int l = 0; l < NL; l++) {
        gemm_mma<<<dim3(3 * DD / 128, MT), 256, GSMEM>>>(
            p_y, qkv_w + (size_t)l * 3 * DD * DD, qkv_b + l * 3 * DD, p_qkv,
            NM, 3 * DD, DD, DD, DD, 0, 0.f);
        attn_tc<<<dim3((LMAX + 127) / 128, NHEADS, NG), 256>>>();
        gemm_mma<<<dim3(1, MT), 256, GSMEM>>>(
            p_attn, out_w + (size_t)l * DD * DD, out_b + l * DD, p_tmp,
            NM, DD, DD, DD, DD, 0, 0.f);
        ln_kernel<<<(NM * 32 + 255) / 256, 256>>>(p_y, p_tmp, ln1_g + l * DD, ln1_b + l * DD, NM);
        gemm_mma<<<dim3(FFD / 128, MT), 256, GSMEM>>>(
            p_y, ffn_w1 + (size_t)l * FFD * DD, ffn_b1 + l * FFD, p_ffn,
            NM, FFD, DD, DD, DD, 1, 0.f);
        gemm_mma<<<dim3(1, MT), 256, GSMEM>>>(
            p_ffn, ffn_w2 + (size_t)l * DD * FFD, ffn_b2 + l * DD, p_tmp,
            NM, DD, FFD, FFD, FFD, 0, 0.f);
        ln_kernel<<<(NM * 32 + 255) / 256, 256>>>(p_y, p_tmp, ln2_g + l * DD, ln2_b + l * DD, NM);
    }

    // -------- pool + fuse + write output --------
    pool_kernel<<<NG, DD>>>();
    pe_kernel<<<NG, DD>>>(fus_w);
    gemm_mma<<<dim3(1, MT), 256, GSMEM>>>(p_xm, fus_w, nullptr, p_tmp,
                                          NM, DD, DD, DD, 256, 0, 0.f);
    copy_out_kernel<<<(NN * DD / 4 + 255) / 256, 256>>>(out);
    fuse_out_kernel<<<(NM * 32 + 255) / 256, 256>>>(movie_idx, genre, fus_b, out);
}

// round 7
// speedup vs baseline: 3.3201x; 1.3109x over previous
#include <cuda_runtime.h>
#include <cuda_fp16.h>
#include <math.h>
#include <stdint.h>

#define NN 50000
#define NE 400000
#define DD 128
#define NM 20400
#define NG 30
#define LMAX 680
#define NHEADS 4
#define NL 4
#define FFD 2048
#define NCHUNK 160   // ceil(20400/128)
#define NITEMS (NE + NN)

// ---------------- scratch (device globals; no runtime allocation) ----------------
__device__ __align__(16) float g_h3[(size_t)NN * 384];     // per-hop GAT features
__device__ __align__(16) float g_gout3[(size_t)NN * 384];  // per-hop aggregation
__device__ __align__(16) float g_acc[(size_t)NN * DD];
__device__ __align__(16) float g_als3[NN * 3 * NHEADS];
__device__ __align__(16) float g_ald3[NN * 3 * NHEADS];
__device__ __align__(16) float g_den3[NN * 3 * NHEADS];
__device__ __align__(16) float g_ew[(size_t)3 * NITEMS * NHEADS];
__device__ __align__(16) float g_y[(size_t)NM * DD];
__device__ __align__(16) float g_qkv[(size_t)NM * 3 * DD];
__device__ __align__(16) float g_attn[(size_t)NM * DD];
__device__ __align__(16) float g_tmp[(size_t)NM * DD];
__device__ __align__(16) float g_ffn[(size_t)NM * FFD];
__device__ __align__(16) float g_xm[(size_t)NM * DD];
__device__ __align__(16) float g_pooled[NG * DD];
__device__ __align__(16) float g_pe[NG * DD];
__device__ int g_pos[NM];
__device__ int g_cnt[NG];
__device__ int g_chist[NCHUNK * NG];

// ---------------- small helpers ----------------
__device__ __forceinline__ float leakyf(float x, float s) { return x >= 0.f ? x : s * x; }

__device__ __forceinline__ uint32_t f2h2(float lo, float hi) {
    uint32_t r;
    asm("cvt.rn.f16x2.f32 %0, %1, %2;" : "=r"(r) : "f"(hi), "f"(lo));
    return r;
}

__device__ __forceinline__ void mma16(float* c, uint32_t a0, uint32_t a1, uint32_t a2,
                                      uint32_t a3, uint32_t b0, uint32_t b1) {
    asm volatile(
        "mma.sync.aligned.m16n8k16.row.col.f32.f16.f16.f32 "
        "{%0,%1,%2,%3}, {%4,%5,%6,%7}, {%8,%9}, {%0,%1,%2,%3};"
        : "+f"(c[0]), "+f"(c[1]), "+f"(c[2]), "+f"(c[3])
        : "r"(a0), "r"(a1), "r"(a2), "r"(a3), "r"(b0), "r"(b1));
}

// ---------------- pipelined fp16 mma GEMM ----------------
// C[M,N] = epi(A[M,K(lda)] * B[N,K(ldb)]^T + bias), fp32 accumulate.
// epi: 0 = store (+bias), 1 = relu(+bias), 2 = C += scale*leaky_{0.01}(v+bias)
// N multiple of 128, K multiple of 32. grid (N/128, ceil(M/128)), block 256,
// dynamic smem = 4*TBUF*4 bytes (double-buffered A+B half tiles).
// SMEM row = 32 halves + pad, stride 20 words: frag banks (20*lq+lr)%32 cover all 32.
#define SRW 20
#define TBUF (128 * SRW)
__global__ __launch_bounds__(256) void gemm_mma(
    const float* __restrict__ A, const float* __restrict__ B,
    const float* __restrict__ bias, float* __restrict__ C,
    int M, int N, int K, int lda, int ldb, int epi, float scale)
{
    extern __shared__ uint32_t sm[];
    const int tid = threadIdx.x;
    const int wid = tid >> 5, lane = tid & 31;
    const int wm = wid & 1, wn = wid >> 1;       // warp tile: 64 rows x 32 cols
    const int row0 = blockIdx.y * 128, col0 = blockIdx.x * 128;
    const int lq = lane >> 2, lr = lane & 3;

    float acc[4][4][4];
#pragma unroll
    for (int i = 0; i < 4; i++)
#pragma unroll
        for (int j = 0; j < 4; j++) {
            acc[i][j][0] = 0.f; acc[i][j][1] = 0.f;
            acc[i][j][2] = 0.f; acc[i][j][3] = 0.f;
        }

    const int s_row = tid >> 3;                  // staging: 8 threads per row
    const int s_c4 = (tid & 7) * 4;              // half offset within row
    const int s_w2 = (tid & 7) * 2;              // word offset
    const int nC = K >> 5;

    float4 pa[4], pb[4];

#define LDG_CHUNK(cc)                                                                \
    {                                                                                \
        int k0 = (cc) << 5;                                                          \
        _Pragma("unroll")                                                            \
        for (int it = 0; it < 4; it++) {                                             \
            int row = it * 32 + s_row;                                               \
            int gr = row0 + row;                                                     \
            pa[it] = make_float4(0.f, 0.f, 0.f, 0.f);                                \
            if (gr < M) pa[it] = *(const float4*)(A + (size_t)gr * lda + k0 + s_c4); \
            pb[it] = *(const float4*)(B + (size_t)(col0 + row) * ldb + k0 + s_c4);   \
        }                                                                            \
    }
#define STS_CHUNK(Ad, Bd)                                                            \
    {                                                                                \
        _Pragma("unroll")                                                            \
        for (int it = 0; it < 4; it++) {                                             \
            int row = it * 32 + s_row;                                               \
            uint2 ua, ub;                                                            \
            ua.x = f2h2(pa[it].x, pa[it].y); ua.y = f2h2(pa[it].z, pa[it].w);        \
            ub.x = f2h2(pb[it].x, pb[it].y); ub.y = f2h2(pb[it].z, pb[it].w);        \
            *(uint2*)&(Ad)[row * SRW + s_w2] = ua;                                   \
            *(uint2*)&(Bd)[row * SRW + s_w2] = ub;                                   \
        }                                                                            \
    }
#define COMPUTE_KS(Asb, Bsb, KS)                                                     \
    {                                                                                \
        int kb = (KS) * 8 + lr;                                                      \
        uint2 bf[4];                                                                 \
        _Pragma("unroll")                                                            \
        for (int nt = 0; nt < 4; nt++) {                                             \
            int n = wn * 32 + nt * 8 + lq;                                           \
            bf[nt].x = (Bsb)[n * SRW + kb];                                          \
            bf[nt].y = (Bsb)[n * SRW + kb + 4];                                      \
        }                                                                            \
        _Pragma("unroll")                                                            \
        for (int mt = 0; mt < 4; mt++) {                                             \
            int r = wm * 64 + mt * 16 + lq;                                          \
            uint32_t a0 = (Asb)[r * SRW + kb];                                       \
            uint32_t a1 = (Asb)[(r + 8) * SRW + kb];                                 \
            uint32_t a2 = (Asb)[r * SRW + kb + 4];                                   \
            uint32_t a3 = (Asb)[(r + 8) * SRW + kb + 4];                             \
            _Pragma("unroll")                                                        \
            for (int nt = 0; nt < 4; nt++)                                           \
                mma16(acc[mt][nt], a0, a1, a2, a3, bf[nt].x, bf[nt].y);              \
        }                                                                            \
    }

    uint32_t* A0 = sm;
    uint32_t* B0 = sm + TBUF;
    uint32_t* A1 = sm + 2 * TBUF;
    uint32_t* B1 = sm + 3 * TBUF;

    LDG_CHUNK(0);
    STS_CHUNK(A0, B0);
    if (nC > 1) LDG_CHUNK(1);
    __syncthreads();

    for (int c = 0; c < nC; c++) {
        uint32_t* Asb = (c & 1) ? A1 : A0;
        uint32_t* Bsb = (c & 1) ? B1 : B0;
        uint32_t* Asn = (c & 1) ? A0 : A1;
        uint32_t* Bsn = (c & 1) ? B0 : B1;
        COMPUTE_KS(Asb, Bsb, 0);
        if (c + 1 < nC) STS_CHUNK(Asn, Bsn);
        COMPUTE_KS(Asb, Bsb, 1);
        if (c + 2 < nC) LDG_CHUNK(c + 2);
        __syncthreads();
    }

    // ---- epilogue ----
    const int rbase = row0 + wm * 64;
    const int cbase = col0 + wn * 32;
#pragma unroll
    for (int mt = 0; mt < 4; mt++) {
        int r0 = rbase + mt * 16 + lq;
#pragma unroll
        for (int half = 0; half < 2; half++) {
            int r = r0 + half * 8;
            if (r < M) {
#pragma unroll
                for (int nt = 0; nt < 4; nt++) {
                    int c = cbase + nt * 8 + lr * 2;
                    float v0 = acc[mt][nt][half * 2 + 0];
                    float v1 = acc[mt][nt][half * 2 + 1];
                    if (bias) { v0 += bias[c]; v1 += bias[c + 1]; }
                    float* cp = C + (size_t)r * N + c;
                    if (epi == 0) {
                        *(float2*)cp = make_float2(v0, v1);
                    } else if (epi == 1) {
                        *(float2*)cp = make_float2(fmaxf(v0, 0.f), fmaxf(v1, 0.f));
                    } else {
                        float2 o = *(float2*)cp;
                        o.x += scale * leakyf(v0, 0.01f);
                        o.y += scale * leakyf(v1, 0.01f);
                        *(float2*)cp = o;
                    }
                }
            }
        }
    }
}

// ---------------- fp16 tensor-core flash attention ----------------
// grid (6 qtiles, NHEADS, NG), block 256 (8 warps x 16 query rows).
// S C-fragment packs directly into the m16n8k16 A-fragment of P (no shuffles).
#define VSW 68   // VT row stride in words (136 halves)
__global__ __launch_bounds__(256) void attn_tc() {
    __shared__ uint32_t QK[128 * SRW];   // Q first, then K blocks (halves)
    __shared__ uint32_t VT[32 * VSW];    // V transposed [dim][key-pair words]
    const int b = blockIdx.z, h = blockIdx.y, qt = blockIdx.x;
    const int cnt = g_cnt[b];
    const int tid = threadIdx.x, wid = tid >> 5, lane = tid & 31;
    const int lq = lane >> 2, lr = lane & 3;
    const float qscale = 0.17677669529663687f;   // 1/sqrt(32)

    // ---- stage Q (scaled, fp16) ----
#pragma unroll
    for (int it = 0; it < 4; it++) {
        int idx = it * 256 + tid;
        int row = idx >> 3, c4 = (idx & 7) * 4;
        int q = qt * 128 + row;
        float4 v = make_float4(0.f, 0.f, 0.f, 0.f);
        if (q < LMAX) v = *(const float4*)(g_qkv + (size_t)(b * LMAX + q) * 384 + h * 32 + c4);
        uint2 u;
        u.x = f2h2(v.x * qscale, v.y * qscale);
        u.y = f2h2(v.z * qscale, v.w * qscale);
        *(uint2*)&QK[row * SRW + (idx & 7) * 2] = u;
    }
    __syncthreads();
    // ---- Q A-fragments (2 k16 steps) ----
    uint32_t qa[2][4];
    {
        int r = wid * 16 + lq;
#pragma unroll
        for (int ks = 0; ks < 2; ks++) {
            int kb = ks * 8 + lr;
            qa[ks][0] = QK[r * SRW + kb];
            qa[ks][1] = QK[(r + 8) * SRW + kb];
            qa[ks][2] = QK[r * SRW + kb + 4];
            qa[ks][3] = QK[(r + 8) * SRW + kb + 4];
        }
    }

    float m0 = -INFINITY, m1 = -INFINITY, den0 = 0.f, den1 = 0.f;
    float of[4][4];
#pragma unroll
    for (int nt = 0; nt < 4; nt++) {
        of[nt][0] = 0.f; of[nt][1] = 0.f; of[nt][2] = 0.f; of[nt][3] = 0.f;
    }

    for (int kb0 = 0; kb0 < LMAX; kb0 += 128) {
        __syncthreads();   // prior reads of QK/VT complete
        // ---- stage K (fp16, row=key) ----
#pragma unroll
        for (int it = 0; it < 4; it++) {
            int idx = it * 256 + tid;
            int row = idx >> 3, c4 = (idx & 7) * 4;
            int key = kb0 + row;
            float4 kv = make_float4(0.f, 0.f, 0.f, 0.f);
            if (key < LMAX)
                kv = *(const float4*)(g_qkv + (size_t)(b * LMAX + key) * 384 + 128 + h * 32 + c4);
            uint2 u;
            u.x = f2h2(kv.x, kv.y); u.y = f2h2(kv.z, kv.w);
            *(uint2*)&QK[row * SRW + (idx & 7) * 2] = u;
        }
        // ---- stage V^T: word[d*VSW + kp] = half2(V[2kp][d], V[2kp+1][d]) ----
#pragma unroll
        for (int it = 0; it < 2; it++) {
            int item = it * 256 + tid;          // 512 items
            int kp = item & 63, g = item >> 6;  // key pair, dim group (4 dims)
            int k0 = kb0 + 2 * kp;
            float4 v0 = make_float4(0.f, 0.f, 0.f, 0.f);
            float4 v1 = make_float4(0.f, 0.f, 0.f, 0.f);
            if (k0 < LMAX)
                v0 = *(const float4*)(g_qkv + (size_t)(b * LMAX + k0) * 384 + 256 + h * 32 + g * 4);
            if (k0 + 1 < LMAX)
                v1 = *(const float4*)(g_qkv + (size_t)(b * LMAX + k0 + 1) * 384 + 256 + h * 32 + g * 4);
            VT[(g * 4 + 0) * VSW + kp] = f2h2(v0.x, v1.x);
            VT[(g * 4 + 1) * VSW + kp] = f2h2(v0.y, v1.y);
            VT[(g * 4 + 2) * VSW + kp] = f2h2(v0.z, v1.z);
            VT[(g * 4 + 3) * VSW + kp] = f2h2(v0.w, v1.w);
        }
        __syncthreads();

        // ---- S = Q·K^T : 2 ksteps x 16 key-tiles ----
        float sf[16][4];
#pragma unroll
        for (int nt = 0; nt < 16; nt++) {
            sf[nt][0] = 0.f; sf[nt][1] = 0.f; sf[nt][2] = 0.f; sf[nt][3] = 0.f;
        }
#pragma unroll
        for (int ks = 0; ks < 2; ks++) {
            int kk = ks * 8 + lr;
#pragma unroll
            for (int nt = 0; nt < 16; nt++) {
                uint32_t b0 = QK[(nt * 8 + lq) * SRW + kk];
                uint32_t b1 = QK[(nt * 8 + lq) * SRW + kk + 4];
                mma16(sf[nt], qa[ks][0], qa[ks][1], qa[ks][2], qa[ks][3], b0, b1);
            }
        }
        // ---- mask + block row-max (rows in quad: 4 lanes) ----
        float bm0 = -INFINITY, bm1 = -INFINITY;
#pragma unroll
        for (int nt = 0; nt < 16; nt++) {
            int c = kb0 + nt * 8 + lr * 2;
            if (c >= cnt) { sf[nt][0] = -1e30f; sf[nt][2] = -1e30f; }
            if (c + 1 >= cnt) { sf[nt][1] = -1e30f; sf[nt][3] = -1e30f; }
            bm0 = fmaxf(bm0, fmaxf(sf[nt][0], sf[nt][1]));
            bm1 = fmaxf(bm1, fmaxf(sf[nt][2], sf[nt][3]));
        }
        bm0 = fmaxf(bm0, __shfl_xor_sync(0xffffffffu, bm0, 1));
        bm0 = fmaxf(bm0, __shfl_xor_sync(0xffffffffu, bm0, 2));
        bm1 = fmaxf(bm1, __shfl_xor_sync(0xffffffffu, bm1, 1));
        bm1 = fmaxf(bm1, __shfl_xor_sync(0xffffffffu, bm1, 2));
        float nm0 = fmaxf(m0, bm0), nm1 = fmaxf(m1, bm1);
        float cor0 = __expf(m0 - nm0), cor1 = __expf(m1 - nm1);
        m0 = nm0; m1 = nm1;
        // ---- exp + row sum + fp16 P (packed directly as A-fragments) ----
        float s0 = 0.f, s1 = 0.f;
        uint32_t pf01[16], pf23[16];
#pragma unroll
        for (int nt = 0; nt < 16; nt++) {
            float p0 = __expf(sf[nt][0] - nm0), p1 = __expf(sf[nt][1] - nm0);
            float p2 = __expf(sf[nt][2] - nm1), p3 = __expf(sf[nt][3] - nm1);
            s0 += p0 + p1; s1 += p2 + p3;
            pf01[nt] = f2h2(p0, p1);
            pf23[nt] = f2h2(p2, p3);
        }
        s0 += __shfl_xor_sync(0xffffffffu, s0, 1);
        s0 += __shfl_xor_sync(0xffffffffu, s0, 2);
        s1 += __shfl_xor_sync(0xffffffffu, s1, 1);
        s1 += __shfl_xor_sync(0xffffffffu, s1, 2);
        den0 = den0 * cor0 + s0;
        den1 = den1 * cor1 + s1;
#pragma unroll
        for (int nt = 0; nt < 4; nt++) {
            of[nt][0] *= cor0; of[nt][1] *= cor0;
            of[nt][2] *= cor1; of[nt][3] *= cor1;
        }
        // ---- O += P·V : S C-frag == PV A-frag (no shuffles) ----
#pragma unroll
        for (int ks = 0; ks < 8; ks++) {
            uint32_t a0 = pf01[2 * ks], a1 = pf23[2 * ks];
            uint32_t a2 = pf01[2 * ks + 1], a3 = pf23[2 * ks + 1];
#pragma unroll
            for (int nt = 0; nt < 4; nt++) {
                uint32_t b0 = VT[(nt * 8 + lq) * VSW + 8 * ks + lr];
                uint32_t b1 = VT[(nt * 8 + lq) * VSW + 8 * ks + lr + 4];
                mma16(of[nt], a0, a1, a2, a3, b0, b1);
            }
        }
    }

    // ---- write O ----
    float i0 = 1.f / den0, i1 = 1.f / den1;
    int q_lo = qt * 128 + wid * 16 + lq, q_hi = q_lo + 8;
#pragma unroll
    for (int nt = 0; nt < 4; nt++) {
        int col = h * 32 + nt * 8 + lr * 2;
        if (q_lo < LMAX)
            *(float2*)(g_attn + (size_t)(b * LMAX + q_lo) * DD + col) =
                make_float2(of[nt][0] * i0, of[nt][1] * i0);
        if (q_hi < LMAX)
            *(float2*)(g_attn + (size_t)(b * LMAX + q_hi) * DD + col) =
                make_float2(of[nt][2] * i1, of[nt][3] * i1);
    }
}

// ---------------- GAT kernels (batched over hops) ----------------
__global__ void zero_acc_kernel() {
    size_t i = (size_t)blockIdx.x * blockDim.x + threadIdx.x;
    if (i < (size_t)NN * DD / 4) ((float4*)g_acc)[i] = make_float4(0.f, 0.f, 0.f, 0.f);
}
__global__ void zero_y_kernel() {
    size_t i = (size_t)blockIdx.x * blockDim.x + threadIdx.x;
    if (i < (size_t)NM * DD / 4) ((float4*)g_y)[i] = make_float4(0.f, 0.f, 0.f, 0.f);
}

__global__ void gat_prep3(const float* __restrict__ a_src,
                          const float* __restrict__ a_dst,
                          const float* __restrict__ bias)
{
    int gid = blockIdx.x * blockDim.x + threadIdx.x;
    int node = gid >> 5, lane = gid & 31;
    int hop = blockIdx.y;
    if (node >= NN) return;
    float s[4], d[4];
#pragma unroll
    for (int j = 0; j < 4; j++) {
        int c = j * 32 + lane;
        float hv = g_h3[(size_t)node * 384 + hop * 128 + c];
        s[j] = hv * a_src[hop * DD + c];
        d[j] = hv * a_dst[hop * DD + c];
        g_gout3[(size_t)node * 384 + hop * 128 + c] = bias[hop * DD + c];
    }
#pragma unroll
    for (int j = 0; j < 4; j++)
#pragma unroll
        for (int o = 16; o > 0; o >>= 1) {
            s[j] += __shfl_xor_sync(0xffffffffu, s[j], o);
            d[j] += __shfl_xor_sync(0xffffffffu, d[j], o);
        }
    if (lane == 0) {
        int idx = (node * 3 + hop) * 4;
        *(float4*)&g_als3[idx] = make_float4(s[0], s[1], s[2], s[3]);
        *(float4*)&g_ald3[idx] = make_float4(d[0], d[1], d[2], d[3]);
        *(float4*)&g_den3[idx] = make_float4(0.f, 0.f, 0.f, 0.f);
    }
}

// pass 1: ew = exp(leaky(als+ald)) stored; den += ew. blockIdx.y = hop.
__global__ void edge_exp3(const int* __restrict__ e0, const int* __restrict__ e1,
                          const int* __restrict__ e2)
{
    int hop = blockIdx.y;
    const int* ei = (hop == 0) ? e0 : (hop == 1) ? e1 : e2;
    int t = blockIdx.x * blockDim.x + threadIdx.x;
    if (t >= NITEMS) return;
    int src, dst;
    if (t < NE) { src = ei[t]; dst = ei[NE + t]; }
    else { src = dst = t - NE; }
    float4 a = *(const float4*)&g_als3[(src * 3 + hop) * 4];
    float4 b = *(const float4*)&g_ald3[(dst * 3 + hop) * 4];
    float4 ew;
    ew.x = expf(leakyf(a.x + b.x, 0.2f));
    ew.y = expf(leakyf(a.y + b.y, 0.2f));
    ew.z = expf(leakyf(a.z + b.z, 0.2f));
    ew.w = expf(leakyf(a.w + b.w, 0.2f));
    *(float4*)&g_ew[((size_t)hop * NITEMS + t) * 4] = ew;
    float* dn = &g_den3[(dst * 3 + hop) * 4];
    atomicAdd(dn + 0, ew.x);
    atomicAdd(dn + 1, ew.y);
    atomicAdd(dn + 2, ew.z);
    atomicAdd(dn + 3, ew.w);
}

// pass 2: warp per item, gout3[dst] += (ew/den) * h3[src]. blockIdx.y = hop.
__global__ void edge_aggr3(const int* __restrict__ e0, const int* __restrict__ e1,
                           const int* __restrict__ e2)
{
    int hop = blockIdx.y;
    const int* ei = (hop == 0) ? e0 : (hop == 1) ? e1 : e2;
    int gid = blockIdx.x * blockDim.x + threadIdx.x;
    int item = gid >> 5, lane = gid & 31;
    if (item >= NITEMS) return;
    int src, dst;
    if (item < NE) { src = ei[item]; dst = ei[NE + item]; }
    else { src = dst = item - NE; }
    float4 ew = *(const float4*)&g_ew[((size_t)hop * NITEMS + item) * 4];
    float4 dn = *(const float4*)&g_den3[(dst * 3 + hop) * 4];
    float al[4] = {ew.x / dn.x, ew.y / dn.y, ew.z / dn.z, ew.w / dn.w};
    const float* hsrc = g_h3 + (size_t)src * 384 + hop * 128;
    float* gd = g_gout3 + (size_t)dst * 384 + hop * 128;
#pragma unroll
    for (int j = 0; j < 4; j++) {
        int c = j * 32 + lane;
        atomicAdd(gd + c, hsrc[c] * al[j]);
    }
}

// ---------------- position / count kernels ----------------
__global__ void hist_kernel(const int* __restrict__ genre) {
    __shared__ int loc[NG];
    if (threadIdx.x < NG) loc[threadIdx.x] = 0;
    __syncthreads();
    int i = blockIdx.x * 128 + threadIdx.x;
    if (i < NM) atomicAdd(&loc[genre[i]], 1);
    __syncthreads();
    if (threadIdx.x < NG) g_chist[blockIdx.x * NG + threadIdx.x] = loc[threadIdx.x];
}
__global__ void scan_kernel() {
    int g = threadIdx.x;
    if (g >= NG) return;
    int run = 0;
    for (int c = 0; c < NCHUNK; c++) {
        int t = g_chist[c * NG + g];
        g_chist[c * NG + g] = run;
        run += t;
    }
    g_cnt[g] = run;
}
__global__ void pos_kernel(const int* __restrict__ genre) {
    int c = blockIdx.x * blockDim.x + threadIdx.x;
    if (c >= NCHUNK) return;
    int off[NG];
    for (int g = 0; g < NG; g++) off[g] = g_chist[c * NG + g];
    int base = c * 128;
    int end = base + 128; if (end > NM) end = NM;
    for (int i = base; i < end; i++) {
        int g = genre[i];
        g_pos[i] = off[g]++;
    }
}

__global__ void gather_kernel(const int* __restrict__ movie_idx, const int* __restrict__ genre) {
    int t = blockIdx.x * blockDim.x + threadIdx.x;
    if (t >= NM * 32) return;
    int i = t >> 5, c4 = (t & 31) * 4;
    float4 v = *(const float4*)&g_acc[(size_t)movie_idx[i] * DD + c4];
    *(float4*)&g_xm[(size_t)i * DD + c4] = v;
    int row = genre[i] * LMAX + g_pos[i];
    *(float4*)&g_y[(size_t)row * DD + c4] = v;
}

// ---------------- LayerNorm (fused residual): y = LN(y + t) ----------------
__global__ void ln_kernel(float* __restrict__ y, const float* __restrict__ t,
                          const float* __restrict__ gam, const float* __restrict__ bet,
                          int rows)
{
    int gid = blockIdx.x * blockDim.x + threadIdx.x;
    int row = gid >> 5, lane = gid & 31;
    if (row >= rows) return;
    size_t off = (size_t)row * DD + lane * 4;
    float4 v = *(float4*)(y + off);
    float4 tv = *(const float4*)(t + off);
    v.x += tv.x; v.y += tv.y; v.z += tv.z; v.w += tv.w;
    float s = v.x + v.y + v.z + v.w;
#pragma unroll
    for (int o = 16; o > 0; o >>= 1) s += __shfl_xor_sync(0xffffffffu, s, o);
    float mean = s * (1.f / DD);
    float dx = v.x - mean, dy = v.y - mean, dz = v.z - mean, dw = v.w - mean;
    float ss = dx * dx + dy * dy + dz * dz + dw * dw;
#pragma unroll
    for (int o = 16; o > 0; o >>= 1) ss += __shfl_xor_sync(0xffffffffu, ss, o);
    float inv = rsqrtf(ss * (1.f / DD) + 1e-5f);
    float4 gg = *(const float4*)(gam + lane * 4);
    float4 bb = *(const float4*)(bet + lane * 4);
    v.x = dx * inv * gg.x + bb.x;
    v.y = dy * inv * gg.y + bb.y;
    v.z = dz * inv * gg.z + bb.z;
    v.w = dw * inv * gg.w + bb.w;
    *(float4*)(y + off) = v;
}

// ---------------- pooling / fusion ----------------
__global__ void pool_kernel() {
    int g = blockIdx.x, d = threadIdx.x;
    int cnt = g_cnt[g];
    float s = 0.f;
    for (int t = 0; t < cnt; t++) s += g_y[(size_t)(g * LMAX + t) * DD + d];
    g_pooled[g * DD + d] = s / fmaxf((float)cnt, 1.f);
}

__global__ void pe_kernel(const float* __restrict__ fus_w) {
    int g = blockIdx.x, n = threadIdx.x;
    float s = 0.f;
    for (int k = 0; k < DD; k++)
        s += g_pooled[g * DD + k] * fus_w[n * 256 + 128 + k];
    g_pe[g * DD + n] = s;
}

__global__ void copy_out_kernel(float* __restrict__ out) {
    size_t i = (size_t)blockIdx.x * blockDim.x + threadIdx.x;
    if (i < (size_t)NN * DD / 4) ((float4*)out)[i] = ((const float4*)g_acc)[i];
}

__global__ void fuse_out_kernel(const int* __restrict__ movie_idx, const int* __restrict__ genre,
                                const float* __restrict__ fus_b, float* __restrict__ out)
{
    int t = blockIdx.x * blockDim.x + threadIdx.x;
    if (t >= NM * 32) return;
    int i = t >> 5, c4 = (t & 31) * 4;
    float4 v = *(const float4*)&g_tmp[(size_t)i * DD + c4];
    float4 p = *(const float4*)&g_pe[genre[i] * DD + c4];
    float4 bb = *(const float4*)(fus_b + c4);
    v.x = leakyf(v.x + p.x + bb.x, 0.01f);
    v.y = leakyf(v.y + p.y + bb.y, 0.01f);
    v.z = leakyf(v.z + p.z + bb.z, 0.01f);
    v.w = leakyf(v.w + p.w + bb.w, 0.01f);
    *(float4*)&out[(size_t)movie_idx[i] * DD + c4] = v;
}

// ---------------- launch ----------------
extern "C" void kernel_launch(void* const* d_in, const int* in_sizes, int n_in,
                              void* d_out, int out_size)
{
    const float* x        = (const float*)d_in[0];
    const int*   e0       = (const int*)d_in[1];
    const int*   e1       = (const int*)d_in[2];
    const int*   e2       = (const int*)d_in[3];
    const int*   movie_idx = (const int*)d_in[4];
    const int*   genre     = (const int*)d_in[5];
    const float* gat_W    = (const float*)d_in[6];
    const float* att_src  = (const float*)d_in[7];
    const float* att_dst  = (const float*)d_in[8];
    const float* gat_bias = (const float*)d_in[9];
    const float* dec_W    = (const float*)d_in[10];
    const float* dec_b    = (const float*)d_in[11];
    const float* qkv_w    = (const float*)d_in[12];
    const float* qkv_b    = (const float*)d_in[13];
    const float* out_w    = (const float*)d_in[14];
    const float* out_b    = (const float*)d_in[15];
    const float* ln1_g    = (const float*)d_in[16];
    const float* ln1_b    = (const float*)d_in[17];
    const float* ln2_g    = (const float*)d_in[18];
    const float* ln2_b    = (const float*)d_in[19];
    const float* ffn_w1   = (const float*)d_in[20];
    const float* ffn_b1   = (const float*)d_in[21];
    const float* ffn_w2   = (const float*)d_in[22];
    const float* ffn_b2   = (const float*)d_in[23];
    const float* fus_w    = (const float*)d_in[24];
    const float* fus_b    = (const float*)d_in[25];
    float* out = (float*)d_out;

    float *p_h3, *p_gout3, *p_acc, *p_y, *p_qkv, *p_attn, *p_tmp, *p_ffn, *p_xm;
    cudaGetSymbolAddress((void**)&p_h3,    g_h3);
    cudaGetSymbolAddress((void**)&p_gout3, g_gout3);
    cudaGetSymbolAddress((void**)&p_acc,   g_acc);
    cudaGetSymbolAddress((void**)&p_y,     g_y);
    cudaGetSymbolAddress((void**)&p_qkv,   g_qkv);
    cudaGetSymbolAddress((void**)&p_attn,  g_attn);
    cudaGetSymbolAddress((void**)&p_tmp,   g_tmp);
    cudaGetSymbolAddress((void**)&p_ffn,   g_ffn);
    cudaGetSymbolAddress((void**)&p_xm,    g_xm);

    const int GSMEM = 4 * TBUF * 4;   // 40960 B double-buffered half tiles
    cudaFuncSetAttribute(gemm_mma, cudaFuncAttributeMaxDynamicSharedMemorySize, GSMEM);

    const int MTN = (NN + 127) / 128;  // 391
    const int MT  = (NM + 127) / 128;  // 160

    // -------- GAT: h3 = x @ [W0;W1;W2]^T in one GEMM --------
    zero_acc_kernel<<<(NN * DD / 4 + 255) / 256, 256>>>();
    gemm_mma<<<dim3(3, MTN), 256, GSMEM>>>(x, gat_W, nullptr, p_h3,
                                           NN, 384, DD, DD, DD, 0, 0.f);
    gat_prep3<<<dim3((NN * 32 + 255) / 256, 3), 256>>>(att_src, att_dst, gat_bias);
    edge_exp3<<<dim3((NITEMS + 255) / 256, 3), 256>>>(e0, e1, e2);
    edge_aggr3<<<dim3(((size_t)NITEMS * 32 + 255) / 256, 3), 256>>>(e0, e1, e2);
    for (int k = 0; k < 3; k++) {
        float scale = (float)exp(-0.1 * k);
        gemm_mma<<<dim3(1, MTN), 256, GSMEM>>>(
            p_gout3 + k * 128, dec_W + (size_t)k * DD * DD, dec_b + k * DD,
            p_acc, NN, DD, DD, 384, DD, 2, scale);
    }

    // -------- build genre sequences --------
    hist_kernel<<<NCHUNK, 128>>>(genre);
    scan_kernel<<<1, 32>>>();
    pos_kernel<<<1, 256>>>(genre);
    zero_y_kernel<<<(NM * DD / 4 + 255) / 256, 256>>>();
    gather_kernel<<<(NM * 32 + 255) / 256, 256>>>(movie_idx, genre);

    // -------- transformer (4 layers) --------
    for (int l = 0; l < NL; l++) {
        gemm_mma<<<dim3(3 * DD / 128, MT), 256, GSMEM>>>(
            p_y, qkv_w + (size_t)l * 3 * DD * DD, qkv_b + l * 3 * DD, p_qkv,
            NM, 3 * DD, DD, DD, DD, 0, 0.f);
        attn_tc<<<dim3((LMAX + 127) / 128, NHEADS, NG), 256>>>();
        gemm_mma<<<dim3(1, MT), 256, GSMEM>>>(
            p_attn, out_w + (size_t)l * DD * DD, out_b + l * DD, p_tmp,
            NM, DD, DD, DD, DD, 0, 0.f);
        ln_kernel<<<(NM * 32 + 255) / 256, 256>>>(p_y, p_tmp, ln1_g + l * DD, ln1_b + l * DD, NM);
        gemm_mma<<<dim3(FFD / 128, MT), 256, GSMEM>>>(
            p_y, ffn_w1 + (size_t)l * FFD * DD, ffn_b1 + l * FFD, p_ffn,
            NM, FFD, DD, DD, DD, 1, 0.f);
        gemm_mma<<<dim3(1, MT), 256, GSMEM>>>(
            p_ffn, ffn_w2 + (size_t)l * DD * FFD, ffn_b2 + l * DD, p_tmp,
            NM, DD, FFD, FFD, FFD, 0, 0.f);
        ln_kernel<<<(NM * 32 + 255) / 256, 256>>>(p_y, p_tmp, ln2_g + l * DD, ln2_b + l * DD, NM);
    }

    // -------- pool + fuse + write output --------
    pool_kernel<<<NG, DD>>>();
    pe_kernel<<<NG, DD>>>(fus_w);
    gemm_mma<<<dim3(1, MT), 256, GSMEM>>>(p_xm, fus_w, nullptr, p_tmp,
                                          NM, DD, DD, DD, 256, 0, 0.f);
    copy_out_kernel<<<(NN * DD / 4 + 255) / 256, 256>>>(out);
    fuse_out_kernel<<<(NM * 32 + 255) / 256, 256>>>(movie_idx, genre, fus_b, out);
}

// round 8
// speedup vs baseline: 3.5650x; 1.0738x over previous
#include <cuda_runtime.h>
#include <cuda_fp16.h>
#include <math.h>
#include <stdint.h>

#define NN 50000
#define NE 400000
#define DD 128
#define NM 20400
#define NG 30
#define LMAX 680
#define NHEADS 4
#define NL 4
#define FFD 2048
#define NCHUNK 160   // ceil(20400/128)
#define NITEMS (NE + NN)

// ---------------- scratch (device globals; no runtime allocation) ----------------
__device__ __align__(16) float g_h3[(size_t)NN * 384];     // per-hop GAT features
__device__ __align__(16) float g_gout3[(size_t)NN * 384];  // per-hop aggregation
__device__ __align__(16) float g_acc[(size_t)NN * DD];
__device__ __align__(16) float g_als3[NN * 3 * NHEADS];
__device__ __align__(16) float g_ald3[NN * 3 * NHEADS];
__device__ __align__(16) float g_ew[(size_t)3 * NITEMS * NHEADS];  // sorted exp numerators
__device__ int g_srcS[(size_t)3 * NITEMS];                         // sorted srcs
__device__ int g_deg[3 * NN];
__device__ int g_off[3 * (NN + 1)];
__device__ int g_cur[3 * NN];
__device__ __align__(16) float g_y[(size_t)NM * DD];
__device__ __align__(16) float g_qkv[(size_t)NM * 3 * DD];
__device__ __align__(16) float g_attn[(size_t)NM * DD];
__device__ __align__(16) float g_tmp[(size_t)NM * DD];
__device__ __align__(16) float g_ffn[(size_t)NM * FFD];
__device__ __align__(16) float g_xm[(size_t)NM * DD];
__device__ __align__(16) float g_pooled[NG * DD];
__device__ __align__(16) float g_pe[NG * DD];
__device__ int g_pos[NM];
__device__ int g_cnt[NG];
__device__ int g_chist[NCHUNK * NG];

// ---------------- small helpers ----------------
__device__ __forceinline__ float leakyf(float x, float s) { return x >= 0.f ? x : s * x; }

__device__ __forceinline__ uint32_t f2h2(float lo, float hi) {
    uint32_t r;
    asm("cvt.rn.f16x2.f32 %0, %1, %2;" : "=r"(r) : "f"(hi), "f"(lo));
    return r;
}

__device__ __forceinline__ uint32_t smem_u32(const void* p) {
    uint32_t a;
    asm("{ .reg .u64 t; cvta.to.shared.u64 t, %1; cvt.u32.u64 %0, t; }" : "=r"(a) : "l"(p));
    return a;
}

__device__ __forceinline__ void mma16(float* c, uint32_t a0, uint32_t a1, uint32_t a2,
                                      uint32_t a3, uint32_t b0, uint32_t b1) {
    asm volatile(
        "mma.sync.aligned.m16n8k16.row.col.f32.f16.f16.f32 "
        "{%0,%1,%2,%3}, {%4,%5,%6,%7}, {%8,%9}, {%0,%1,%2,%3};"
        : "+f"(c[0]), "+f"(c[1]), "+f"(c[2]), "+f"(c[3])
        : "r"(a0), "r"(a1), "r"(a2), "r"(a3), "r"(b0), "r"(b1));
}

__device__ __forceinline__ void ldsm4(uint32_t* r, uint32_t addr) {
    asm volatile("ldmatrix.sync.aligned.m8n8.x4.shared.b16 {%0,%1,%2,%3}, [%4];"
                 : "=r"(r[0]), "=r"(r[1]), "=r"(r[2]), "=r"(r[3]) : "r"(addr));
}

// ---------------- pipelined fp16 mma GEMM (ldmatrix mainloop) ----------------
// C[M,N] = epi(A[M,K(lda)] * B[N,K(ldb)]^T + bias), fp32 accumulate.
// epi: 0 = store (+bias), 1 = relu(+bias), 2 = C += scale*leaky_{0.01}(v+bias)
// N multiple of 128, K multiple of 32. grid (N/128, ceil(M/128)), block 256,
// dynamic smem = 4*TBUF*4 bytes (double-buffered A+B half tiles, row stride 20 words).
#define SRW 20
#define TBUF (128 * SRW)
__global__ __launch_bounds__(256) void gemm_mma(
    const float* __restrict__ A, const float* __restrict__ B,
    const float* __restrict__ bias, float* __restrict__ C,
    int M, int N, int K, int lda, int ldb, int epi, float scale)
{
    extern __shared__ uint32_t sm[];
    const int tid = threadIdx.x;
    const int wid = tid >> 5, lane = tid & 31;
    const int wm = wid & 1, wn = wid >> 1;       // warp tile: 64 rows x 32 cols
    const int row0 = blockIdx.y * 128, col0 = blockIdx.x * 128;
    const int lq = lane >> 2, lr = lane & 3;
    // ldmatrix per-thread source rows/cols
    const int rr = lane & 7;
    const int aRow = wm * 64 + rr + ((lane >> 3) & 1) * 8;
    const int aColW = ((lane >> 4) & 1) * 4;
    const int bRow = wn * 32 + rr + ((lane >> 4) & 1) * 8;
    const int bColW = ((lane >> 3) & 1) * 4;

    float acc[4][4][4];
#pragma unroll
    for (int i = 0; i < 4; i++)
#pragma unroll
        for (int j = 0; j < 4; j++) {
            acc[i][j][0] = 0.f; acc[i][j][1] = 0.f;
            acc[i][j][2] = 0.f; acc[i][j][3] = 0.f;
        }

    const int s_row = tid >> 3;                  // staging: 8 threads per row
    const int s_c4 = (tid & 7) * 4;              // half offset within row
    const int s_w2 = (tid & 7) * 2;              // word offset
    const int nC = K >> 5;

    float4 pa[4], pb[4];

#define LDG_CHUNK(cc)                                                                \
    {                                                                                \
        int k0 = (cc) << 5;                                                          \
        _Pragma("unroll")                                                            \
        for (int it = 0; it < 4; it++) {                                             \
            int row = it * 32 + s_row;                                               \
            int gr = row0 + row;                                                     \
            pa[it] = make_float4(0.f, 0.f, 0.f, 0.f);                                \
            if (gr < M) pa[it] = *(const float4*)(A + (size_t)gr * lda + k0 + s_c4); \
            pb[it] = *(const float4*)(B + (size_t)(col0 + row) * ldb + k0 + s_c4);   \
        }                                                                            \
    }
#define STS_CHUNK(Ad, Bd)                                                            \
    {                                                                                \
        _Pragma("unroll")                                                            \
        for (int it = 0; it < 4; it++) {                                             \
            int row = it * 32 + s_row;                                               \
            uint2 ua, ub;                                                            \
            ua.x = f2h2(pa[it].x, pa[it].y); ua.y = f2h2(pa[it].z, pa[it].w);        \
            ub.x = f2h2(pb[it].x, pb[it].y); ub.y = f2h2(pb[it].z, pb[it].w);        \
            *(uint2*)&(Ad)[row * SRW + s_w2] = ua;                                   \
            *(uint2*)&(Bd)[row * SRW + s_w2] = ub;                                   \
        }                                                                            \
    }
#define COMPUTE_KS(AsAddr, BsAddr, KS)                                               \
    {                                                                                \
        uint32_t bq[2][4];                                                           \
        _Pragma("unroll")                                                            \
        for (int ntp = 0; ntp < 2; ntp++)                                            \
            ldsm4(bq[ntp], (BsAddr) + (((bRow + ntp * 16) * SRW) + (KS) * 8 + bColW) * 4); \
        _Pragma("unroll")                                                            \
        for (int mt = 0; mt < 4; mt++) {                                             \
            uint32_t aq[4];                                                          \
            ldsm4(aq, (AsAddr) + (((aRow + mt * 16) * SRW) + (KS) * 8 + aColW) * 4); \
            _Pragma("unroll")                                                        \
            for (int nt = 0; nt < 4; nt++)                                           \
                mma16(acc[mt][nt], aq[0], aq[1], aq[2], aq[3],                       \
                      bq[nt >> 1][(nt & 1) * 2 + 0], bq[nt >> 1][(nt & 1) * 2 + 1]); \
        }                                                                            \
    }

    uint32_t* A0 = sm;
    uint32_t* B0 = sm + TBUF;
    uint32_t* A1 = sm + 2 * TBUF;
    uint32_t* B1 = sm + 3 * TBUF;
    const uint32_t sb = smem_u32(sm);
    const uint32_t aAddr0 = sb, bAddr0 = sb + TBUF * 4;
    const uint32_t aAddr1 = sb + 2 * TBUF * 4, bAddr1 = sb + 3 * TBUF * 4;

    LDG_CHUNK(0);
    STS_CHUNK(A0, B0);
    if (nC > 1) LDG_CHUNK(1);
    __syncthreads();

    for (int c = 0; c < nC; c++) {
        uint32_t aA = (c & 1) ? aAddr1 : aAddr0;
        uint32_t bA = (c & 1) ? bAddr1 : bAddr0;
        uint32_t* Asn = (c & 1) ? A0 : A1;
        uint32_t* Bsn = (c & 1) ? B0 : B1;
        COMPUTE_KS(aA, bA, 0);
        if (c + 1 < nC) STS_CHUNK(Asn, Bsn);
        COMPUTE_KS(aA, bA, 1);
        if (c + 2 < nC) LDG_CHUNK(c + 2);
        __syncthreads();
    }

    // ---- epilogue ----
    const int rbase = row0 + wm * 64;
    const int cbase = col0 + wn * 32;
#pragma unroll
    for (int mt = 0; mt < 4; mt++) {
        int r0 = rbase + mt * 16 + lq;
#pragma unroll
        for (int half = 0; half < 2; half++) {
            int r = r0 + half * 8;
            if (r < M) {
#pragma unroll
                for (int nt = 0; nt < 4; nt++) {
                    int c = cbase + nt * 8 + lr * 2;
                    float v0 = acc[mt][nt][half * 2 + 0];
                    float v1 = acc[mt][nt][half * 2 + 1];
                    if (bias) { v0 += bias[c]; v1 += bias[c + 1]; }
                    float* cp = C + (size_t)r * N + c;
                    if (epi == 0) {
                        *(float2*)cp = make_float2(v0, v1);
                    } else if (epi == 1) {
                        *(float2*)cp = make_float2(fmaxf(v0, 0.f), fmaxf(v1, 0.f));
                    } else {
                        float2 o = *(float2*)cp;
                        o.x += scale * leakyf(v0, 0.01f);
                        o.y += scale * leakyf(v1, 0.01f);
                        *(float2*)cp = o;
                    }
                }
            }
        }
    }
}

// ---------------- fp16 tensor-core flash attention ----------------
#define VSW 68   // VT row stride in words (136 halves)
__global__ __launch_bounds__(256) void attn_tc() {
    __shared__ uint32_t QK[128 * SRW];
    __shared__ uint32_t VT[32 * VSW];
    const int b = blockIdx.z, h = blockIdx.y, qt = blockIdx.x;
    const int cnt = g_cnt[b];
    const int tid = threadIdx.x, wid = tid >> 5, lane = tid & 31;
    const int lq = lane >> 2, lr = lane & 3;
    const float qscale = 0.17677669529663687f;   // 1/sqrt(32)

#pragma unroll
    for (int it = 0; it < 4; it++) {
        int idx = it * 256 + tid;
        int row = idx >> 3, c4 = (idx & 7) * 4;
        int q = qt * 128 + row;
        float4 v = make_float4(0.f, 0.f, 0.f, 0.f);
        if (q < LMAX) v = *(const float4*)(g_qkv + (size_t)(b * LMAX + q) * 384 + h * 32 + c4);
        uint2 u;
        u.x = f2h2(v.x * qscale, v.y * qscale);
        u.y = f2h2(v.z * qscale, v.w * qscale);
        *(uint2*)&QK[row * SRW + (idx & 7) * 2] = u;
    }
    __syncthreads();
    uint32_t qa[2][4];
    {
        int r = wid * 16 + lq;
#pragma unroll
        for (int ks = 0; ks < 2; ks++) {
            int kb = ks * 8 + lr;
            qa[ks][0] = QK[r * SRW + kb];
            qa[ks][1] = QK[(r + 8) * SRW + kb];
            qa[ks][2] = QK[r * SRW + kb + 4];
            qa[ks][3] = QK[(r + 8) * SRW + kb + 4];
        }
    }

    float m0 = -INFINITY, m1 = -INFINITY, den0 = 0.f, den1 = 0.f;
    float of[4][4];
#pragma unroll
    for (int nt = 0; nt < 4; nt++) {
        of[nt][0] = 0.f; of[nt][1] = 0.f; of[nt][2] = 0.f; of[nt][3] = 0.f;
    }

    for (int kb0 = 0; kb0 < LMAX; kb0 += 128) {
        __syncthreads();
#pragma unroll
        for (int it = 0; it < 4; it++) {
            int idx = it * 256 + tid;
            int row = idx >> 3, c4 = (idx & 7) * 4;
            int key = kb0 + row;
            float4 kv = make_float4(0.f, 0.f, 0.f, 0.f);
            if (key < LMAX)
                kv = *(const float4*)(g_qkv + (size_t)(b * LMAX + key) * 384 + 128 + h * 32 + c4);
            uint2 u;
            u.x = f2h2(kv.x, kv.y); u.y = f2h2(kv.z, kv.w);
            *(uint2*)&QK[row * SRW + (idx & 7) * 2] = u;
        }
#pragma unroll
        for (int it = 0; it < 2; it++) {
            int item = it * 256 + tid;
            int kp = item & 63, g = item >> 6;
            int k0 = kb0 + 2 * kp;
            float4 v0 = make_float4(0.f, 0.f, 0.f, 0.f);
            float4 v1 = make_float4(0.f, 0.f, 0.f, 0.f);
            if (k0 < LMAX)
                v0 = *(const float4*)(g_qkv + (size_t)(b * LMAX + k0) * 384 + 256 + h * 32 + g * 4);
            if (k0 + 1 < LMAX)
                v1 = *(const float4*)(g_qkv + (size_t)(b * LMAX + k0 + 1) * 384 + 256 + h * 32 + g * 4);
            VT[(g * 4 + 0) * VSW + kp] = f2h2(v0.x, v1.x);
            VT[(g * 4 + 1) * VSW + kp] = f2h2(v0.y, v1.y);
            VT[(g * 4 + 2) * VSW + kp] = f2h2(v0.z, v1.z);
            VT[(g * 4 + 3) * VSW + kp] = f2h2(v0.w, v1.w);
        }
        __syncthreads();

        float sf[16][4];
#pragma unroll
        for (int nt = 0; nt < 16; nt++) {
            sf[nt][0] = 0.f; sf[nt][1] = 0.f; sf[nt][2] = 0.f; sf[nt][3] = 0.f;
        }
#pragma unroll
        for (int ks = 0; ks < 2; ks++) {
            int kk = ks * 8 + lr;
#pragma unroll
            for (int nt = 0; nt < 16; nt++) {
                uint32_t b0 = QK[(nt * 8 + lq) * SRW + kk];
                uint32_t b1 = QK[(nt * 8 + lq) * SRW + kk + 4];
                mma16(sf[nt], qa[ks][0], qa[ks][1], qa[ks][2], qa[ks][3], b0, b1);
            }
        }
        float bm0 = -INFINITY, bm1 = -INFINITY;
#pragma unroll
        for (int nt = 0; nt < 16; nt++) {
            int c = kb0 + nt * 8 + lr * 2;
            if (c >= cnt) { sf[nt][0] = -1e30f; sf[nt][2] = -1e30f; }
            if (c + 1 >= cnt) { sf[nt][1] = -1e30f; sf[nt][3] = -1e30f; }
            bm0 = fmaxf(bm0, fmaxf(sf[nt][0], sf[nt][1]));
            bm1 = fmaxf(bm1, fmaxf(sf[nt][2], sf[nt][3]));
        }
        bm0 = fmaxf(bm0, __shfl_xor_sync(0xffffffffu, bm0, 1));
        bm0 = fmaxf(bm0, __shfl_xor_sync(0xffffffffu, bm0, 2));
        bm1 = fmaxf(bm1, __shfl_xor_sync(0xffffffffu, bm1, 1));
        bm1 = fmaxf(bm1, __shfl_xor_sync(0xffffffffu, bm1, 2));
        float nm0 = fmaxf(m0, bm0), nm1 = fmaxf(m1, bm1);
        float cor0 = __expf(m0 - nm0), cor1 = __expf(m1 - nm1);
        m0 = nm0; m1 = nm1;
        float s0 = 0.f, s1 = 0.f;
        uint32_t pf01[16], pf23[16];
#pragma unroll
        for (int nt = 0; nt < 16; nt++) {
            float p0 = __expf(sf[nt][0] - nm0), p1 = __expf(sf[nt][1] - nm0);
            float p2 = __expf(sf[nt][2] - nm1), p3 = __expf(sf[nt][3] - nm1);
            s0 += p0 + p1; s1 += p2 + p3;
            pf01[nt] = f2h2(p0, p1);
            pf23[nt] = f2h2(p2, p3);
        }
        s0 += __shfl_xor_sync(0xffffffffu, s0, 1);
        s0 += __shfl_xor_sync(0xffffffffu, s0, 2);
        s1 += __shfl_xor_sync(0xffffffffu, s1, 1);
        s1 += __shfl_xor_sync(0xffffffffu, s1, 2);
        den0 = den0 * cor0 + s0;
        den1 = den1 * cor1 + s1;
#pragma unroll
        for (int nt = 0; nt < 4; nt++) {
            of[nt][0] *= cor0; of[nt][1] *= cor0;
            of[nt][2] *= cor1; of[nt][3] *= cor1;
        }
#pragma unroll
        for (int ks = 0; ks < 8; ks++) {
            uint32_t a0 = pf01[2 * ks], a1 = pf23[2 * ks];
            uint32_t a2 = pf01[2 * ks + 1], a3 = pf23[2 * ks + 1];
#pragma unroll
            for (int nt = 0; nt < 4; nt++) {
                uint32_t b0 = VT[(nt * 8 + lq) * VSW + 8 * ks + lr];
                uint32_t b1 = VT[(nt * 8 + lq) * VSW + 8 * ks + lr + 4];
                mma16(of[nt], a0, a1, a2, a3, b0, b1);
            }
        }
    }

    float i0 = 1.f / den0, i1 = 1.f / den1;
    int q_lo = qt * 128 + wid * 16 + lq, q_hi = q_lo + 8;
#pragma unroll
    for (int nt = 0; nt < 4; nt++) {
        int col = h * 32 + nt * 8 + lr * 2;
        if (q_lo < LMAX)
            *(float2*)(g_attn + (size_t)(b * LMAX + q_lo) * DD + col) =
                make_float2(of[nt][0] * i0, of[nt][1] * i0);
        if (q_hi < LMAX)
            *(float2*)(g_attn + (size_t)(b * LMAX + q_hi) * DD + col) =
                make_float2(of[nt][2] * i1, of[nt][3] * i1);
    }
}

// ---------------- GAT kernels (CSR-bucketed, batched over hops) ----------------
__global__ void zero_acc_kernel() {
    size_t i = (size_t)blockIdx.x * blockDim.x + threadIdx.x;
    if (i < (size_t)NN * DD / 4) ((float4*)g_acc)[i] = make_float4(0.f, 0.f, 0.f, 0.f);
}
__global__ void zero_y_kernel() {
    size_t i = (size_t)blockIdx.x * blockDim.x + threadIdx.x;
    if (i < (size_t)NM * DD / 4) ((float4*)g_y)[i] = make_float4(0.f, 0.f, 0.f, 0.f);
}

// warp per node, blockIdx.y = hop: al_src/al_dst reductions; zero deg
__global__ void gat_prep3(const float* __restrict__ a_src,
                          const float* __restrict__ a_dst)
{
    int gid = blockIdx.x * blockDim.x + threadIdx.x;
    int node = gid >> 5, lane = gid & 31;
    int hop = blockIdx.y;
    if (node >= NN) return;
    float s[4], d[4];
#pragma unroll
    for (int j = 0; j < 4; j++) {
        int c = j * 32 + lane;
        float hv = g_h3[(size_t)node * 384 + hop * 128 + c];
        s[j] = hv * a_src[hop * DD + c];
        d[j] = hv * a_dst[hop * DD + c];
    }
#pragma unroll
    for (int j = 0; j < 4; j++)
#pragma unroll
        for (int o = 16; o > 0; o >>= 1) {
            s[j] += __shfl_xor_sync(0xffffffffu, s[j], o);
            d[j] += __shfl_xor_sync(0xffffffffu, d[j], o);
        }
    if (lane == 0) {
        int idx = (node * 3 + hop) * 4;
        *(float4*)&g_als3[idx] = make_float4(s[0], s[1], s[2], s[3]);
        *(float4*)&g_ald3[idx] = make_float4(d[0], d[1], d[2], d[3]);
        g_deg[hop * NN + node] = 0;
    }
}

// degree count. blockIdx.y = hop.
__global__ void deg3(const int* __restrict__ e0, const int* __restrict__ e1,
                     const int* __restrict__ e2)
{
    int hop = blockIdx.y;
    const int* ei = (hop == 0) ? e0 : (hop == 1) ? e1 : e2;
    int t = blockIdx.x * blockDim.x + threadIdx.x;
    if (t >= NITEMS) return;
    int dst = (t < NE) ? ei[NE + t] : t - NE;
    atomicAdd(&g_deg[hop * NN + dst], 1);
}

// exclusive scan per hop (one 1024-thread block per hop)
__global__ __launch_bounds__(1024) void scan3() {
    __shared__ int part[1024];
    const int hop = blockIdx.x;
    const int t = threadIdx.x;
    const int CH = (NN + 1023) / 1024;   // 49
    int beg = t * CH, end = beg + CH;
    if (end > NN) end = NN;
    int s = 0;
    for (int i = beg; i < end; i++) s += g_deg[hop * NN + i];
    part[t] = s;
    __syncthreads();
    for (int o = 1; o < 1024; o <<= 1) {
        int u = (t >= o) ? part[t - o] : 0;
        __syncthreads();
        part[t] += u;
        __syncthreads();
    }
    int run = part[t] - s;
    for (int i = beg; i < end; i++) {
        int d = g_deg[hop * NN + i];
        g_off[hop * (NN + 1) + i] = run;
        g_cur[hop * NN + i] = run;
        run += d;
    }
    if (t == 0) g_off[hop * (NN + 1) + NN] = NITEMS;
}

// scatter: compute ew = exp(leaky(als+ald)), place at CSR slot. blockIdx.y = hop.
__global__ void edge_scat3(const int* __restrict__ e0, const int* __restrict__ e1,
                           const int* __restrict__ e2)
{
    int hop = blockIdx.y;
    const int* ei = (hop == 0) ? e0 : (hop == 1) ? e1 : e2;
    int t = blockIdx.x * blockDim.x + threadIdx.x;
    if (t >= NITEMS) return;
    int src, dst;
    if (t < NE) { src = ei[t]; dst = ei[NE + t]; }
    else { src = dst = t - NE; }
    float4 a = *(const float4*)&g_als3[(src * 3 + hop) * 4];
    float4 b = *(const float4*)&g_ald3[(dst * 3 + hop) * 4];
    float4 ew;
    ew.x = expf(leakyf(a.x + b.x, 0.2f));
    ew.y = expf(leakyf(a.y + b.y, 0.2f));
    ew.z = expf(leakyf(a.z + b.z, 0.2f));
    ew.w = expf(leakyf(a.w + b.w, 0.2f));
    int pos = atomicAdd(&g_cur[hop * NN + dst], 1);
    g_srcS[(size_t)hop * NITEMS + pos] = src;
    *(float4*)&g_ew[((size_t)hop * NITEMS + pos) * 4] = ew;
}

// aggregation: warp per (dst, hop): den from bucket, then gout = bias + sum alpha*h
__global__ void aggr3(const float* __restrict__ bias) {
    int gid = blockIdx.x * blockDim.x + threadIdx.x;
    int dst = gid >> 5, lane = gid & 31;
    int hop = blockIdx.y;
    if (dst >= NN) return;
    int e0 = g_off[hop * (NN + 1) + dst];
    int e1 = g_off[hop * (NN + 1) + dst + 1];
    float4 den = make_float4(0.f, 0.f, 0.f, 0.f);
    for (int e = e0 + lane; e < e1; e += 32) {
        float4 w4 = *(const float4*)&g_ew[((size_t)hop * NITEMS + e) * 4];
        den.x += w4.x; den.y += w4.y; den.z += w4.z; den.w += w4.w;
    }
#pragma unroll
    for (int o = 16; o > 0; o >>= 1) {
        den.x += __shfl_xor_sync(0xffffffffu, den.x, o);
        den.y += __shfl_xor_sync(0xffffffffu, den.y, o);
        den.z += __shfl_xor_sync(0xffffffffu, den.z, o);
        den.w += __shfl_xor_sync(0xffffffffu, den.w, o);
    }
    float4 inv = make_float4(1.f / den.x, 1.f / den.y, 1.f / den.z, 1.f / den.w);
    float a0 = 0.f, a1 = 0.f, a2 = 0.f, a3 = 0.f;
    for (int e = e0; e < e1; e++) {
        float4 w4 = *(const float4*)&g_ew[((size_t)hop * NITEMS + e) * 4];
        int src = g_srcS[(size_t)hop * NITEMS + e];
        const float* hs = g_h3 + (size_t)src * 384 + hop * 128;
        a0 += w4.x * inv.x * hs[lane];
        a1 += w4.y * inv.y * hs[32 + lane];
        a2 += w4.z * inv.z * hs[64 + lane];
        a3 += w4.w * inv.w * hs[96 + lane];
    }
    float* gd = g_gout3 + (size_t)dst * 384 + hop * 128;
    const float* bb = bias + hop * 128;
    gd[lane]      = a0 + bb[lane];
    gd[32 + lane] = a1 + bb[32 + lane];
    gd[64 + lane] = a2 + bb[64 + lane];
    gd[96 + lane] = a3 + bb[96 + lane];
}

// ---------------- position / count kernels ----------------
__global__ void hist_kernel(const int* __restrict__ genre) {
    __shared__ int loc[NG];
    if (threadIdx.x < NG) loc[threadIdx.x] = 0;
    __syncthreads();
    int i = blockIdx.x * 128 + threadIdx.x;
    if (i < NM) atomicAdd(&loc[genre[i]], 1);
    __syncthreads();
    if (threadIdx.x < NG) g_chist[blockIdx.x * NG + threadIdx.x] = loc[threadIdx.x];
}
__global__ void scan_kernel() {
    int g = threadIdx.x;
    if (g >= NG) return;
    int run = 0;
    for (int c = 0; c < NCHUNK; c++) {
        int t = g_chist[c * NG + g];
        g_chist[c * NG + g] = run;
        run += t;
    }
    g_cnt[g] = run;
}
__global__ void pos_kernel(const int* __restrict__ genre) {
    int c = blockIdx.x * blockDim.x + threadIdx.x;
    if (c >= NCHUNK) return;
    int off[NG];
    for (int g = 0; g < NG; g++) off[g] = g_chist[c * NG + g];
    int base = c * 128;
    int end = base + 128; if (end > NM) end = NM;
    for (int i = base; i < end; i++) {
        int g = genre[i];
        g_pos[i] = off[g]++;
    }
}

__global__ void gather_kernel(const int* __restrict__ movie_idx, const int* __restrict__ genre) {
    int t = blockIdx.x * blockDim.x + threadIdx.x;
    if (t >= NM * 32) return;
    int i = t >> 5, c4 = (t & 31) * 4;
    float4 v = *(const float4*)&g_acc[(size_t)movie_idx[i] * DD + c4];
    *(float4*)&g_xm[(size_t)i * DD + c4] = v;
    int row = genre[i] * LMAX + g_pos[i];
    *(float4*)&g_y[(size_t)row * DD + c4] = v;
}

// ---------------- LayerNorm (fused residual): y = LN(y + t) ----------------
__global__ void ln_kernel(float* __restrict__ y, const float* __restrict__ t,
                          const float* __restrict__ gam, const float* __restrict__ bet,
                          int rows)
{
    int gid = blockIdx.x * blockDim.x + threadIdx.x;
    int row = gid >> 5, lane = gid & 31;
    if (row >= rows) return;
    size_t off = (size_t)row * DD + lane * 4;
    float4 v = *(float4*)(y + off);
    float4 tv = *(const float4*)(t + off);
    v.x += tv.x; v.y += tv.y; v.z += tv.z; v.w += tv.w;
    float s = v.x + v.y + v.z + v.w;
#pragma unroll
    for (int o = 16; o > 0; o >>= 1) s += __shfl_xor_sync(0xffffffffu, s, o);
    float mean = s * (1.f / DD);
    float dx = v.x - mean, dy = v.y - mean, dz = v.z - mean, dw = v.w - mean;
    float ss = dx * dx + dy * dy + dz * dz + dw * dw;
#pragma unroll
    for (int o = 16; o > 0; o >>= 1) ss += __shfl_xor_sync(0xffffffffu, ss, o);
    float inv = rsqrtf(ss * (1.f / DD) + 1e-5f);
    float4 gg = *(const float4*)(gam + lane * 4);
    float4 bb = *(const float4*)(bet + lane * 4);
    v.x = dx * inv * gg.x + bb.x;
    v.y = dy * inv * gg.y + bb.y;
    v.z = dz * inv * gg.z + bb.z;
    v.w = dw * inv * gg.w + bb.w;
    *(float4*)(y + off) = v;
}

// ---------------- pooling / fusion ----------------
__global__ void pool_kernel() {
    int g = blockIdx.x, d = threadIdx.x;
    int cnt = g_cnt[g];
    float s = 0.f;
    for (int t = 0; t < cnt; t++) s += g_y[(size_t)(g * LMAX + t) * DD + d];
    g_pooled[g * DD + d] = s / fmaxf((float)cnt, 1.f);
}

__global__ void pe_kernel(const float* __restrict__ fus_w) {
    int g = blockIdx.x, n = threadIdx.x;
    float s = 0.f;
    for (int k = 0; k < DD; k++)
        s += g_pooled[g * DD + k] * fus_w[n * 256 + 128 + k];
    g_pe[g * DD + n] = s;
}

__global__ void copy_out_kernel(float* __restrict__ out) {
    size_t i = (size_t)blockIdx.x * blockDim.x + threadIdx.x;
    if (i < (size_t)NN * DD / 4) ((float4*)out)[i] = ((const float4*)g_acc)[i];
}

__global__ void fuse_out_kernel(const int* __restrict__ movie_idx, const int* __restrict__ genre,
                                const float* __restrict__ fus_b, float* __restrict__ out)
{
    int t = blockIdx.x * blockDim.x + threadIdx.x;
    if (t >= NM * 32) return;
    int i = t >> 5, c4 = (t & 31) * 4;
    float4 v = *(const float4*)&g_tmp[(size_t)i * DD + c4];
    float4 p = *(const float4*)&g_pe[genre[i] * DD + c4];
    float4 bb = *(const float4*)(fus_b + c4);
    v.x = leakyf(v.x + p.x + bb.x, 0.01f);
    v.y = leakyf(v.y + p.y + bb.y, 0.01f);
    v.z = leakyf(v.z + p.z + bb.z, 0.01f);
    v.w = leakyf(v.w + p.w + bb.w, 0.01f);
    *(float4*)&out[(size_t)movie_idx[i] * DD + c4] = v;
}

// ---------------- launch ----------------
extern "C" void kernel_launch(void* const* d_in, const int* in_sizes, int n_in,
                              void* d_out, int out_size)
{
    const float* x        = (const float*)d_in[0];
    const int*   e0       = (const int*)d_in[1];
    const int*   e1       = (const int*)d_in[2];
    const int*   e2       = (const int*)d_in[3];
    const int*   movie_idx = (const int*)d_in[4];
    const int*   genre     = (const int*)d_in[5];
    const float* gat_W    = (const float*)d_in[6];
    const float* att_src  = (const float*)d_in[7];
    const float* att_dst  = (const float*)d_in[8];
    const float* gat_bias = (const float*)d_in[9];
    const float* dec_W    = (const float*)d_in[10];
    const float* dec_b    = (const float*)d_in[11];
    const float* qkv_w    = (const float*)d_in[12];
    const float* qkv_b    = (const float*)d_in[13];
    const float* out_w    = (const float*)d_in[14];
    const float* out_b    = (const float*)d_in[15];
    const float* ln1_g    = (const float*)d_in[16];
    const float* ln1_b    = (const float*)d_in[17];
    const float* ln2_g    = (const float*)d_in[18];
    const float* ln2_b    = (const float*)d_in[19];
    const float* ffn_w1   = (const float*)d_in[20];
    const float* ffn_b1   = (const float*)d_in[21];
    const float* ffn_w2   = (const float*)d_in[22];
    const float* ffn_b2   = (const float*)d_in[23];
    const float* fus_w    = (const float*)d_in[24];
    const float* fus_b    = (const float*)d_in[25];
    float* out = (float*)d_out;

    float *p_h3, *p_gout3, *p_acc, *p_y, *p_qkv, *p_attn, *p_tmp, *p_ffn, *p_xm;
    cudaGetSymbolAddress((void**)&p_h3,    g_h3);
    cudaGetSymbolAddress((void**)&p_gout3, g_gout3);
    cudaGetSymbolAddress((void**)&p_acc,   g_acc);
    cudaGetSymbolAddress((void**)&p_y,     g_y);
    cudaGetSymbolAddress((void**)&p_qkv,   g_qkv);
    cudaGetSymbolAddress((void**)&p_attn,  g_attn);
    cudaGetSymbolAddress((void**)&p_tmp,   g_tmp);
    cudaGetSymbolAddress((void**)&p_ffn,   g_ffn);
    cudaGetSymbolAddress((void**)&p_xm,    g_xm);

    const int GSMEM = 4 * TBUF * 4;   // 40960 B double-buffered half tiles
    cudaFuncSetAttribute(gemm_mma, cudaFuncAttributeMaxDynamicSharedMemorySize, GSMEM);

    const int MTN = (NN + 127) / 128;  // 391
    const int MT  = (NM + 127) / 128;  // 160

    // -------- GAT: h3 = x @ [W0;W1;W2]^T, CSR edge softmax, decoders --------
    zero_acc_kernel<<<(NN * DD / 4 + 255) / 256, 256>>>();
    gemm_mma<<<dim3(3, MTN), 256, GSMEM>>>(x, gat_W, nullptr, p_h3,
                                           NN, 384, DD, DD, DD, 0, 0.f);
    gat_prep3<<<dim3((NN * 32 + 255) / 256, 3), 256>>>(att_src, att_dst);
    deg3<<<dim3((NITEMS + 255) / 256, 3), 256>>>(e0, e1, e2);
    scan3<<<3, 1024>>>();
    edge_scat3<<<dim3((NITEMS + 255) / 256, 3), 256>>>(e0, e1, e2);
    aggr3<<<dim3((NN * 32 + 255) / 256, 3), 256>>>(gat_bias);
    for (int k = 0; k < 3; k++) {
        float scale = (float)exp(-0.1 * k);
        gemm_mma<<<dim3(1, MTN), 256, GSMEM>>>(
            p_gout3 + k * 128, dec_W + (size_t)k * DD * DD, dec_b + k * DD,
            p_acc, NN, DD, DD, 384, DD, 2, scale);
    }

    // -------- build genre sequences --------
    hist_kernel<<<NCHUNK, 128>>>(genre);
    scan_kernel<<<1, 32>>>();
    pos_kernel<<<1, 256>>>(genre);
    zero_y_kernel<<<(NM * DD / 4 + 255) / 256, 256>>>();
    gather_kernel<<<(NM * 32 + 255) / 256, 256>>>(movie_idx, genre);

    // -------- transformer (4 layers) --------
    for (int l = 0; l < NL; l++) {
        gemm_mma<<<dim3(3 * DD / 128, MT), 256, GSMEM>>>(
            p_y, qkv_w + (size_t)l * 3 * DD * DD, qkv_b + l * 3 * DD, p_qkv,
            NM, 3 * DD, DD, DD, DD, 0, 0.f);
        attn_tc<<<dim3((LMAX + 127) / 128, NHEADS, NG), 256>>>();
        gemm_mma<<<dim3(1, MT), 256, GSMEM>>>(
            p_attn, out_w + (size_t)l * DD * DD, out_b + l * DD, p_tmp,
            NM, DD, DD, DD, DD, 0, 0.f);
        ln_kernel<<<(NM * 32 + 255) / 256, 256>>>(p_y, p_tmp, ln1_g + l * DD, ln1_b + l * DD, NM);
        gemm_mma<<<dim3(FFD / 128, MT), 256, GSMEM>>>(
            p_y, ffn_w1 + (size_t)l * FFD * DD, ffn_b1 + l * FFD, p_ffn,
            NM, FFD, DD, DD, DD, 1, 0.f);
        gemm_mma<<<dim3(1, MT), 256, GSMEM>>>(
            p_ffn, ffn_w2 + (size_t)l * DD * FFD, ffn_b2 + l * DD, p_tmp,
            NM, DD, FFD, FFD, FFD, 0, 0.f);
        ln_kernel<<<(NM * 32 + 255) / 256, 256>>>(p_y, p_tmp, ln2_g + l * DD, ln2_b + l * DD, NM);
    }

    // -------- pool + fuse + write output --------
    pool_kernel<<<NG, DD>>>();
    pe_kernel<<<NG, DD>>>(fus_w);
    gemm_mma<<<dim3(1, MT), 256, GSMEM>>>(p_xm, fus_w, nullptr, p_tmp,
                                          NM, DD, DD, DD, 256, 0, 0.f);
    copy_out_kernel<<<(NN * DD / 4 + 255) / 256, 256>>>(out);
    fuse_out_kernel<<<(NM * 32 + 255) / 256, 256>>>(movie_idx, genre, fus_b, out);
}

// round 9
// speedup vs baseline: 3.8044x; 1.0671x over previous
#include <cuda_runtime.h>
#include <cuda_fp16.h>
#include <math.h>
#include <stdint.h>

#define NN 50000
#define NE 400000
#define DD 128
#define NM 20400
#define NG 30
#define LMAX 680
#define NHEADS 4
#define NL 4
#define FFD 2048
#define NCHUNK 160   // ceil(20400/128)
#define NITEMS (NE + NN)

// ---------------- scratch (device globals; no runtime allocation) ----------------
__device__ __align__(16) float  g_h3[(size_t)NN * 384];
__device__ __align__(16) float  g_acc[(size_t)NN * DD];
__device__ __align__(16) float  g_als3[NN * 3 * NHEADS];
__device__ __align__(16) float  g_ald3[NN * 3 * NHEADS];
__device__ __align__(16) float  g_ew[(size_t)3 * NITEMS * NHEADS];
__device__ int g_srcS[(size_t)3 * NITEMS];
__device__ int g_deg[3 * NN];
__device__ int g_off[3 * (NN + 1)];
__device__ int g_cur[3 * NN];
__device__ __align__(16) float  g_y[(size_t)NM * DD];
__device__ __align__(16) float  g_tmp[(size_t)NM * DD];
__device__ __align__(16) float  g_pooled[NG * DD];
__device__ __align__(16) float  g_pe[NG * DD];
__device__ int g_pos[NM];
__device__ int g_cnt[NG];
__device__ int g_chist[NCHUNK * NG];
// fp16 shadows / intermediates
__device__ __align__(16) __half g_x16[(size_t)NN * DD];
__device__ __align__(16) __half g_gout316[(size_t)NN * 384];
__device__ __align__(16) __half g_y16[(size_t)NM * DD];
__device__ __align__(16) __half g_qkv16[(size_t)NM * 3 * DD];
__device__ __align__(16) __half g_attn16[(size_t)NM * DD];
__device__ __align__(16) __half g_ffn16[(size_t)NM * FFD];
__device__ __align__(16) __half g_xm16[(size_t)NM * DD];
// fp16 weights
__device__ __align__(16) __half g_gatW16[3 * DD * DD];
__device__ __align__(16) __half g_decW16[3 * DD * DD];
__device__ __align__(16) __half g_qkvW16[NL * 3 * DD * DD];
__device__ __align__(16) __half g_outW16[NL * DD * DD];
__device__ __align__(16) __half g_fw116[(size_t)NL * FFD * DD];
__device__ __align__(16) __half g_fw216[(size_t)NL * DD * FFD];
__device__ __align__(16) __half g_fusW16[DD * 256];

// ---------------- small helpers ----------------
__device__ __forceinline__ float leakyf(float x, float s) { return x >= 0.f ? x : s * x; }

__device__ __forceinline__ uint32_t f2h2(float lo, float hi) {
    uint32_t r;
    asm("cvt.rn.f16x2.f32 %0, %1, %2;" : "=r"(r) : "f"(hi), "f"(lo));
    return r;
}

__device__ __forceinline__ uint32_t smem_u32(const void* p) {
    uint32_t a;
    asm("{ .reg .u64 t; cvta.to.shared.u64 t, %1; cvt.u32.u64 %0, t; }" : "=r"(a) : "l"(p));
    return a;
}

__device__ __forceinline__ void mma16(float* c, uint32_t a0, uint32_t a1, uint32_t a2,
                                      uint32_t a3, uint32_t b0, uint32_t b1) {
    asm volatile(
        "mma.sync.aligned.m16n8k16.row.col.f32.f16.f16.f32 "
        "{%0,%1,%2,%3}, {%4,%5,%6,%7}, {%8,%9}, {%0,%1,%2,%3};"
        : "+f"(c[0]), "+f"(c[1]), "+f"(c[2]), "+f"(c[3])
        : "r"(a0), "r"(a1), "r"(a2), "r"(a3), "r"(b0), "r"(b1));
}

__device__ __forceinline__ void ldsm4(uint32_t* r, uint32_t addr) {
    asm volatile("ldmatrix.sync.aligned.m8n8.x4.shared.b16 {%0,%1,%2,%3}, [%4];"
                 : "=r"(r[0]), "=r"(r[1]), "=r"(r[2]), "=r"(r[3]) : "r"(addr));
}

// ---------------- float -> half conversion (weights/x, one-shot) ----------------
__global__ void f2h_kernel(const float* __restrict__ s, __half* __restrict__ d, int n4) {
    int i = blockIdx.x * blockDim.x + threadIdx.x;
    if (i < n4) {
        float4 v = ((const float4*)s)[i];
        uint2 u;
        u.x = f2h2(v.x, v.y);
        u.y = f2h2(v.z, v.w);
        ((uint2*)d)[i] = u;
    }
}

// ---------------- pipelined fp16 mma GEMM (fp16 operands in GMEM) ----------------
// C = epi(A[M,K(lda)] * B[N,K(ldb)]^T + bias), fp32 accum.
// epi: 0 = fp32 store(+bias), 1 = fp32 relu, 2 = C += scale*leaky(v+bias),
//      3 = fp16 store -> C16, 4 = fp16 relu -> C16
// N mult of 128, K mult of 32. grid (N/128, ceil(M/128)), block 256,
// dyn smem = 4*TBUF*4 bytes (double-buffered A+B tiles; rows 16 data words + 4 pad).
#define SRW 20
#define TBUF (128 * SRW)
__global__ __launch_bounds__(256) void gemm_mma(
    const __half* __restrict__ A, const __half* __restrict__ B,
    const float* __restrict__ bias, float* __restrict__ C, __half* __restrict__ C16,
    int M, int N, int K, int lda, int ldb, int epi, float scale)
{
    extern __shared__ uint32_t sm[];
    const int tid = threadIdx.x;
    const int wid = tid >> 5, lane = tid & 31;
    const int wm = wid & 1, wn = wid >> 1;       // warp tile: 64 rows x 32 cols
    const int row0 = blockIdx.y * 128, col0 = blockIdx.x * 128;
    const int lq = lane >> 2, lr = lane & 3;
    const int rr = lane & 7;
    const int aRow = wm * 64 + rr + ((lane >> 3) & 1) * 8;
    const int aColW = ((lane >> 4) & 1) * 4;
    const int bRow = wn * 32 + rr + ((lane >> 4) & 1) * 8;
    const int bColW = ((lane >> 3) & 1) * 4;

    float acc[4][4][4];
#pragma unroll
    for (int i = 0; i < 4; i++)
#pragma unroll
        for (int j = 0; j < 4; j++) {
            acc[i][j][0] = 0.f; acc[i][j][1] = 0.f;
            acc[i][j][2] = 0.f; acc[i][j][3] = 0.f;
        }

    const int s_row = tid >> 2;                  // staging: 4 threads per row (uint4 each)
    const int s_c = tid & 3;                     // 16B chunk within row
    const int nC = K >> 5;

    uint4 pa[2], pb[2];

#define LDG_CHUNK(cc)                                                                  \
    {                                                                                  \
        int k0 = (cc) << 5;                                                            \
        _Pragma("unroll")                                                              \
        for (int it = 0; it < 2; it++) {                                               \
            int row = it * 64 + s_row;                                                 \
            int gr = row0 + row;                                                       \
            pa[it] = make_uint4(0u, 0u, 0u, 0u);                                       \
            if (gr < M) pa[it] = *(const uint4*)(A + (size_t)gr * lda + k0 + s_c * 8); \
            pb[it] = *(const uint4*)(B + (size_t)(col0 + row) * ldb + k0 + s_c * 8);   \
        }                                                                              \
    }
#define STS_CHUNK(Ad, Bd)                                                              \
    {                                                                                  \
        _Pragma("unroll")                                                              \
        for (int it = 0; it < 2; it++) {                                               \
            int row = it * 64 + s_row;                                                 \
            *(uint4*)&(Ad)[row * SRW + s_c * 4] = pa[it];                              \
            *(uint4*)&(Bd)[row * SRW + s_c * 4] = pb[it];                              \
        }                                                                              \
    }
#define COMPUTE_KS(AsAddr, BsAddr, KS)                                                 \
    {                                                                                  \
        uint32_t bq[2][4];                                                             \
        _Pragma("unroll")                                                              \
        for (int ntp = 0; ntp < 2; ntp++)                                              \
            ldsm4(bq[ntp], (BsAddr) + (((bRow + ntp * 16) * SRW) + (KS) * 8 + bColW) * 4); \
        _Pragma("unroll")                                                              \
        for (int mt = 0; mt < 4; mt++) {                                               \
            uint32_t aq[4];                                                            \
            ldsm4(aq, (AsAddr) + (((aRow + mt * 16) * SRW) + (KS) * 8 + aColW) * 4);   \
            _Pragma("unroll")                                                          \
            for (int nt = 0; nt < 4; nt++)                                             \
                mma16(acc[mt][nt], aq[0], aq[1], aq[2], aq[3],                         \
                      bq[nt >> 1][(nt & 1) * 2 + 0], bq[nt >> 1][(nt & 1) * 2 + 1]);   \
        }                                                                              \
    }

    uint32_t* A0 = sm;
    uint32_t* B0 = sm + TBUF;
    uint32_t* A1 = sm + 2 * TBUF;
    uint32_t* B1 = sm + 3 * TBUF;
    const uint32_t sb = smem_u32(sm);
    const uint32_t aAddr0 = sb, bAddr0 = sb + TBUF * 4;
    const uint32_t aAddr1 = sb + 2 * TBUF * 4, bAddr1 = sb + 3 * TBUF * 4;

    LDG_CHUNK(0);
    STS_CHUNK(A0, B0);
    if (nC > 1) LDG_CHUNK(1);
    __syncthreads();

    for (int c = 0; c < nC; c++) {
        uint32_t aA = (c & 1) ? aAddr1 : aAddr0;
        uint32_t bA = (c & 1) ? bAddr1 : bAddr0;
        uint32_t* Asn = (c & 1) ? A0 : A1;
        uint32_t* Bsn = (c & 1) ? B0 : B1;
        COMPUTE_KS(aA, bA, 0);
        if (c + 1 < nC) STS_CHUNK(Asn, Bsn);
        COMPUTE_KS(aA, bA, 1);
        if (c + 2 < nC) LDG_CHUNK(c + 2);
        __syncthreads();
    }

    // ---- epilogue ----
    const int rbase = row0 + wm * 64;
    const int cbase = col0 + wn * 32;
#pragma unroll
    for (int mt = 0; mt < 4; mt++) {
        int r0 = rbase + mt * 16 + lq;
#pragma unroll
        for (int half = 0; half < 2; half++) {
            int r = r0 + half * 8;
            if (r < M) {
#pragma unroll
                for (int nt = 0; nt < 4; nt++) {
                    int c = cbase + nt * 8 + lr * 2;
                    float v0 = acc[mt][nt][half * 2 + 0];
                    float v1 = acc[mt][nt][half * 2 + 1];
                    if (bias) { v0 += bias[c]; v1 += bias[c + 1]; }
                    if (epi == 0) {
                        *(float2*)(C + (size_t)r * N + c) = make_float2(v0, v1);
                    } else if (epi == 1) {
                        *(float2*)(C + (size_t)r * N + c) =
                            make_float2(fmaxf(v0, 0.f), fmaxf(v1, 0.f));
                    } else if (epi == 2) {
                        float* cp = C + (size_t)r * N + c;
                        float2 o = *(float2*)cp;
                        o.x += scale * leakyf(v0, 0.01f);
                        o.y += scale * leakyf(v1, 0.01f);
                        *(float2*)cp = o;
                    } else if (epi == 3) {
                        *(uint32_t*)(C16 + (size_t)r * N + c) = f2h2(v0, v1);
                    } else {
                        *(uint32_t*)(C16 + (size_t)r * N + c) =
                            f2h2(fmaxf(v0, 0.f), fmaxf(v1, 0.f));
                    }
                }
            }
        }
    }
}

// ---------------- fp16 tensor-core flash attention (fp16 qkv input) ----------------
#define VSW 68
__global__ __launch_bounds__(256) void attn_tc() {
    __shared__ uint32_t QK[128 * SRW];
    __shared__ uint32_t VT[32 * VSW];
    const int b = blockIdx.z, h = blockIdx.y, qt = blockIdx.x;
    const int cnt = g_cnt[b];
    const int tid = threadIdx.x, wid = tid >> 5, lane = tid & 31;
    const int lq = lane >> 2, lr = lane & 3;
    const float qscale = 0.17677669529663687f;   // 1/sqrt(32)

    // ---- stage Q (fp16 copy; scale folded post-mma) ----
#pragma unroll
    for (int it = 0; it < 4; it++) {
        int idx = it * 256 + tid;
        int row = idx >> 3;
        int q = qt * 128 + row;
        uint2 u = make_uint2(0u, 0u);
        if (q < LMAX)
            u = *(const uint2*)(g_qkv16 + (size_t)(b * LMAX + q) * 384 + h * 32 + (idx & 7) * 4);
        *(uint2*)&QK[row * SRW + (idx & 7) * 2] = u;
    }
    __syncthreads();
    uint32_t qa[2][4];
    {
        int r = wid * 16 + lq;
#pragma unroll
        for (int ks = 0; ks < 2; ks++) {
            int kb = ks * 8 + lr;
            qa[ks][0] = QK[r * SRW + kb];
            qa[ks][1] = QK[(r + 8) * SRW + kb];
            qa[ks][2] = QK[r * SRW + kb + 4];
            qa[ks][3] = QK[(r + 8) * SRW + kb + 4];
        }
    }

    float m0 = -INFINITY, m1 = -INFINITY, den0 = 0.f, den1 = 0.f;
    float of[4][4];
#pragma unroll
    for (int nt = 0; nt < 4; nt++) {
        of[nt][0] = 0.f; of[nt][1] = 0.f; of[nt][2] = 0.f; of[nt][3] = 0.f;
    }

    for (int kb0 = 0; kb0 < LMAX; kb0 += 128) {
        __syncthreads();
        // ---- stage K ----
#pragma unroll
        for (int it = 0; it < 4; it++) {
            int idx = it * 256 + tid;
            int row = idx >> 3;
            int key = kb0 + row;
            uint2 u = make_uint2(0u, 0u);
            if (key < LMAX)
                u = *(const uint2*)(g_qkv16 + (size_t)(b * LMAX + key) * 384 + 128 + h * 32 + (idx & 7) * 4);
            *(uint2*)&QK[row * SRW + (idx & 7) * 2] = u;
        }
        // ---- stage V^T via byte_perm ----
#pragma unroll
        for (int it = 0; it < 2; it++) {
            int item = it * 256 + tid;
            int kp = item & 63, g = item >> 6;
            int k0 = kb0 + 2 * kp;
            uint2 a = make_uint2(0u, 0u), bb = make_uint2(0u, 0u);
            if (k0 < LMAX)
                a = *(const uint2*)(g_qkv16 + (size_t)(b * LMAX + k0) * 384 + 256 + h * 32 + g * 4);
            if (k0 + 1 < LMAX)
                bb = *(const uint2*)(g_qkv16 + (size_t)(b * LMAX + k0 + 1) * 384 + 256 + h * 32 + g * 4);
            VT[(g * 4 + 0) * VSW + kp] = __byte_perm(a.x, bb.x, 0x5410);
            VT[(g * 4 + 1) * VSW + kp] = __byte_perm(a.x, bb.x, 0x7632);
            VT[(g * 4 + 2) * VSW + kp] = __byte_perm(a.y, bb.y, 0x5410);
            VT[(g * 4 + 3) * VSW + kp] = __byte_perm(a.y, bb.y, 0x7632);
        }
        __syncthreads();

        float sf[16][4];
#pragma unroll
        for (int nt = 0; nt < 16; nt++) {
            sf[nt][0] = 0.f; sf[nt][1] = 0.f; sf[nt][2] = 0.f; sf[nt][3] = 0.f;
        }
#pragma unroll
        for (int ks = 0; ks < 2; ks++) {
            int kk = ks * 8 + lr;
#pragma unroll
            for (int nt = 0; nt < 16; nt++) {
                uint32_t b0 = QK[(nt * 8 + lq) * SRW + kk];
                uint32_t b1 = QK[(nt * 8 + lq) * SRW + kk + 4];
                mma16(sf[nt], qa[ks][0], qa[ks][1], qa[ks][2], qa[ks][3], b0, b1);
            }
        }
        float bm0 = -INFINITY, bm1 = -INFINITY;
#pragma unroll
        for (int nt = 0; nt < 16; nt++) {
            sf[nt][0] *= qscale; sf[nt][1] *= qscale;
            sf[nt][2] *= qscale; sf[nt][3] *= qscale;
            int c = kb0 + nt * 8 + lr * 2;
            if (c >= cnt) { sf[nt][0] = -1e30f; sf[nt][2] = -1e30f; }
            if (c + 1 >= cnt) { sf[nt][1] = -1e30f; sf[nt][3] = -1e30f; }
            bm0 = fmaxf(bm0, fmaxf(sf[nt][0], sf[nt][1]));
            bm1 = fmaxf(bm1, fmaxf(sf[nt][2], sf[nt][3]));
        }
        bm0 = fmaxf(bm0, __shfl_xor_sync(0xffffffffu, bm0, 1));
        bm0 = fmaxf(bm0, __shfl_xor_sync(0xffffffffu, bm0, 2));
        bm1 = fmaxf(bm1, __shfl_xor_sync(0xffffffffu, bm1, 1));
        bm1 = fmaxf(bm1, __shfl_xor_sync(0xffffffffu, bm1, 2));
        float nm0 = fmaxf(m0, bm0), nm1 = fmaxf(m1, bm1);
        float cor0 = __expf(m0 - nm0), cor1 = __expf(m1 - nm1);
        m0 = nm0; m1 = nm1;
        float s0 = 0.f, s1 = 0.f;
        uint32_t pf01[16], pf23[16];
#pragma unroll
        for (int nt = 0; nt < 16; nt++) {
            float p0 = __expf(sf[nt][0] - nm0), p1 = __expf(sf[nt][1] - nm0);
            float p2 = __expf(sf[nt][2] - nm1), p3 = __expf(sf[nt][3] - nm1);
            s0 += p0 + p1; s1 += p2 + p3;
            pf01[nt] = f2h2(p0, p1);
            pf23[nt] = f2h2(p2, p3);
        }
        s0 += __shfl_xor_sync(0xffffffffu, s0, 1);
        s0 += __shfl_xor_sync(0xffffffffu, s0, 2);
        s1 += __shfl_xor_sync(0xffffffffu, s1, 1);
        s1 += __shfl_xor_sync(0xffffffffu, s1, 2);
        den0 = den0 * cor0 + s0;
        den1 = den1 * cor1 + s1;
#pragma unroll
        for (int nt = 0; nt < 4; nt++) {
            of[nt][0] *= cor0; of[nt][1] *= cor0;
            of[nt][2] *= cor1; of[nt][3] *= cor1;
        }
#pragma unroll
        for (int ks = 0; ks < 8; ks++) {
            uint32_t a0 = pf01[2 * ks], a1 = pf23[2 * ks];
            uint32_t a2 = pf01[2 * ks + 1], a3 = pf23[2 * ks + 1];
#pragma unroll
            for (int nt = 0; nt < 4; nt++) {
                uint32_t b0 = VT[(nt * 8 + lq) * VSW + 8 * ks + lr];
                uint32_t b1 = VT[(nt * 8 + lq) * VSW + 8 * ks + lr + 4];
                mma16(of[nt], a0, a1, a2, a3, b0, b1);
            }
        }
    }

    // ---- write O (fp16, feeds proj GEMM) ----
    float i0 = 1.f / den0, i1 = 1.f / den1;
    int q_lo = qt * 128 + wid * 16 + lq, q_hi = q_lo + 8;
#pragma unroll
    for (int nt = 0; nt < 4; nt++) {
        int col = h * 32 + nt * 8 + lr * 2;
        if (q_lo < LMAX)
            *(uint32_t*)(g_attn16 + (size_t)(b * LMAX + q_lo) * DD + col) =
                f2h2(of[nt][0] * i0, of[nt][1] * i0);
        if (q_hi < LMAX)
            *(uint32_t*)(g_attn16 + (size_t)(b * LMAX + q_hi) * DD + col) =
                f2h2(of[nt][2] * i1, of[nt][3] * i1);
    }
}

// ---------------- GAT kernels (CSR-bucketed, batched over hops) ----------------
__global__ void zero_acc_kernel() {
    size_t i = (size_t)blockIdx.x * blockDim.x + threadIdx.x;
    if (i < (size_t)NN * DD / 4) ((float4*)g_acc)[i] = make_float4(0.f, 0.f, 0.f, 0.f);
}
__global__ void zero_y_kernel() {
    size_t i = (size_t)blockIdx.x * blockDim.x + threadIdx.x;
    if (i < (size_t)NM * DD / 4) {
        ((float4*)g_y)[i] = make_float4(0.f, 0.f, 0.f, 0.f);
        ((uint2*)g_y16)[i] = make_uint2(0u, 0u);
    }
}

__global__ void gat_prep3(const float* __restrict__ a_src,
                          const float* __restrict__ a_dst)
{
    int gid = blockIdx.x * blockDim.x + threadIdx.x;
    int node = gid >> 5, lane = gid & 31;
    int hop = blockIdx.y;
    if (node >= NN) return;
    float s[4], d[4];
#pragma unroll
    for (int j = 0; j < 4; j++) {
        int c = j * 32 + lane;
        float hv = g_h3[(size_t)node * 384 + hop * 128 + c];
        s[j] = hv * a_src[hop * DD + c];
        d[j] = hv * a_dst[hop * DD + c];
    }
#pragma unroll
    for (int j = 0; j < 4; j++)
#pragma unroll
        for (int o = 16; o > 0; o >>= 1) {
            s[j] += __shfl_xor_sync(0xffffffffu, s[j], o);
            d[j] += __shfl_xor_sync(0xffffffffu, d[j], o);
        }
    if (lane == 0) {
        int idx = (node * 3 + hop) * 4;
        *(float4*)&g_als3[idx] = make_float4(s[0], s[1], s[2], s[3]);
        *(float4*)&g_ald3[idx] = make_float4(d[0], d[1], d[2], d[3]);
        g_deg[hop * NN + node] = 0;
    }
}

__global__ void deg3(const int* __restrict__ e0, const int* __restrict__ e1,
                     const int* __restrict__ e2)
{
    int hop = blockIdx.y;
    const int* ei = (hop == 0) ? e0 : (hop == 1) ? e1 : e2;
    int t = blockIdx.x * blockDim.x + threadIdx.x;
    if (t >= NITEMS) return;
    int dst = (t < NE) ? ei[NE + t] : t - NE;
    atomicAdd(&g_deg[hop * NN + dst], 1);
}

__global__ __launch_bounds__(1024) void scan3() {
    __shared__ int part[1024];
    const int hop = blockIdx.x;
    const int t = threadIdx.x;
    const int CH = (NN + 1023) / 1024;
    int beg = t * CH, end = beg + CH;
    if (end > NN) end = NN;
    int s = 0;
    for (int i = beg; i < end; i++) s += g_deg[hop * NN + i];
    part[t] = s;
    __syncthreads();
    for (int o = 1; o < 1024; o <<= 1) {
        int u = (t >= o) ? part[t - o] : 0;
        __syncthreads();
        part[t] += u;
        __syncthreads();
    }
    int run = part[t] - s;
    for (int i = beg; i < end; i++) {
        int d = g_deg[hop * NN + i];
        g_off[hop * (NN + 1) + i] = run;
        g_cur[hop * NN + i] = run;
        run += d;
    }
    if (t == 0) g_off[hop * (NN + 1) + NN] = NITEMS;
}

__global__ void edge_scat3(const int* __restrict__ e0, const int* __restrict__ e1,
                           const int* __restrict__ e2)
{
    int hop = blockIdx.y;
    const int* ei = (hop == 0) ? e0 : (hop == 1) ? e1 : e2;
    int t = blockIdx.x * blockDim.x + threadIdx.x;
    if (t >= NITEMS) return;
    int src, dst;
    if (t < NE) { src = ei[t]; dst = ei[NE + t]; }
    else { src = dst = t - NE; }
    float4 a = *(const float4*)&g_als3[(src * 3 + hop) * 4];
    float4 b = *(const float4*)&g_ald3[(dst * 3 + hop) * 4];
    float4 ew;
    ew.x = expf(leakyf(a.x + b.x, 0.2f));
    ew.y = expf(leakyf(a.y + b.y, 0.2f));
    ew.z = expf(leakyf(a.z + b.z, 0.2f));
    ew.w = expf(leakyf(a.w + b.w, 0.2f));
    int pos = atomicAdd(&g_cur[hop * NN + dst], 1);
    g_srcS[(size_t)hop * NITEMS + pos] = src;
    *(float4*)&g_ew[((size_t)hop * NITEMS + pos) * 4] = ew;
}

// aggregation: warp per (dst, hop); writes fp16 gout316 (dec GEMM operand)
__global__ void aggr3(const float* __restrict__ bias) {
    int gid = blockIdx.x * blockDim.x + threadIdx.x;
    int dst = gid >> 5, lane = gid & 31;
    int hop = blockIdx.y;
    if (dst >= NN) return;
    int e0 = g_off[hop * (NN + 1) + dst];
    int e1 = g_off[hop * (NN + 1) + dst + 1];
    float4 den = make_float4(0.f, 0.f, 0.f, 0.f);
    for (int e = e0 + lane; e < e1; e += 32) {
        float4 w4 = *(const float4*)&g_ew[((size_t)hop * NITEMS + e) * 4];
        den.x += w4.x; den.y += w4.y; den.z += w4.z; den.w += w4.w;
    }
#pragma unroll
    for (int o = 16; o > 0; o >>= 1) {
        den.x += __shfl_xor_sync(0xffffffffu, den.x, o);
        den.y += __shfl_xor_sync(0xffffffffu, den.y, o);
        den.z += __shfl_xor_sync(0xffffffffu, den.z, o);
        den.w += __shfl_xor_sync(0xffffffffu, den.w, o);
    }
    float4 inv = make_float4(1.f / den.x, 1.f / den.y, 1.f / den.z, 1.f / den.w);
    float a0 = 0.f, a1 = 0.f, a2 = 0.f, a3 = 0.f;
    for (int e = e0; e < e1; e++) {
        float4 w4 = *(const float4*)&g_ew[((size_t)hop * NITEMS + e) * 4];
        int src = g_srcS[(size_t)hop * NITEMS + e];
        const float* hs = g_h3 + (size_t)src * 384 + hop * 128;
        a0 += w4.x * inv.x * hs[lane];
        a1 += w4.y * inv.y * hs[32 + lane];
        a2 += w4.z * inv.z * hs[64 + lane];
        a3 += w4.w * inv.w * hs[96 + lane];
    }
    __half* gd = g_gout316 + (size_t)dst * 384 + hop * 128;
    const float* bb = bias + hop * 128;
    gd[lane]      = __float2half(a0 + bb[lane]);
    gd[32 + lane] = __float2half(a1 + bb[32 + lane]);
    gd[64 + lane] = __float2half(a2 + bb[64 + lane]);
    gd[96 + lane] = __float2half(a3 + bb[96 + lane]);
}

// ---------------- position / count kernels ----------------
__global__ void hist_kernel(const int* __restrict__ genre) {
    __shared__ int loc[NG];
    if (threadIdx.x < NG) loc[threadIdx.x] = 0;
    __syncthreads();
    int i = blockIdx.x * 128 + threadIdx.x;
    if (i < NM) atomicAdd(&loc[genre[i]], 1);
    __syncthreads();
    if (threadIdx.x < NG) g_chist[blockIdx.x * NG + threadIdx.x] = loc[threadIdx.x];
}
__global__ void scan_kernel() {
    int g = threadIdx.x;
    if (g >= NG) return;
    int run = 0;
    for (int c = 0; c < NCHUNK; c++) {
        int t = g_chist[c * NG + g];
        g_chist[c * NG + g] = run;
        run += t;
    }
    g_cnt[g] = run;
}
__global__ void pos_kernel(const int* __restrict__ genre) {
    int c = blockIdx.x * blockDim.x + threadIdx.x;
    if (c >= NCHUNK) return;
    int off[NG];
    for (int g = 0; g < NG; g++) off[g] = g_chist[c * NG + g];
    int base = c * 128;
    int end = base + 128; if (end > NM) end = NM;
    for (int i = base; i < end; i++) {
        int g = genre[i];
        g_pos[i] = off[g]++;
    }
}

// gather: y fp32 + y16 + xm16
__global__ void gather_kernel(const int* __restrict__ movie_idx, const int* __restrict__ genre) {
    int t = blockIdx.x * blockDim.x + threadIdx.x;
    if (t >= NM * 32) return;
    int i = t >> 5, c4 = (t & 31) * 4;
    float4 v = *(const float4*)&g_acc[(size_t)movie_idx[i] * DD + c4];
    uint2 h2 = make_uint2(f2h2(v.x, v.y), f2h2(v.z, v.w));
    *(uint2*)(g_xm16 + (size_t)i * DD + c4) = h2;
    int row = genre[i] * LMAX + g_pos[i];
    *(float4*)&g_y[(size_t)row * DD + c4] = v;
    *(uint2*)(g_y16 + (size_t)row * DD + c4) = h2;
}

// ---------------- LayerNorm (fused residual, dual fp32+fp16 output) ----------------
__global__ void ln_kernel(float* __restrict__ y, __half* __restrict__ y16,
                          const float* __restrict__ t,
                          const float* __restrict__ gam, const float* __restrict__ bet,
                          int rows)
{
    int gid = blockIdx.x * blockDim.x + threadIdx.x;
    int row = gid >> 5, lane = gid & 31;
    if (row >= rows) return;
    size_t off = (size_t)row * DD + lane * 4;
    float4 v = *(float4*)(y + off);
    float4 tv = *(const float4*)(t + off);
    v.x += tv.x; v.y += tv.y; v.z += tv.z; v.w += tv.w;
    float s = v.x + v.y + v.z + v.w;
#pragma unroll
    for (int o = 16; o > 0; o >>= 1) s += __shfl_xor_sync(0xffffffffu, s, o);
    float mean = s * (1.f / DD);
    float dx = v.x - mean, dy = v.y - mean, dz = v.z - mean, dw = v.w - mean;
    float ss = dx * dx + dy * dy + dz * dz + dw * dw;
#pragma unroll
    for (int o = 16; o > 0; o >>= 1) ss += __shfl_xor_sync(0xffffffffu, ss, o);
    float inv = rsqrtf(ss * (1.f / DD) + 1e-5f);
    float4 gg = *(const float4*)(gam + lane * 4);
    float4 bb = *(const float4*)(bet + lane * 4);
    v.x = dx * inv * gg.x + bb.x;
    v.y = dy * inv * gg.y + bb.y;
    v.z = dz * inv * gg.z + bb.z;
    v.w = dw * inv * gg.w + bb.w;
    *(float4*)(y + off) = v;
    *(uint2*)(y16 + off) = make_uint2(f2h2(v.x, v.y), f2h2(v.z, v.w));
}

// ---------------- pooling / fusion ----------------
__global__ void pool_kernel() {
    int g = blockIdx.x, d = threadIdx.x;
    int cnt = g_cnt[g];
    float s = 0.f;
    for (int t = 0; t < cnt; t++) s += g_y[(size_t)(g * LMAX + t) * DD + d];
    g_pooled[g * DD + d] = s / fmaxf((float)cnt, 1.f);
}

__global__ void pe_kernel(const float* __restrict__ fus_w) {
    int g = blockIdx.x, n = threadIdx.x;
    float s = 0.f;
    for (int k = 0; k < DD; k++)
        s += g_pooled[g * DD + k] * fus_w[n * 256 + 128 + k];
    g_pe[g * DD + n] = s;
}

__global__ void copy_out_kernel(float* __restrict__ out) {
    size_t i = (size_t)blockIdx.x * blockDim.x + threadIdx.x;
    if (i < (size_t)NN * DD / 4) ((float4*)out)[i] = ((const float4*)g_acc)[i];
}

__global__ void fuse_out_kernel(const int* __restrict__ movie_idx, const int* __restrict__ genre,
                                const float* __restrict__ fus_b, float* __restrict__ out)
{
    int t = blockIdx.x * blockDim.x + threadIdx.x;
    if (t >= NM * 32) return;
    int i = t >> 5, c4 = (t & 31) * 4;
    float4 v = *(const float4*)&g_tmp[(size_t)i * DD + c4];
    float4 p = *(const float4*)&g_pe[genre[i] * DD + c4];
    float4 bb = *(const float4*)(fus_b + c4);
    v.x = leakyf(v.x + p.x + bb.x, 0.01f);
    v.y = leakyf(v.y + p.y + bb.y, 0.01f);
    v.z = leakyf(v.z + p.z + bb.z, 0.01f);
    v.w = leakyf(v.w + p.w + bb.w, 0.01f);
    *(float4*)&out[(size_t)movie_idx[i] * DD + c4] = v;
}

// ---------------- launch ----------------
extern "C" void kernel_launch(void* const* d_in, const int* in_sizes, int n_in,
                              void* d_out, int out_size)
{
    const float* x        = (const float*)d_in[0];
    const int*   e0       = (const int*)d_in[1];
    const int*   e1       = (const int*)d_in[2];
    const int*   e2       = (const int*)d_in[3];
    const int*   movie_idx = (const int*)d_in[4];
    const int*   genre     = (const int*)d_in[5];
    const float* gat_W    = (const float*)d_in[6];
    const float* att_src  = (const float*)d_in[7];
    const float* att_dst  = (const float*)d_in[8];
    const float* gat_bias = (const float*)d_in[9];
    const float* dec_W    = (const float*)d_in[10];
    const float* dec_b    = (const float*)d_in[11];
    const float* qkv_w    = (const float*)d_in[12];
    const float* qkv_b    = (const float*)d_in[13];
    const float* out_w    = (const float*)d_in[14];
    const float* out_b    = (const float*)d_in[15];
    const float* ln1_g    = (const float*)d_in[16];
    const float* ln1_b    = (const float*)d_in[17];
    const float* ln2_g    = (const float*)d_in[18];
    const float* ln2_b    = (const float*)d_in[19];
    const float* ffn_w1   = (const float*)d_in[20];
    const float* ffn_b1   = (const float*)d_in[21];
    const float* ffn_w2   = (const float*)d_in[22];
    const float* ffn_b2   = (const float*)d_in[23];
    const float* fus_w    = (const float*)d_in[24];
    const float* fus_b    = (const float*)d_in[25];
    float* out = (float*)d_out;

    float *p_h3, *p_acc, *p_y, *p_tmp;
    __half *p_x16, *p_gout316, *p_y16, *p_qkv16, *p_attn16, *p_ffn16, *p_xm16;
    __half *p_gatW16, *p_decW16, *p_qkvW16, *p_outW16, *p_fw116, *p_fw216, *p_fusW16;
    cudaGetSymbolAddress((void**)&p_h3,     g_h3);
    cudaGetSymbolAddress((void**)&p_acc,    g_acc);
    cudaGetSymbolAddress((void**)&p_y,      g_y);
    cudaGetSymbolAddress((void**)&p_tmp,    g_tmp);
    cudaGetSymbolAddress((void**)&p_x16,    g_x16);
    cudaGetSymbolAddress((void**)&p_gout316, g_gout316);
    cudaGetSymbolAddress((void**)&p_y16,    g_y16);
    cudaGetSymbolAddress((void**)&p_qkv16,  g_qkv16);
    cudaGetSymbolAddress((void**)&p_attn16, g_attn16);
    cudaGetSymbolAddress((void**)&p_ffn16,  g_ffn16);
    cudaGetSymbolAddress((void**)&p_xm16,   g_xm16);
    cudaGetSymbolAddress((void**)&p_gatW16, g_gatW16);
    cudaGetSymbolAddress((void**)&p_decW16, g_decW16);
    cudaGetSymbolAddress((void**)&p_qkvW16, g_qkvW16);
    cudaGetSymbolAddress((void**)&p_outW16, g_outW16);
    cudaGetSymbolAddress((void**)&p_fw116,  g_fw116);
    cudaGetSymbolAddress((void**)&p_fw216,  g_fw216);
    cudaGetSymbolAddress((void**)&p_fusW16, g_fusW16);

    const int GSMEM = 4 * TBUF * 4;   // 40960 B
    cudaFuncSetAttribute(gemm_mma, cudaFuncAttributeMaxDynamicSharedMemorySize, GSMEM);

    const int MTN = (NN + 127) / 128;  // 391
    const int MT  = (NM + 127) / 128;  // 160

#define F2H(src, dst, n) f2h_kernel<<<((n) / 4 + 255) / 256, 256>>>(src, dst, (n) / 4)
    // -------- one-shot fp16 conversions --------
    F2H(x, p_x16, NN * DD);
    F2H(gat_W, p_gatW16, 3 * DD * DD);
    F2H(dec_W, p_decW16, 3 * DD * DD);
    F2H(qkv_w, p_qkvW16, NL * 3 * DD * DD);
    F2H(out_w, p_outW16, NL * DD * DD);
    F2H(ffn_w1, p_fw116, NL * FFD * DD);
    F2H(ffn_w2, p_fw216, NL * DD * FFD);
    F2H(fus_w, p_fusW16, DD * 256);

    // -------- GAT --------
    zero_acc_kernel<<<(NN * DD / 4 + 255) / 256, 256>>>();
    gemm_mma<<<dim3(3, MTN), 256, GSMEM>>>(p_x16, p_gatW16, nullptr, p_h3, nullptr,
                                           NN, 384, DD, DD, DD, 0, 0.f);
    gat_prep3<<<dim3((NN * 32 + 255) / 256, 3), 256>>>(att_src, att_dst);
    deg3<<<dim3((NITEMS + 255) / 256, 3), 256>>>(e0, e1, e2);
    scan3<<<3, 1024>>>();
    edge_scat3<<<dim3((NITEMS + 255) / 256, 3), 256>>>(e0, e1, e2);
    aggr3<<<dim3((NN * 32 + 255) / 256, 3), 256>>>(gat_bias);
    for (int k = 0; k < 3; k++) {
        float scale = (float)exp(-0.1 * k);
        gemm_mma<<<dim3(1, MTN), 256, GSMEM>>>(
            p_gout316 + k * 128, p_decW16 + (size_t)k * DD * DD, dec_b + k * DD,
            p_acc, nullptr, NN, DD, DD, 384, DD, 2, scale);
    }

    // -------- build genre sequences --------
    hist_kernel<<<NCHUNK, 128>>>(genre);
    scan_kernel<<<1, 32>>>();
    pos_kernel<<<1, 256>>>(genre);
    zero_y_kernel<<<(NM * DD / 4 + 255) / 256, 256>>>();
    gather_kernel<<<(NM * 32 + 255) / 256, 256>>>(movie_idx, genre);

    // -------- transformer (4 layers) --------
    for (int l = 0; l < NL; l++) {
        gemm_mma<<<dim3(3 * DD / 128, MT), 256, GSMEM>>>(
            p_y16, p_qkvW16 + (size_t)l * 3 * DD * DD, qkv_b + l * 3 * DD,
            nullptr, p_qkv16, NM, 3 * DD, DD, DD, DD, 3, 0.f);
        attn_tc<<<dim3((LMAX + 127) / 128, NHEADS, NG), 256>>>();
        gemm_mma<<<dim3(1, MT), 256, GSMEM>>>(
            p_attn16, p_outW16 + (size_t)l * DD * DD, out_b + l * DD,
            p_tmp, nullptr, NM, DD, DD, DD, DD, 0, 0.f);
        ln_kernel<<<(NM * 32 + 255) / 256, 256>>>(p_y, p_y16, p_tmp,
                                                  ln1_g + l * DD, ln1_b + l * DD, NM);
        gemm_mma<<<dim3(FFD / 128, MT), 256, GSMEM>>>(
            p_y16, p_fw116 + (size_t)l * FFD * DD, ffn_b1 + l * FFD,
            nullptr, p_ffn16, NM, FFD, DD, DD, DD, 4, 0.f);
        gemm_mma<<<dim3(1, MT), 256, GSMEM>>>(
            p_ffn16, p_fw216 + (size_t)l * DD * FFD, ffn_b2 + l * DD,
            p_tmp, nullptr, NM, DD, FFD, FFD, FFD, 0, 0.f);
        ln_kernel<<<(NM * 32 + 255) / 256, 256>>>(p_y, p_y16, p_tmp,
                                                  ln2_g + l * DD, ln2_b + l * DD, NM);
    }

    // -------- pool + fuse + write output --------
    pool_kernel<<<NG, DD>>>();
    pe_kernel<<<NG, DD>>>(fus_w);
    gemm_mma<<<dim3(1, MT), 256, GSMEM>>>(p_xm16, p_fusW16, nullptr, p_tmp, nullptr,
                                          NM, DD, DD, DD, 256, 0, 0.f);
    copy_out_kernel<<<(NN * DD / 4 + 255) / 256, 256>>>(out);
    fuse_out_kernel<<<(NM * 32 + 255) / 256, 256>>>(movie_idx, genre, fus_b, out);
}

// round 10
// speedup vs baseline: 3.9008x; 1.0254x over previous
#include <cuda_runtime.h>
#include <cuda_fp16.h>
#include <math.h>
#include <stdint.h>

#define NN 50000
#define NE 400000
#define DD 128
#define NM 20400
#define NG 30
#define LMAX 680
#define NHEADS 4
#define NL 4
#define FFD 2048
#define NCHUNK 160   // ceil(20400/128)
#define NITEMS (NE + NN)

// ---------------- scratch (device globals; no runtime allocation) ----------------
__device__ __align__(16) float  g_als3[NN * 3 * NHEADS];
__device__ __align__(16) float  g_ald3[NN * 3 * NHEADS];
__device__ __align__(16) float  g_ew[(size_t)3 * NITEMS * NHEADS];
__device__ int g_srcS[(size_t)3 * NITEMS];
__device__ int g_deg[3 * NN];
__device__ int g_off[3 * (NN + 1)];
__device__ int g_cur[3 * NN];
__device__ __align__(16) float  g_y[(size_t)NM * DD];
__device__ __align__(16) float  g_tmp[(size_t)NM * DD];
__device__ __align__(16) float  g_pooled[NG * DD];
__device__ __align__(16) float  g_pe[NG * DD];
__device__ int g_pos[NM];
__device__ int g_cnt[NG];
__device__ int g_chist[NCHUNK * NG];
// fp16 shadows / intermediates
__device__ __align__(16) __half g_x16[(size_t)NN * DD];
__device__ __align__(16) __half g_h316[(size_t)NN * 384];
__device__ __align__(16) __half g_gout316[(size_t)NN * 384];
__device__ __align__(16) __half g_y16[(size_t)NM * DD];
__device__ __align__(16) __half g_qkv16[(size_t)NM * 3 * DD];
__device__ __align__(16) __half g_attn16[(size_t)NM * DD];
__device__ __align__(16) __half g_ffn16[(size_t)NM * FFD];
__device__ __align__(16) __half g_xm16[(size_t)NM * DD];
// fp16 weights
__device__ __align__(16) __half g_gatW16[3 * DD * DD];
__device__ __align__(16) __half g_decW16[3 * DD * DD];
__device__ __align__(16) __half g_qkvW16[NL * 3 * DD * DD];
__device__ __align__(16) __half g_outW16[NL * DD * DD];
__device__ __align__(16) __half g_fw116[(size_t)NL * FFD * DD];
__device__ __align__(16) __half g_fw216[(size_t)NL * DD * FFD];
__device__ __align__(16) __half g_fusW16[DD * 256];

// ---------------- small helpers ----------------
__device__ __forceinline__ float leakyf(float x, float s) { return x >= 0.f ? x : s * x; }

__device__ __forceinline__ uint32_t f2h2(float lo, float hi) {
    uint32_t r;
    asm("cvt.rn.f16x2.f32 %0, %1, %2;" : "=r"(r) : "f"(hi), "f"(lo));
    return r;
}

__device__ __forceinline__ uint32_t smem_u32(const void* p) {
    uint32_t a;
    asm("{ .reg .u64 t; cvta.to.shared.u64 t, %1; cvt.u32.u64 %0, t; }" : "=r"(a) : "l"(p));
    return a;
}

__device__ __forceinline__ void mma16(float* c, uint32_t a0, uint32_t a1, uint32_t a2,
                                      uint32_t a3, uint32_t b0, uint32_t b1) {
    asm volatile(
        "mma.sync.aligned.m16n8k16.row.col.f32.f16.f16.f32 "
        "{%0,%1,%2,%3}, {%4,%5,%6,%7}, {%8,%9}, {%0,%1,%2,%3};"
        : "+f"(c[0]), "+f"(c[1]), "+f"(c[2]), "+f"(c[3])
        : "r"(a0), "r"(a1), "r"(a2), "r"(a3), "r"(b0), "r"(b1));
}

__device__ __forceinline__ void ldsm4(uint32_t* r, uint32_t addr) {
    asm volatile("ldmatrix.sync.aligned.m8n8.x4.shared.b16 {%0,%1,%2,%3}, [%4];"
                 : "=r"(r[0]), "=r"(r[1]), "=r"(r[2]), "=r"(r[3]) : "r"(addr));
}

// ---------------- float -> half conversion ----------------
__global__ void f2h_kernel(const float* __restrict__ s, __half* __restrict__ d, int n4) {
    int i = blockIdx.x * blockDim.x + threadIdx.x;
    if (i < n4) {
        float4 v = ((const float4*)s)[i];
        uint2 u;
        u.x = f2h2(v.x, v.y);
        u.y = f2h2(v.z, v.w);
        ((uint2*)d)[i] = u;
    }
}

#define SRW 20
#define TBUF (128 * SRW)

// common fragment-index setup
#define FRAG_SETUP                                                  \
    const int tid = threadIdx.x;                                    \
    const int wid = tid >> 5, lane = tid & 31;                      \
    const int wm = wid & 1, wn = wid >> 1;                          \
    const int lq = lane >> 2, lr = lane & 3;                        \
    const int rr = lane & 7;                                        \
    const int aRow = wm * 64 + rr + ((lane >> 3) & 1) * 8;          \
    const int aColW = ((lane >> 4) & 1) * 4;                        \
    const int bRow = wn * 32 + rr + ((lane >> 4) & 1) * 8;          \
    const int bColW = ((lane >> 3) & 1) * 4;                        \
    const int s_row = tid >> 2;                                     \
    const int s_c = tid & 3;

#define STS_CHUNK(Ad, Bd)                                           \
    {                                                               \
        _Pragma("unroll")                                           \
        for (int it = 0; it < 2; it++) {                            \
            int row = it * 64 + s_row;                              \
            *(uint4*)&(Ad)[row * SRW + s_c * 4] = pa[it];           \
            *(uint4*)&(Bd)[row * SRW + s_c * 4] = pb[it];           \
        }                                                           \
    }
#define COMPUTE_KS(AsAddr, BsAddr, KS)                                                 \
    {                                                                                  \
        uint32_t bq[2][4];                                                             \
        _Pragma("unroll")                                                              \
        for (int ntp = 0; ntp < 2; ntp++)                                              \
            ldsm4(bq[ntp], (BsAddr) + (((bRow + ntp * 16) * SRW) + (KS) * 8 + bColW) * 4); \
        _Pragma("unroll")                                                              \
        for (int mt = 0; mt < 4; mt++) {                                               \
            uint32_t aq[4];                                                            \
            ldsm4(aq, (AsAddr) + (((aRow + mt * 16) * SRW) + (KS) * 8 + aColW) * 4);   \
            _Pragma("unroll")                                                          \
            for (int nt = 0; nt < 4; nt++)                                             \
                mma16(acc[mt][nt], aq[0], aq[1], aq[2], aq[3],                         \
                      bq[nt >> 1][(nt & 1) * 2 + 0], bq[nt >> 1][(nt & 1) * 2 + 1]);   \
        }                                                                              \
    }

// ---------------- pipelined fp16 mma GEMM ----------------
// C = epi(A[M,K(lda)] * B[N,K(ldb)]^T + bias), fp32 accum.
// epi: 0 = fp32 store(+bias), 3 = fp16 store -> C16, 4 = fp16 relu -> C16
__global__ __launch_bounds__(256) void gemm_mma(
    const __half* __restrict__ A, const __half* __restrict__ B,
    const float* __restrict__ bias, float* __restrict__ C, __half* __restrict__ C16,
    int M, int N, int K, int lda, int ldb, int epi)
{
    extern __shared__ uint32_t sm[];
    FRAG_SETUP
    const int row0 = blockIdx.y * 128, col0 = blockIdx.x * 128;

    float acc[4][4][4];
#pragma unroll
    for (int i = 0; i < 4; i++)
#pragma unroll
        for (int j = 0; j < 4; j++) {
            acc[i][j][0] = 0.f; acc[i][j][1] = 0.f;
            acc[i][j][2] = 0.f; acc[i][j][3] = 0.f;
        }
    const int nC = K >> 5;
    uint4 pa[2], pb[2];

#define LDG_CHUNK(cc)                                                                  \
    {                                                                                  \
        int k0 = (cc) << 5;                                                            \
        _Pragma("unroll")                                                              \
        for (int it = 0; it < 2; it++) {                                               \
            int row = it * 64 + s_row;                                                 \
            int gr = row0 + row;                                                       \
            pa[it] = make_uint4(0u, 0u, 0u, 0u);                                       \
            if (gr < M) pa[it] = *(const uint4*)(A + (size_t)gr * lda + k0 + s_c * 8); \
            pb[it] = *(const uint4*)(B + (size_t)(col0 + row) * ldb + k0 + s_c * 8);   \
        }                                                                              \
    }

    uint32_t* A0 = sm;
    uint32_t* B0 = sm + TBUF;
    uint32_t* A1 = sm + 2 * TBUF;
    uint32_t* B1 = sm + 3 * TBUF;
    const uint32_t sb = smem_u32(sm);
    const uint32_t aAddr0 = sb, bAddr0 = sb + TBUF * 4;
    const uint32_t aAddr1 = sb + 2 * TBUF * 4, bAddr1 = sb + 3 * TBUF * 4;

    LDG_CHUNK(0);
    STS_CHUNK(A0, B0);
    if (nC > 1) LDG_CHUNK(1);
    __syncthreads();

    for (int c = 0; c < nC; c++) {
        uint32_t aA = (c & 1) ? aAddr1 : aAddr0;
        uint32_t bA = (c & 1) ? bAddr1 : bAddr0;
        uint32_t* Asn = (c & 1) ? A0 : A1;
        uint32_t* Bsn = (c & 1) ? B0 : B1;
        COMPUTE_KS(aA, bA, 0);
        if (c + 1 < nC) STS_CHUNK(Asn, Bsn);
        COMPUTE_KS(aA, bA, 1);
        if (c + 2 < nC) LDG_CHUNK(c + 2);
        __syncthreads();
    }

    const int rbase = row0 + wm * 64;
    const int cbase = col0 + wn * 32;
#pragma unroll
    for (int mt = 0; mt < 4; mt++) {
        int r0 = rbase + mt * 16 + lq;
#pragma unroll
        for (int half = 0; half < 2; half++) {
            int r = r0 + half * 8;
            if (r < M) {
#pragma unroll
                for (int nt = 0; nt < 4; nt++) {
                    int c = cbase + nt * 8 + lr * 2;
                    float v0 = acc[mt][nt][half * 2 + 0];
                    float v1 = acc[mt][nt][half * 2 + 1];
                    if (bias) { v0 += bias[c]; v1 += bias[c + 1]; }
                    if (epi == 0) {
                        *(float2*)(C + (size_t)r * N + c) = make_float2(v0, v1);
                    } else if (epi == 3) {
                        *(uint32_t*)(C16 + (size_t)r * N + c) = f2h2(v0, v1);
                    } else {
                        *(uint32_t*)(C16 + (size_t)r * N + c) =
                            f2h2(fmaxf(v0, 0.f), fmaxf(v1, 0.f));
                    }
                }
            }
        }
    }
}

// ---------------- fused 3-hop decoder GEMM ----------------
// out[r,:] = sum_k scale_k * leaky(gout316[r, k*128:(k+1)*128] * decW_k^T + dec_b_k)
// grid (1, ceil(M/128)), block 256.
__global__ __launch_bounds__(256) void gemm_dec(
    const __half* __restrict__ A, const __half* __restrict__ B,
    const float* __restrict__ bias, float* __restrict__ Cout, int M)
{
    extern __shared__ uint32_t sm[];
    FRAG_SETUP
    const int row0 = blockIdx.y * 128;
    const float scales[3] = {1.f, 0.90483741803596f, 0.81873075307798f};

    float acc[4][4][4], acc2[4][4][4];
#pragma unroll
    for (int i = 0; i < 4; i++)
#pragma unroll
        for (int j = 0; j < 4; j++)
#pragma unroll
            for (int k = 0; k < 4; k++) { acc[i][j][k] = 0.f; acc2[i][j][k] = 0.f; }

    uint4 pa[2], pb[2];
#define LDG_DEC(cc)                                                                    \
    {                                                                                  \
        int k0 = (cc) << 5;                                                            \
        int hop = (cc) >> 2, kb = ((cc) & 3) << 5;                                     \
        _Pragma("unroll")                                                              \
        for (int it = 0; it < 2; it++) {                                               \
            int row = it * 64 + s_row;                                                 \
            int gr = row0 + row;                                                       \
            pa[it] = make_uint4(0u, 0u, 0u, 0u);                                       \
            if (gr < M) pa[it] = *(const uint4*)(A + (size_t)gr * 384 + k0 + s_c * 8); \
            pb[it] = *(const uint4*)(B + (size_t)hop * 16384 + (size_t)row * 128 + kb + s_c * 8); \
        }                                                                              \
    }

    uint32_t* A0 = sm;
    uint32_t* B0 = sm + TBUF;
    uint32_t* A1 = sm + 2 * TBUF;
    uint32_t* B1 = sm + 3 * TBUF;
    const uint32_t sb = smem_u32(sm);
    const uint32_t aAddr0 = sb, bAddr0 = sb + TBUF * 4;
    const uint32_t aAddr1 = sb + 2 * TBUF * 4, bAddr1 = sb + 3 * TBUF * 4;
    const int cbase = wn * 32;

    LDG_DEC(0);
    STS_CHUNK(A0, B0);
    LDG_DEC(1);
    __syncthreads();

    for (int c = 0; c < 12; c++) {
        uint32_t aA = (c & 1) ? aAddr1 : aAddr0;
        uint32_t bA = (c & 1) ? bAddr1 : bAddr0;
        uint32_t* Asn = (c & 1) ? A0 : A1;
        uint32_t* Bsn = (c & 1) ? B0 : B1;
        COMPUTE_KS(aA, bA, 0);
        if (c + 1 < 12) STS_CHUNK(Asn, Bsn);
        COMPUTE_KS(aA, bA, 1);
        if (c + 2 < 12) LDG_DEC(c + 2);
        __syncthreads();
        if ((c & 3) == 3) {
            int hop = c >> 2;
            float sc = scales[hop];
#pragma unroll
            for (int nt = 0; nt < 4; nt++) {
                int col = cbase + nt * 8 + lr * 2;
                float b0 = bias[hop * 128 + col];
                float b1 = bias[hop * 128 + col + 1];
#pragma unroll
                for (int mt = 0; mt < 4; mt++) {
                    acc2[mt][nt][0] += sc * leakyf(acc[mt][nt][0] + b0, 0.01f);
                    acc2[mt][nt][1] += sc * leakyf(acc[mt][nt][1] + b1, 0.01f);
                    acc2[mt][nt][2] += sc * leakyf(acc[mt][nt][2] + b0, 0.01f);
                    acc2[mt][nt][3] += sc * leakyf(acc[mt][nt][3] + b1, 0.01f);
                    acc[mt][nt][0] = 0.f; acc[mt][nt][1] = 0.f;
                    acc[mt][nt][2] = 0.f; acc[mt][nt][3] = 0.f;
                }
            }
        }
    }

    const int rbase = row0 + wm * 64;
#pragma unroll
    for (int mt = 0; mt < 4; mt++) {
        int r0 = rbase + mt * 16 + lq;
#pragma unroll
        for (int half = 0; half < 2; half++) {
            int r = r0 + half * 8;
            if (r < M) {
#pragma unroll
                for (int nt = 0; nt < 4; nt++) {
                    int col = cbase + nt * 8 + lr * 2;
                    *(float2*)(Cout + (size_t)r * DD + col) =
                        make_float2(acc2[mt][nt][half * 2 + 0], acc2[mt][nt][half * 2 + 1]);
                }
            }
        }
    }
}

// ---------------- fp16 tensor-core flash attention ----------------
#define VSW 68
__global__ __launch_bounds__(256) void attn_tc() {
    __shared__ uint32_t QK[128 * SRW];
    __shared__ uint32_t VT[32 * VSW];
    const int b = blockIdx.z, h = blockIdx.y, qt = blockIdx.x;
    const int cnt = g_cnt[b];
    const int tid = threadIdx.x, wid = tid >> 5, lane = tid & 31;
    const int lq = lane >> 2, lr = lane & 3;
    const float qscale = 0.17677669529663687f;

#pragma unroll
    for (int it = 0; it < 4; it++) {
        int idx = it * 256 + tid;
        int row = idx >> 3;
        int q = qt * 128 + row;
        uint2 u = make_uint2(0u, 0u);
        if (q < LMAX)
            u = *(const uint2*)(g_qkv16 + (size_t)(b * LMAX + q) * 384 + h * 32 + (idx & 7) * 4);
        *(uint2*)&QK[row * SRW + (idx & 7) * 2] = u;
    }
    __syncthreads();
    uint32_t qa[2][4];
    {
        int r = wid * 16 + lq;
#pragma unroll
        for (int ks = 0; ks < 2; ks++) {
            int kb = ks * 8 + lr;
            qa[ks][0] = QK[r * SRW + kb];
            qa[ks][1] = QK[(r + 8) * SRW + kb];
            qa[ks][2] = QK[r * SRW + kb + 4];
            qa[ks][3] = QK[(r + 8) * SRW + kb + 4];
        }
    }

    float m0 = -INFINITY, m1 = -INFINITY, den0 = 0.f, den1 = 0.f;
    float of[4][4];
#pragma unroll
    for (int nt = 0; nt < 4; nt++) {
        of[nt][0] = 0.f; of[nt][1] = 0.f; of[nt][2] = 0.f; of[nt][3] = 0.f;
    }

    for (int kb0 = 0; kb0 < LMAX; kb0 += 128) {
        __syncthreads();
#pragma unroll
        for (int it = 0; it < 4; it++) {
            int idx = it * 256 + tid;
            int row = idx >> 3;
            int key = kb0 + row;
            uint2 u = make_uint2(0u, 0u);
            if (key < LMAX)
                u = *(const uint2*)(g_qkv16 + (size_t)(b * LMAX + key) * 384 + 128 + h * 32 + (idx & 7) * 4);
            *(uint2*)&QK[row * SRW + (idx & 7) * 2] = u;
        }
#pragma unroll
        for (int it = 0; it < 2; it++) {
            int item = it * 256 + tid;
            int kp = item & 63, g = item >> 6;
            int k0 = kb0 + 2 * kp;
            uint2 a = make_uint2(0u, 0u), bb = make_uint2(0u, 0u);
            if (k0 < LMAX)
                a = *(const uint2*)(g_qkv16 + (size_t)(b * LMAX + k0) * 384 + 256 + h * 32 + g * 4);
            if (k0 + 1 < LMAX)
                bb = *(const uint2*)(g_qkv16 + (size_t)(b * LMAX + k0 + 1) * 384 + 256 + h * 32 + g * 4);
            VT[(g * 4 + 0) * VSW + kp] = __byte_perm(a.x, bb.x, 0x5410);
            VT[(g * 4 + 1) * VSW + kp] = __byte_perm(a.x, bb.x, 0x7632);
            VT[(g * 4 + 2) * VSW + kp] = __byte_perm(a.y, bb.y, 0x5410);
            VT[(g * 4 + 3) * VSW + kp] = __byte_perm(a.y, bb.y, 0x7632);
        }
        __syncthreads();

        float sf[16][4];
#pragma unroll
        for (int nt = 0; nt < 16; nt++) {
            sf[nt][0] = 0.f; sf[nt][1] = 0.f; sf[nt][2] = 0.f; sf[nt][3] = 0.f;
        }
#pragma unroll
        for (int ks = 0; ks < 2; ks++) {
            int kk = ks * 8 + lr;
#pragma unroll
            for (int nt = 0; nt < 16; nt++) {
                uint32_t b0 = QK[(nt * 8 + lq) * SRW + kk];
                uint32_t b1 = QK[(nt * 8 + lq) * SRW + kk + 4];
                mma16(sf[nt], qa[ks][0], qa[ks][1], qa[ks][2], qa[ks][3], b0, b1);
            }
        }
        float bm0 = -INFINITY, bm1 = -INFINITY;
#pragma unroll
        for (int nt = 0; nt < 16; nt++) {
            sf[nt][0] *= qscale; sf[nt][1] *= qscale;
            sf[nt][2] *= qscale; sf[nt][3] *= qscale;
            int c = kb0 + nt * 8 + lr * 2;
            if (c >= cnt) { sf[nt][0] = -1e30f; sf[nt][2] = -1e30f; }
            if (c + 1 >= cnt) { sf[nt][1] = -1e30f; sf[nt][3] = -1e30f; }
            bm0 = fmaxf(bm0, fmaxf(sf[nt][0], sf[nt][1]));
            bm1 = fmaxf(bm1, fmaxf(sf[nt][2], sf[nt][3]));
        }
        bm0 = fmaxf(bm0, __shfl_xor_sync(0xffffffffu, bm0, 1));
        bm0 = fmaxf(bm0, __shfl_xor_sync(0xffffffffu, bm0, 2));
        bm1 = fmaxf(bm1, __shfl_xor_sync(0xffffffffu, bm1, 1));
        bm1 = fmaxf(bm1, __shfl_xor_sync(0xffffffffu, bm1, 2));
        float nm0 = fmaxf(m0, bm0), nm1 = fmaxf(m1, bm1);
        float cor0 = __expf(m0 - nm0), cor1 = __expf(m1 - nm1);
        m0 = nm0; m1 = nm1;
        float s0 = 0.f, s1 = 0.f;
        uint32_t pf01[16], pf23[16];
#pragma unroll
        for (int nt = 0; nt < 16; nt++) {
            float p0 = __expf(sf[nt][0] - nm0), p1 = __expf(sf[nt][1] - nm0);
            float p2 = __expf(sf[nt][2] - nm1), p3 = __expf(sf[nt][3] - nm1);
            s0 += p0 + p1; s1 += p2 + p3;
            pf01[nt] = f2h2(p0, p1);
            pf23[nt] = f2h2(p2, p3);
        }
        s0 += __shfl_xor_sync(0xffffffffu, s0, 1);
        s0 += __shfl_xor_sync(0xffffffffu, s0, 2);
        s1 += __shfl_xor_sync(0xffffffffu, s1, 1);
        s1 += __shfl_xor_sync(0xffffffffu, s1, 2);
        den0 = den0 * cor0 + s0;
        den1 = den1 * cor1 + s1;
#pragma unroll
        for (int nt = 0; nt < 4; nt++) {
            of[nt][0] *= cor0; of[nt][1] *= cor0;
            of[nt][2] *= cor1; of[nt][3] *= cor1;
        }
#pragma unroll
        for (int ks = 0; ks < 8; ks++) {
            uint32_t a0 = pf01[2 * ks], a1 = pf23[2 * ks];
            uint32_t a2 = pf01[2 * ks + 1], a3 = pf23[2 * ks + 1];
#pragma unroll
            for (int nt = 0; nt < 4; nt++) {
                uint32_t b0 = VT[(nt * 8 + lq) * VSW + 8 * ks + lr];
                uint32_t b1 = VT[(nt * 8 + lq) * VSW + 8 * ks + lr + 4];
                mma16(of[nt], a0, a1, a2, a3, b0, b1);
            }
        }
    }

    float i0 = 1.f / den0, i1 = 1.f / den1;
    int q_lo = qt * 128 + wid * 16 + lq, q_hi = q_lo + 8;
#pragma unroll
    for (int nt = 0; nt < 4; nt++) {
        int col = h * 32 + nt * 8 + lr * 2;
        if (q_lo < LMAX)
            *(uint32_t*)(g_attn16 + (size_t)(b * LMAX + q_lo) * DD + col) =
                f2h2(of[nt][0] * i0, of[nt][1] * i0);
        if (q_hi < LMAX)
            *(uint32_t*)(g_attn16 + (size_t)(b * LMAX + q_hi) * DD + col) =
                f2h2(of[nt][2] * i1, of[nt][3] * i1);
    }
}

// ---------------- GAT kernels (CSR, fp16 h3) ----------------
__global__ void zero_y_kernel() {
    size_t i = (size_t)blockIdx.x * blockDim.x + threadIdx.x;
    if (i < (size_t)NM * DD / 4) {
        ((float4*)g_y)[i] = make_float4(0.f, 0.f, 0.f, 0.f);
        ((uint2*)g_y16)[i] = make_uint2(0u, 0u);
    }
}

__global__ void gat_prep3(const float* __restrict__ a_src,
                          const float* __restrict__ a_dst)
{
    int gid = blockIdx.x * blockDim.x + threadIdx.x;
    int node = gid >> 5, lane = gid & 31;
    int hop = blockIdx.y;
    if (node >= NN) return;
    float s[4], d[4];
#pragma unroll
    for (int j = 0; j < 4; j++) {
        int c = j * 32 + lane;
        float hv = __half2float(g_h316[(size_t)node * 384 + hop * 128 + c]);
        s[j] = hv * a_src[hop * DD + c];
        d[j] = hv * a_dst[hop * DD + c];
    }
#pragma unroll
    for (int j = 0; j < 4; j++)
#pragma unroll
        for (int o = 16; o > 0; o >>= 1) {
            s[j] += __shfl_xor_sync(0xffffffffu, s[j], o);
            d[j] += __shfl_xor_sync(0xffffffffu, d[j], o);
        }
    if (lane == 0) {
        int idx = (node * 3 + hop) * 4;
        *(float4*)&g_als3[idx] = make_float4(s[0], s[1], s[2], s[3]);
        *(float4*)&g_ald3[idx] = make_float4(d[0], d[1], d[2], d[3]);
        g_deg[hop * NN + node] = 0;
    }
}

__global__ void deg3(const int* __restrict__ e0, const int* __restrict__ e1,
                     const int* __restrict__ e2)
{
    int hop = blockIdx.y;
    const int* ei = (hop == 0) ? e0 : (hop == 1) ? e1 : e2;
    int t = blockIdx.x * blockDim.x + threadIdx.x;
    if (t >= NITEMS) return;
    int dst = (t < NE) ? ei[NE + t] : t - NE;
    atomicAdd(&g_deg[hop * NN + dst], 1);
}

__global__ __launch_bounds__(1024) void scan3() {
    __shared__ int part[1024];
    const int hop = blockIdx.x;
    const int t = threadIdx.x;
    const int CH = (NN + 1023) / 1024;
    int beg = t * CH, end = beg + CH;
    if (end > NN) end = NN;
    int s = 0;
    for (int i = beg; i < end; i++) s += g_deg[hop * NN + i];
    part[t] = s;
    __syncthreads();
    for (int o = 1; o < 1024; o <<= 1) {
        int u = (t >= o) ? part[t - o] : 0;
        __syncthreads();
        part[t] += u;
        __syncthreads();
    }
    int run = part[t] - s;
    for (int i = beg; i < end; i++) {
        int d = g_deg[hop * NN + i];
        g_off[hop * (NN + 1) + i] = run;
        g_cur[hop * NN + i] = run;
        run += d;
    }
    if (t == 0) g_off[hop * (NN + 1) + NN] = NITEMS;
}

__global__ void edge_scat3(const int* __restrict__ e0, const int* __restrict__ e1,
                           const int* __restrict__ e2)
{
    int hop = blockIdx.y;
    const int* ei = (hop == 0) ? e0 : (hop == 1) ? e1 : e2;
    int t = blockIdx.x * blockDim.x + threadIdx.x;
    if (t >= NITEMS) return;
    int src, dst;
    if (t < NE) { src = ei[t]; dst = ei[NE + t]; }
    else { src = dst = t - NE; }
    float4 a = *(const float4*)&g_als3[(src * 3 + hop) * 4];
    float4 b = *(const float4*)&g_ald3[(dst * 3 + hop) * 4];
    float4 ew;
    ew.x = expf(leakyf(a.x + b.x, 0.2f));
    ew.y = expf(leakyf(a.y + b.y, 0.2f));
    ew.z = expf(leakyf(a.z + b.z, 0.2f));
    ew.w = expf(leakyf(a.w + b.w, 0.2f));
    int pos = atomicAdd(&g_cur[hop * NN + dst], 1);
    g_srcS[(size_t)hop * NITEMS + pos] = src;
    *(float4*)&g_ew[((size_t)hop * NITEMS + pos) * 4] = ew;
}

// aggregation: warp per (dst, hop); fp16 h3 in, fp16 gout316 out
__global__ void aggr3(const float* __restrict__ bias) {
    int gid = blockIdx.x * blockDim.x + threadIdx.x;
    int dst = gid >> 5, lane = gid & 31;
    int hop = blockIdx.y;
    if (dst >= NN) return;
    int e0 = g_off[hop * (NN + 1) + dst];
    int e1 = g_off[hop * (NN + 1) + dst + 1];
    float4 den = make_float4(0.f, 0.f, 0.f, 0.f);
    for (int e = e0 + lane; e < e1; e += 32) {
        float4 w4 = *(const float4*)&g_ew[((size_t)hop * NITEMS + e) * 4];
        den.x += w4.x; den.y += w4.y; den.z += w4.z; den.w += w4.w;
    }
#pragma unroll
    for (int o = 16; o > 0; o >>= 1) {
        den.x += __shfl_xor_sync(0xffffffffu, den.x, o);
        den.y += __shfl_xor_sync(0xffffffffu, den.y, o);
        den.z += __shfl_xor_sync(0xffffffffu, den.z, o);
        den.w += __shfl_xor_sync(0xffffffffu, den.w, o);
    }
    float4 inv = make_float4(1.f / den.x, 1.f / den.y, 1.f / den.z, 1.f / den.w);
    float a0 = 0.f, a1 = 0.f, a2 = 0.f, a3 = 0.f;
    for (int e = e0; e < e1; e++) {
        float4 w4 = *(const float4*)&g_ew[((size_t)hop * NITEMS + e) * 4];
        int src = g_srcS[(size_t)hop * NITEMS + e];
        const __half* hs = g_h316 + (size_t)src * 384 + hop * 128;
        a0 += w4.x * inv.x * __half2float(hs[lane]);
        a1 += w4.y * inv.y * __half2float(hs[32 + lane]);
        a2 += w4.z * inv.z * __half2float(hs[64 + lane]);
        a3 += w4.w * inv.w * __half2float(hs[96 + lane]);
    }
    __half* gd = g_gout316 + (size_t)dst * 384 + hop * 128;
    const float* bb = bias + hop * 128;
    gd[lane]      = __float2half(a0 + bb[lane]);
    gd[32 + lane] = __float2half(a1 + bb[32 + lane]);
    gd[64 + lane] = __float2half(a2 + bb[64 + lane]);
    gd[96 + lane] = __float2half(a3 + bb[96 + lane]);
}

// ---------------- position / count kernels ----------------
__global__ void hist_kernel(const int* __restrict__ genre) {
    __shared__ int loc[NG];
    if (threadIdx.x < NG) loc[threadIdx.x] = 0;
    __syncthreads();
    int i = blockIdx.x * 128 + threadIdx.x;
    if (i < NM) atomicAdd(&loc[genre[i]], 1);
    __syncthreads();
    if (threadIdx.x < NG) g_chist[blockIdx.x * NG + threadIdx.x] = loc[threadIdx.x];
}
__global__ void scan_kernel() {
    int g = threadIdx.x;
    if (g >= NG) return;
    int run = 0;
    for (int c = 0; c < NCHUNK; c++) {
        int t = g_chist[c * NG + g];
        g_chist[c * NG + g] = run;
        run += t;
    }
    g_cnt[g] = run;
}
__global__ void pos_kernel(const int* __restrict__ genre) {
    int c = blockIdx.x * blockDim.x + threadIdx.x;
    if (c >= NCHUNK) return;
    int off[NG];
    for (int g = 0; g < NG; g++) off[g] = g_chist[c * NG + g];
    int base = c * 128;
    int end = base + 128; if (end > NM) end = NM;
    for (int i = base; i < end; i++) {
        int g = genre[i];
        g_pos[i] = off[g]++;
    }
}

// gather from out (GAT result): y fp32 + y16 + xm16
__global__ void gather_kernel(const int* __restrict__ movie_idx, const int* __restrict__ genre,
                              const float* __restrict__ src)
{
    int t = blockIdx.x * blockDim.x + threadIdx.x;
    if (t >= NM * 32) return;
    int i = t >> 5, c4 = (t & 31) * 4;
    float4 v = *(const float4*)&src[(size_t)movie_idx[i] * DD + c4];
    uint2 h2 = make_uint2(f2h2(v.x, v.y), f2h2(v.z, v.w));
    *(uint2*)(g_xm16 + (size_t)i * DD + c4) = h2;
    int row = genre[i] * LMAX + g_pos[i];
    *(float4*)&g_y[(size_t)row * DD + c4] = v;
    *(uint2*)(g_y16 + (size_t)row * DD + c4) = h2;
}

// ---------------- LayerNorm (fused residual, dual fp32+fp16 output) ----------------
__global__ void ln_kernel(float* __restrict__ y, __half* __restrict__ y16,
                          const float* __restrict__ t,
                          const float* __restrict__ gam, const float* __restrict__ bet,
                          int rows)
{
    int gid = blockIdx.x * blockDim.x + threadIdx.x;
    int row = gid >> 5, lane = gid & 31;
    if (row >= rows) return;
    size_t off = (size_t)row * DD + lane * 4;
    float4 v = *(float4*)(y + off);
    float4 tv = *(const float4*)(t + off);
    v.x += tv.x; v.y += tv.y; v.z += tv.z; v.w += tv.w;
    float s = v.x + v.y + v.z + v.w;
#pragma unroll
    for (int o = 16; o > 0; o >>= 1) s += __shfl_xor_sync(0xffffffffu, s, o);
    float mean = s * (1.f / DD);
    float dx = v.x - mean, dy = v.y - mean, dz = v.z - mean, dw = v.w - mean;
    float ss = dx * dx + dy * dy + dz * dz + dw * dw;
#pragma unroll
    for (int o = 16; o > 0; o >>= 1) ss += __shfl_xor_sync(0xffffffffu, ss, o);
    float inv = rsqrtf(ss * (1.f / DD) + 1e-5f);
    float4 gg = *(const float4*)(gam + lane * 4);
    float4 bb = *(const float4*)(bet + lane * 4);
    v.x = dx * inv * gg.x + bb.x;
    v.y = dy * inv * gg.y + bb.y;
    v.z = dz * inv * gg.z + bb.z;
    v.w = dw * inv * gg.w + bb.w;
    *(float4*)(y + off) = v;
    *(uint2*)(y16 + off) = make_uint2(f2h2(v.x, v.y), f2h2(v.z, v.w));
}

// ---------------- pooling / fusion ----------------
__global__ void pool_kernel() {
    int g = blockIdx.x, d = threadIdx.x;
    int cnt = g_cnt[g];
    float s = 0.f;
    for (int t = 0; t < cnt; t++) s += g_y[(size_t)(g * LMAX + t) * DD + d];
    g_pooled[g * DD + d] = s / fmaxf((float)cnt, 1.f);
}

__global__ void pe_kernel(const float* __restrict__ fus_w) {
    int g = blockIdx.x, n = threadIdx.x;
    float s = 0.f;
    for (int k = 0; k < DD; k++)
        s += g_pooled[g * DD + k] * fus_w[n * 256 + 128 + k];
    g_pe[g * DD + n] = s;
}

__global__ void fuse_out_kernel(const int* __restrict__ movie_idx, const int* __restrict__ genre,
                                const float* __restrict__ fus_b, float* __restrict__ out)
{
    int t = blockIdx.x * blockDim.x + threadIdx.x;
    if (t >= NM * 32) return;
    int i = t >> 5, c4 = (t & 31) * 4;
    float4 v = *(const float4*)&g_tmp[(size_t)i * DD + c4];
    float4 p = *(const float4*)&g_pe[genre[i] * DD + c4];
    float4 bb = *(const float4*)(fus_b + c4);
    v.x = leakyf(v.x + p.x + bb.x, 0.01f);
    v.y = leakyf(v.y + p.y + bb.y, 0.01f);
    v.z = leakyf(v.z + p.z + bb.z, 0.01f);
    v.w = leakyf(v.w + p.w + bb.w, 0.01f);
    *(float4*)&out[(size_t)movie_idx[i] * DD + c4] = v;
}

// ---------------- launch ----------------
extern "C" void kernel_launch(void* const* d_in, const int* in_sizes, int n_in,
                              void* d_out, int out_size)
{
    const float* x        = (const float*)d_in[0];
    const int*   e0       = (const int*)d_in[1];
    const int*   e1       = (const int*)d_in[2];
    const int*   e2       = (const int*)d_in[3];
    const int*   movie_idx = (const int*)d_in[4];
    const int*   genre     = (const int*)d_in[5];
    const float* gat_W    = (const float*)d_in[6];
    const float* att_src  = (const float*)d_in[7];
    const float* att_dst  = (const float*)d_in[8];
    const float* gat_bias = (const float*)d_in[9];
    const float* dec_W    = (const float*)d_in[10];
    const float* dec_b    = (const float*)d_in[11];
    const float* qkv_w    = (const float*)d_in[12];
    const float* qkv_b    = (const float*)d_in[13];
    const float* out_w    = (const float*)d_in[14];
    const float* out_b    = (const float*)d_in[15];
    const float* ln1_g    = (const float*)d_in[16];
    const float* ln1_b    = (const float*)d_in[17];
    const float* ln2_g    = (const float*)d_in[18];
    const float* ln2_b    = (const float*)d_in[19];
    const float* ffn_w1   = (const float*)d_in[20];
    const float* ffn_b1   = (const float*)d_in[21];
    const float* ffn_w2   = (const float*)d_in[22];
    const float* ffn_b2   = (const float*)d_in[23];
    const float* fus_w    = (const float*)d_in[24];
    const float* fus_b    = (const float*)d_in[25];
    float* out = (float*)d_out;

    float *p_y, *p_tmp;
    __half *p_x16, *p_h316, *p_gout316, *p_y16, *p_qkv16, *p_attn16, *p_ffn16, *p_xm16;
    __half *p_gatW16, *p_decW16, *p_qkvW16, *p_outW16, *p_fw116, *p_fw216, *p_fusW16;
    cudaGetSymbolAddress((void**)&p_y,      g_y);
    cudaGetSymbolAddress((void**)&p_tmp,    g_tmp);
    cudaGetSymbolAddress((void**)&p_x16,    g_x16);
    cudaGetSymbolAddress((void**)&p_h316,   g_h316);
    cudaGetSymbolAddress((void**)&p_gout316, g_gout316);
    cudaGetSymbolAddress((void**)&p_y16,    g_y16);
    cudaGetSymbolAddress((void**)&p_qkv16,  g_qkv16);
    cudaGetSymbolAddress((void**)&p_attn16, g_attn16);
    cudaGetSymbolAddress((void**)&p_ffn16,  g_ffn16);
    cudaGetSymbolAddress((void**)&p_xm16,   g_xm16);
    cudaGetSymbolAddress((void**)&p_gatW16, g_gatW16);
    cudaGetSymbolAddress((void**)&p_decW16, g_decW16);
    cudaGetSymbolAddress((void**)&p_qkvW16, g_qkvW16);
    cudaGetSymbolAddress((void**)&p_outW16, g_outW16);
    cudaGetSymbolAddress((void**)&p_fw116,  g_fw116);
    cudaGetSymbolAddress((void**)&p_fw216,  g_fw216);
    cudaGetSymbolAddress((void**)&p_fusW16, g_fusW16);

    const int GSMEM = 4 * TBUF * 4;   // 40960 B
    cudaFuncSetAttribute(gemm_mma, cudaFuncAttributeMaxDynamicSharedMemorySize, GSMEM);
    cudaFuncSetAttribute(gemm_dec, cudaFuncAttributeMaxDynamicSharedMemorySize, GSMEM);

    const int MTN = (NN + 127) / 128;  // 391
    const int MT  = (NM + 127) / 128;  // 160

#define F2H(src, dst, n) f2h_kernel<<<((n) / 4 + 255) / 256, 256>>>(src, dst, (n) / 4)
    F2H(x, p_x16, NN * DD);
    F2H(gat_W, p_gatW16, 3 * DD * DD);
    F2H(dec_W, p_decW16, 3 * DD * DD);
    F2H(qkv_w, p_qkvW16, NL * 3 * DD * DD);
    F2H(out_w, p_outW16, NL * DD * DD);
    F2H(ffn_w1, p_fw116, NL * FFD * DD);
    F2H(ffn_w2, p_fw216, NL * DD * FFD);
    F2H(fus_w, p_fusW16, DD * 256);

    // -------- GAT --------
    gemm_mma<<<dim3(3, MTN), 256, GSMEM>>>(p_x16, p_gatW16, nullptr, nullptr, p_h316,
                                           NN, 384, DD, DD, DD, 3);
    gat_prep3<<<dim3((NN * 32 + 255) / 256, 3), 256>>>(att_src, att_dst);
    deg3<<<dim3((NITEMS + 255) / 256, 3), 256>>>(e0, e1, e2);
    scan3<<<3, 1024>>>();
    edge_scat3<<<dim3((NITEMS + 255) / 256, 3), 256>>>(e0, e1, e2);
    aggr3<<<dim3((NN * 32 + 255) / 256, 3), 256>>>(gat_bias);
    gemm_dec<<<dim3(1, MTN), 256, GSMEM>>>(p_gout316, p_decW16, dec_b, out, NN);

    // -------- build genre sequences (reads GAT result from out) --------
    hist_kernel<<<NCHUNK, 128>>>(genre);
    scan_kernel<<<1, 32>>>();
    pos_kernel<<<1, 256>>>(genre);
    zero_y_kernel<<<(NM * DD / 4 + 255) / 256, 256>>>();
    gather_kernel<<<(NM * 32 + 255) / 256, 256>>>(movie_idx, genre, out);

    // -------- transformer (4 layers) --------
    for (int l = 0; l < NL; l++) {
        gemm_mma<<<dim3(3 * DD / 128, MT), 256, GSMEM>>>(
            p_y16, p_qkvW16 + (size_t)l * 3 * DD * DD, qkv_b + l * 3 * DD,
            nullptr, p_qkv16, NM, 3 * DD, DD, DD, DD, 3);
        attn_tc<<<dim3((LMAX + 127) / 128, NHEADS, NG), 256>>>();
        gemm_mma<<<dim3(1, MT), 256, GSMEM>>>(
            p_attn16, p_outW16 + (size_t)l * DD * DD, out_b + l * DD,
            p_tmp, nullptr, NM, DD, DD, DD, DD, 0);
        ln_kernel<<<(NM * 32 + 255) / 256, 256>>>(p_y, p_y16, p_tmp,
                                                  ln1_g + l * DD, ln1_b + l * DD, NM);
        gemm_mma<<<dim3(FFD / 128, MT), 256, GSMEM>>>(
            p_y16, p_fw116 + (size_t)l * FFD * DD, ffn_b1 + l * FFD,
            nullptr, p_ffn16, NM, FFD, DD, DD, DD, 4);
        gemm_mma<<<dim3(1, MT), 256, GSMEM>>>(
            p_ffn16, p_fw216 + (size_t)l * DD * FFD, ffn_b2 + l * DD,
            p_tmp, nullptr, NM, DD, FFD, FFD, FFD, 0);
        ln_kernel<<<(NM * 32 + 255) / 256, 256>>>(p_y, p_y16, p_tmp,
                                                  ln2_g + l * DD, ln2_b + l * DD, NM);
    }

    // -------- pool + fuse + write output --------
    pool_kernel<<<NG, DD>>>();
    pe_kernel<<<NG, DD>>>(fus_w);
    gemm_mma<<<dim3(1, MT), 256, GSMEM>>>(p_xm16, p_fusW16, nullptr, p_tmp, nullptr,
                                          NM, DD, DD, DD, 256, 0);
    fuse_out_kernel<<<(NM * 32 + 255) / 256, 256>>>(movie_idx, genre, fus_b, out);
}

// round 11
// speedup vs baseline: 3.9610x; 1.0154x over previous
#include <cuda_runtime.h>
#include <cuda_fp16.h>
#include <math.h>
#include <stdint.h>

#define NN 50000
#define NE 400000
#define DD 128
#define NM 20400
#define NG 30
#define LMAX 680
#define NHEADS 4
#define NL 4
#define FFD 2048
#define NCHUNK 160   // ceil(20400/128)
#define NITEMS (NE + NN)

// ---------------- scratch (device globals; no runtime allocation) ----------------
__device__ __align__(16) float  g_als3[NN * 3 * NHEADS];
__device__ __align__(16) float  g_ald3[NN * 3 * NHEADS];
__device__ __align__(16) float  g_ew[(size_t)3 * NITEMS * NHEADS];
__device__ int g_srcS[(size_t)3 * NITEMS];
__device__ int g_deg[3 * NN];
__device__ int g_off[3 * (NN + 1)];
__device__ int g_cur[3 * NN];
__device__ __align__(16) float  g_y[(size_t)NM * DD];
__device__ __align__(16) float  g_tmp[(size_t)NM * DD];
__device__ __align__(16) float  g_pooled[NG * DD];
__device__ __align__(16) float  g_pe[NG * DD];
__device__ int g_pos[NM];
__device__ int g_cnt[NG];
__device__ int g_chist[NCHUNK * NG];
// fp16 shadows / intermediates
__device__ __align__(16) __half g_x16[(size_t)NN * DD];
__device__ __align__(16) __half g_h316[(size_t)NN * 384];
__device__ __align__(16) __half g_gout316[(size_t)NN * 384];
__device__ __align__(16) __half g_y16[(size_t)NM * DD];
__device__ __align__(16) __half g_qkv16[(size_t)NM * 3 * DD];
__device__ __align__(16) __half g_attn16[(size_t)NM * DD];
__device__ __align__(16) __half g_ffn16[(size_t)NM * FFD];
__device__ __align__(16) __half g_xm16[(size_t)NM * DD];
// fp16 weights
__device__ __align__(16) __half g_gatW16[3 * DD * DD];
__device__ __align__(16) __half g_decW16[3 * DD * DD];
__device__ __align__(16) __half g_qkvW16[NL * 3 * DD * DD];
__device__ __align__(16) __half g_outW16[NL * DD * DD];
__device__ __align__(16) __half g_fw116[(size_t)NL * FFD * DD];
__device__ __align__(16) __half g_fw216[(size_t)NL * DD * FFD];
__device__ __align__(16) __half g_fusW16[DD * 256];

// ---------------- small helpers ----------------
__device__ __forceinline__ float leakyf(float x, float s) { return x >= 0.f ? x : s * x; }

__device__ __forceinline__ uint32_t f2h2(float lo, float hi) {
    uint32_t r;
    asm("cvt.rn.f16x2.f32 %0, %1, %2;" : "=r"(r) : "f"(hi), "f"(lo));
    return r;
}

__device__ __forceinline__ uint32_t h2ex2(uint32_t x) {
    uint32_t r;
    asm("ex2.approx.f16x2 %0, %1;" : "=r"(r) : "r"(x));
    return r;
}

__device__ __forceinline__ float ex2f(float x) {
    float r;
    asm("ex2.approx.f32 %0, %1;" : "=f"(r) : "f"(x));
    return r;
}

__device__ __forceinline__ uint32_t smem_u32(const void* p) {
    uint32_t a;
    asm("{ .reg .u64 t; cvta.to.shared.u64 t, %1; cvt.u32.u64 %0, t; }" : "=r"(a) : "l"(p));
    return a;
}

__device__ __forceinline__ void mma16(float* c, uint32_t a0, uint32_t a1, uint32_t a2,
                                      uint32_t a3, uint32_t b0, uint32_t b1) {
    asm volatile(
        "mma.sync.aligned.m16n8k16.row.col.f32.f16.f16.f32 "
        "{%0,%1,%2,%3}, {%4,%5,%6,%7}, {%8,%9}, {%0,%1,%2,%3};"
        : "+f"(c[0]), "+f"(c[1]), "+f"(c[2]), "+f"(c[3])
        : "r"(a0), "r"(a1), "r"(a2), "r"(a3), "r"(b0), "r"(b1));
}

__device__ __forceinline__ void ldsm4(uint32_t* r, uint32_t addr) {
    asm volatile("ldmatrix.sync.aligned.m8n8.x4.shared.b16 {%0,%1,%2,%3}, [%4];"
                 : "=r"(r[0]), "=r"(r[1]), "=r"(r[2]), "=r"(r[3]) : "r"(addr));
}

// ---------------- float -> half conversion ----------------
__global__ void f2h_kernel(const float* __restrict__ s, __half* __restrict__ d, int n4) {
    int i = blockIdx.x * blockDim.x + threadIdx.x;
    if (i < n4) {
        float4 v = ((const float4*)s)[i];
        uint2 u;
        u.x = f2h2(v.x, v.y);
        u.y = f2h2(v.z, v.w);
        ((uint2*)d)[i] = u;
    }
}

#define SRW 20
#define TBUF (128 * SRW)

// common fragment-index setup
#define FRAG_SETUP                                                  \
    const int tid = threadIdx.x;                                    \
    const int wid = tid >> 5, lane = tid & 31;                      \
    const int wm = wid & 1, wn = wid >> 1;                          \
    const int lq = lane >> 2, lr = lane & 3;                        \
    const int rr = lane & 7;                                        \
    const int aRow = wm * 64 + rr + ((lane >> 3) & 1) * 8;          \
    const int aColW = ((lane >> 4) & 1) * 4;                        \
    const int bRow = wn * 32 + rr + ((lane >> 4) & 1) * 8;          \
    const int bColW = ((lane >> 3) & 1) * 4;                        \
    const int s_row = tid >> 2;                                     \
    const int s_c = tid & 3;

#define STS_CHUNK(Ad, Bd)                                           \
    {                                                               \
        _Pragma("unroll")                                           \
        for (int it = 0; it < 2; it++) {                            \
            int row = it * 64 + s_row;                              \
            *(uint4*)&(Ad)[row * SRW + s_c * 4] = pa[it];           \
            *(uint4*)&(Bd)[row * SRW + s_c * 4] = pb[it];           \
        }                                                           \
    }
#define COMPUTE_KS(AsAddr, BsAddr, KS)                                                 \
    {                                                                                  \
        uint32_t bq[2][4];                                                             \
        _Pragma("unroll")                                                              \
        for (int ntp = 0; ntp < 2; ntp++)                                              \
            ldsm4(bq[ntp], (BsAddr) + (((bRow + ntp * 16) * SRW) + (KS) * 8 + bColW) * 4); \
        _Pragma("unroll")                                                              \
        for (int mt = 0; mt < 4; mt++) {                                               \
            uint32_t aq[4];                                                            \
            ldsm4(aq, (AsAddr) + (((aRow + mt * 16) * SRW) + (KS) * 8 + aColW) * 4);   \
            _Pragma("unroll")                                                          \
            for (int nt = 0; nt < 4; nt++)                                             \
                mma16(acc[mt][nt], aq[0], aq[1], aq[2], aq[3],                         \
                      bq[nt >> 1][(nt & 1) * 2 + 0], bq[nt >> 1][(nt & 1) * 2 + 1]);   \
        }                                                                              \
    }

// ---------------- pipelined fp16 mma GEMM ----------------
// C = epi(A[M,K(lda)] * B[N,K(ldb)]^T + bias), fp32 accum.
// epi: 0 = fp32 store(+bias), 3 = fp16 store -> C16, 4 = fp16 relu -> C16
__global__ __launch_bounds__(256) void gemm_mma(
    const __half* __restrict__ A, const __half* __restrict__ B,
    const float* __restrict__ bias, float* __restrict__ C, __half* __restrict__ C16,
    int M, int N, int K, int lda, int ldb, int epi)
{
    extern __shared__ uint32_t sm[];
    FRAG_SETUP
    const int row0 = blockIdx.y * 128, col0 = blockIdx.x * 128;

    float acc[4][4][4];
#pragma unroll
    for (int i = 0; i < 4; i++)
#pragma unroll
        for (int j = 0; j < 4; j++) {
            acc[i][j][0] = 0.f; acc[i][j][1] = 0.f;
            acc[i][j][2] = 0.f; acc[i][j][3] = 0.f;
        }
    const int nC = K >> 5;
    uint4 pa[2], pb[2];

#define LDG_CHUNK(cc)                                                                  \
    {                                                                                  \
        int k0 = (cc) << 5;                                                            \
        _Pragma("unroll")                                                              \
        for (int it = 0; it < 2; it++) {                                               \
            int row = it * 64 + s_row;                                                 \
            int gr = row0 + row;                                                       \
            pa[it] = make_uint4(0u, 0u, 0u, 0u);                                       \
            if (gr < M) pa[it] = *(const uint4*)(A + (size_t)gr * lda + k0 + s_c * 8); \
            pb[it] = *(const uint4*)(B + (size_t)(col0 + row) * ldb + k0 + s_c * 8);   \
        }                                                                              \
    }

    uint32_t* A0 = sm;
    uint32_t* B0 = sm + TBUF;
    uint32_t* A1 = sm + 2 * TBUF;
    uint32_t* B1 = sm + 3 * TBUF;
    const uint32_t sb = smem_u32(sm);
    const uint32_t aAddr0 = sb, bAddr0 = sb + TBUF * 4;
    const uint32_t aAddr1 = sb + 2 * TBUF * 4, bAddr1 = sb + 3 * TBUF * 4;

    LDG_CHUNK(0);
    STS_CHUNK(A0, B0);
    if (nC > 1) LDG_CHUNK(1);
    __syncthreads();

    for (int c = 0; c < nC; c++) {
        uint32_t aA = (c & 1) ? aAddr1 : aAddr0;
        uint32_t bA = (c & 1) ? bAddr1 : bAddr0;
        uint32_t* Asn = (c & 1) ? A0 : A1;
        uint32_t* Bsn = (c & 1) ? B0 : B1;
        COMPUTE_KS(aA, bA, 0);
        if (c + 1 < nC) STS_CHUNK(Asn, Bsn);
        COMPUTE_KS(aA, bA, 1);
        if (c + 2 < nC) LDG_CHUNK(c + 2);
        __syncthreads();
    }

    const int rbase = row0 + wm * 64;
    const int cbase = col0 + wn * 32;
#pragma unroll
    for (int mt = 0; mt < 4; mt++) {
        int r0 = rbase + mt * 16 + lq;
#pragma unroll
        for (int half = 0; half < 2; half++) {
            int r = r0 + half * 8;
            if (r < M) {
#pragma unroll
                for (int nt = 0; nt < 4; nt++) {
                    int c = cbase + nt * 8 + lr * 2;
                    float v0 = acc[mt][nt][half * 2 + 0];
                    float v1 = acc[mt][nt][half * 2 + 1];
                    if (bias) { v0 += bias[c]; v1 += bias[c + 1]; }
                    if (epi == 0) {
                        *(float2*)(C + (size_t)r * N + c) = make_float2(v0, v1);
                    } else if (epi == 3) {
                        *(uint32_t*)(C16 + (size_t)r * N + c) = f2h2(v0, v1);
                    } else {
                        *(uint32_t*)(C16 + (size_t)r * N + c) =
                            f2h2(fmaxf(v0, 0.f), fmaxf(v1, 0.f));
                    }
                }
            }
        }
    }
}

// ---------------- fused 3-hop decoder GEMM ----------------
__global__ __launch_bounds__(256) void gemm_dec(
    const __half* __restrict__ A, const __half* __restrict__ B,
    const float* __restrict__ bias, float* __restrict__ Cout, int M)
{
    extern __shared__ uint32_t sm[];
    FRAG_SETUP
    const int row0 = blockIdx.y * 128;
    const float scales[3] = {1.f, 0.90483741803596f, 0.81873075307798f};

    float acc[4][4][4], acc2[4][4][4];
#pragma unroll
    for (int i = 0; i < 4; i++)
#pragma unroll
        for (int j = 0; j < 4; j++)
#pragma unroll
            for (int k = 0; k < 4; k++) { acc[i][j][k] = 0.f; acc2[i][j][k] = 0.f; }

    uint4 pa[2], pb[2];
#define LDG_DEC(cc)                                                                    \
    {                                                                                  \
        int k0 = (cc) << 5;                                                            \
        int hop = (cc) >> 2, kb = ((cc) & 3) << 5;                                     \
        _Pragma("unroll")                                                              \
        for (int it = 0; it < 2; it++) {                                               \
            int row = it * 64 + s_row;                                                 \
            int gr = row0 + row;                                                       \
            pa[it] = make_uint4(0u, 0u, 0u, 0u);                                       \
            if (gr < M) pa[it] = *(const uint4*)(A + (size_t)gr * 384 + k0 + s_c * 8); \
            pb[it] = *(const uint4*)(B + (size_t)hop * 16384 + (size_t)row * 128 + kb + s_c * 8); \
        }                                                                              \
    }

    uint32_t* A0 = sm;
    uint32_t* B0 = sm + TBUF;
    uint32_t* A1 = sm + 2 * TBUF;
    uint32_t* B1 = sm + 3 * TBUF;
    const uint32_t sb = smem_u32(sm);
    const uint32_t aAddr0 = sb, bAddr0 = sb + TBUF * 4;
    const uint32_t aAddr1 = sb + 2 * TBUF * 4, bAddr1 = sb + 3 * TBUF * 4;
    const int cbase = wn * 32;

    LDG_DEC(0);
    STS_CHUNK(A0, B0);
    LDG_DEC(1);
    __syncthreads();

    for (int c = 0; c < 12; c++) {
        uint32_t aA = (c & 1) ? aAddr1 : aAddr0;
        uint32_t bA = (c & 1) ? bAddr1 : bAddr0;
        uint32_t* Asn = (c & 1) ? A0 : A1;
        uint32_t* Bsn = (c & 1) ? B0 : B1;
        COMPUTE_KS(aA, bA, 0);
        if (c + 1 < 12) STS_CHUNK(Asn, Bsn);
        COMPUTE_KS(aA, bA, 1);
        if (c + 2 < 12) LDG_DEC(c + 2);
        __syncthreads();
        if ((c & 3) == 3) {
            int hop = c >> 2;
            float sc = scales[hop];
#pragma unroll
            for (int nt = 0; nt < 4; nt++) {
                int col = cbase + nt * 8 + lr * 2;
                float b0 = bias[hop * 128 + col];
                float b1 = bias[hop * 128 + col + 1];
#pragma unroll
                for (int mt = 0; mt < 4; mt++) {
                    acc2[mt][nt][0] += sc * leakyf(acc[mt][nt][0] + b0, 0.01f);
                    acc2[mt][nt][1] += sc * leakyf(acc[mt][nt][1] + b1, 0.01f);
                    acc2[mt][nt][2] += sc * leakyf(acc[mt][nt][2] + b0, 0.01f);
                    acc2[mt][nt][3] += sc * leakyf(acc[mt][nt][3] + b1, 0.01f);
                    acc[mt][nt][0] = 0.f; acc[mt][nt][1] = 0.f;
                    acc[mt][nt][2] = 0.f; acc[mt][nt][3] = 0.f;
                }
            }
        }
    }

    const int rbase = row0 + wm * 64;
#pragma unroll
    for (int mt = 0; mt < 4; mt++) {
        int r0 = rbase + mt * 16 + lq;
#pragma unroll
        for (int half = 0; half < 2; half++) {
            int r = r0 + half * 8;
            if (r < M) {
#pragma unroll
                for (int nt = 0; nt < 4; nt++) {
                    int col = cbase + nt * 8 + lr * 2;
                    *(float2*)(Cout + (size_t)r * DD + col) =
                        make_float2(acc2[mt][nt][half * 2 + 0], acc2[mt][nt][half * 2 + 1]);
                }
            }
        }
    }
}

// ---------------- fp16 tensor-core flash attention (f16x2 ex2 softmax) ----------------
#define VSW 68
__global__ __launch_bounds__(256) void attn_tc() {
    __shared__ uint32_t QK[128 * SRW];
    __shared__ uint32_t VT[32 * VSW];
    const int b = blockIdx.z, h = blockIdx.y, qt = blockIdx.x;
    const int cnt = g_cnt[b];
    const int tid = threadIdx.x, wid = tid >> 5, lane = tid & 31;
    const int lq = lane >> 2, lr = lane & 3;
    const float qs2 = 0.2550181731927341f;   // (1/sqrt(32)) * log2(e)
    const uint32_t ones2 = 0x3C003C00u;      // half2(1.0, 1.0)

#pragma unroll
    for (int it = 0; it < 4; it++) {
        int idx = it * 256 + tid;
        int row = idx >> 3;
        int q = qt * 128 + row;
        uint2 u = make_uint2(0u, 0u);
        if (q < LMAX)
            u = *(const uint2*)(g_qkv16 + (size_t)(b * LMAX + q) * 384 + h * 32 + (idx & 7) * 4);
        *(uint2*)&QK[row * SRW + (idx & 7) * 2] = u;
    }
    __syncthreads();
    uint32_t qa[2][4];
    {
        int r = wid * 16 + lq;
#pragma unroll
        for (int ks = 0; ks < 2; ks++) {
            int kb = ks * 8 + lr;
            qa[ks][0] = QK[r * SRW + kb];
            qa[ks][1] = QK[(r + 8) * SRW + kb];
            qa[ks][2] = QK[r * SRW + kb + 4];
            qa[ks][3] = QK[(r + 8) * SRW + kb + 4];
        }
    }

    float m0 = -INFINITY, m1 = -INFINITY, den0 = 0.f, den1 = 0.f;
    float of[4][4];
#pragma unroll
    for (int nt = 0; nt < 4; nt++) {
        of[nt][0] = 0.f; of[nt][1] = 0.f; of[nt][2] = 0.f; of[nt][3] = 0.f;
    }

    for (int kb0 = 0; kb0 < LMAX; kb0 += 128) {
        __syncthreads();
#pragma unroll
        for (int it = 0; it < 4; it++) {
            int idx = it * 256 + tid;
            int row = idx >> 3;
            int key = kb0 + row;
            uint2 u = make_uint2(0u, 0u);
            if (key < LMAX)
                u = *(const uint2*)(g_qkv16 + (size_t)(b * LMAX + key) * 384 + 128 + h * 32 + (idx & 7) * 4);
            *(uint2*)&QK[row * SRW + (idx & 7) * 2] = u;
        }
#pragma unroll
        for (int it = 0; it < 2; it++) {
            int item = it * 256 + tid;
            int kp = item & 63, g = item >> 6;
            int k0 = kb0 + 2 * kp;
            uint2 a = make_uint2(0u, 0u), bb = make_uint2(0u, 0u);
            if (k0 < LMAX)
                a = *(const uint2*)(g_qkv16 + (size_t)(b * LMAX + k0) * 384 + 256 + h * 32 + g * 4);
            if (k0 + 1 < LMAX)
                bb = *(const uint2*)(g_qkv16 + (size_t)(b * LMAX + k0 + 1) * 384 + 256 + h * 32 + g * 4);
            VT[(g * 4 + 0) * VSW + kp] = __byte_perm(a.x, bb.x, 0x5410);
            VT[(g * 4 + 1) * VSW + kp] = __byte_perm(a.x, bb.x, 0x7632);
            VT[(g * 4 + 2) * VSW + kp] = __byte_perm(a.y, bb.y, 0x5410);
            VT[(g * 4 + 3) * VSW + kp] = __byte_perm(a.y, bb.y, 0x7632);
        }
        __syncthreads();

        float sf[16][4];
#pragma unroll
        for (int nt = 0; nt < 16; nt++) {
            sf[nt][0] = 0.f; sf[nt][1] = 0.f; sf[nt][2] = 0.f; sf[nt][3] = 0.f;
        }
#pragma unroll
        for (int ks = 0; ks < 2; ks++) {
            int kk = ks * 8 + lr;
#pragma unroll
            for (int nt = 0; nt < 16; nt++) {
                uint32_t b0 = QK[(nt * 8 + lq) * SRW + kk];
                uint32_t b1 = QK[(nt * 8 + lq) * SRW + kk + 4];
                mma16(sf[nt], qa[ks][0], qa[ks][1], qa[ks][2], qa[ks][3], b0, b1);
            }
        }
        // ---- scale to log2 domain, mask, block row-max ----
        float bm0 = -INFINITY, bm1 = -INFINITY;
#pragma unroll
        for (int nt = 0; nt < 16; nt++) {
            sf[nt][0] *= qs2; sf[nt][1] *= qs2;
            sf[nt][2] *= qs2; sf[nt][3] *= qs2;
            int c = kb0 + nt * 8 + lr * 2;
            if (c >= cnt) { sf[nt][0] = -1e30f; sf[nt][2] = -1e30f; }
            if (c + 1 >= cnt) { sf[nt][1] = -1e30f; sf[nt][3] = -1e30f; }
            bm0 = fmaxf(bm0, fmaxf(sf[nt][0], sf[nt][1]));
            bm1 = fmaxf(bm1, fmaxf(sf[nt][2], sf[nt][3]));
        }
        bm0 = fmaxf(bm0, __shfl_xor_sync(0xffffffffu, bm0, 1));
        bm0 = fmaxf(bm0, __shfl_xor_sync(0xffffffffu, bm0, 2));
        bm1 = fmaxf(bm1, __shfl_xor_sync(0xffffffffu, bm1, 1));
        bm1 = fmaxf(bm1, __shfl_xor_sync(0xffffffffu, bm1, 2));
        float nm0 = fmaxf(m0, bm0), nm1 = fmaxf(m1, bm1);
        float cor0 = ex2f(m0 - nm0), cor1 = ex2f(m1 - nm1);
        m0 = nm0; m1 = nm1;
        // ---- p = 2^(t - m), two at a time in fp16 ----
        uint32_t pf01[16], pf23[16];
#pragma unroll
        for (int nt = 0; nt < 16; nt++) {
            pf01[nt] = h2ex2(f2h2(sf[nt][0] - nm0, sf[nt][1] - nm0));
            pf23[nt] = h2ex2(f2h2(sf[nt][2] - nm1, sf[nt][3] - nm1));
        }
#pragma unroll
        for (int nt = 0; nt < 4; nt++) {
            of[nt][0] *= cor0; of[nt][1] *= cor0;
            of[nt][2] *= cor1; of[nt][3] *= cor1;
        }
        // ---- O += P·V, and den via ones-column mma ----
        float dn[4] = {0.f, 0.f, 0.f, 0.f};
#pragma unroll
        for (int ks = 0; ks < 8; ks++) {
            uint32_t a0 = pf01[2 * ks], a1 = pf23[2 * ks];
            uint32_t a2 = pf01[2 * ks + 1], a3 = pf23[2 * ks + 1];
#pragma unroll
            for (int nt = 0; nt < 4; nt++) {
                uint32_t b0 = VT[(nt * 8 + lq) * VSW + 8 * ks + lr];
                uint32_t b1 = VT[(nt * 8 + lq) * VSW + 8 * ks + lr + 4];
                mma16(of[nt], a0, a1, a2, a3, b0, b1);
            }
            mma16(dn, a0, a1, a2, a3, ones2, ones2);
        }
        den0 = den0 * cor0 + dn[0];
        den1 = den1 * cor1 + dn[2];
    }

    float i0 = 1.f / den0, i1 = 1.f / den1;
    int q_lo = qt * 128 + wid * 16 + lq, q_hi = q_lo + 8;
#pragma unroll
    for (int nt = 0; nt < 4; nt++) {
        int col = h * 32 + nt * 8 + lr * 2;
        if (q_lo < LMAX)
            *(uint32_t*)(g_attn16 + (size_t)(b * LMAX + q_lo) * DD + col) =
                f2h2(of[nt][0] * i0, of[nt][1] * i0);
        if (q_hi < LMAX)
            *(uint32_t*)(g_attn16 + (size_t)(b * LMAX + q_hi) * DD + col) =
                f2h2(of[nt][2] * i1, of[nt][3] * i1);
    }
}

// ---------------- GAT kernels (CSR, fp16 h3) ----------------
__global__ void zero_y_kernel() {
    size_t i = (size_t)blockIdx.x * blockDim.x + threadIdx.x;
    if (i < (size_t)NM * DD / 4) {
        ((float4*)g_y)[i] = make_float4(0.f, 0.f, 0.f, 0.f);
        ((uint2*)g_y16)[i] = make_uint2(0u, 0u);
    }
}

__global__ void gat_prep3(const float* __restrict__ a_src,
                          const float* __restrict__ a_dst)
{
    int gid = blockIdx.x * blockDim.x + threadIdx.x;
    int node = gid >> 5, lane = gid & 31;
    int hop = blockIdx.y;
    if (node >= NN) return;
    float s[4], d[4];
#pragma unroll
    for (int j = 0; j < 4; j++) {
        int c = j * 32 + lane;
        float hv = __half2float(g_h316[(size_t)node * 384 + hop * 128 + c]);
        s[j] = hv * a_src[hop * DD + c];
        d[j] = hv * a_dst[hop * DD + c];
    }
#pragma unroll
    for (int j = 0; j < 4; j++)
#pragma unroll
        for (int o = 16; o > 0; o >>= 1) {
            s[j] += __shfl_xor_sync(0xffffffffu, s[j], o);
            d[j] += __shfl_xor_sync(0xffffffffu, d[j], o);
        }
    if (lane == 0) {
        int idx = (node * 3 + hop) * 4;
        *(float4*)&g_als3[idx] = make_float4(s[0], s[1], s[2], s[3]);
        *(float4*)&g_ald3[idx] = make_float4(d[0], d[1], d[2], d[3]);
        g_deg[hop * NN + node] = 0;
    }
}

__global__ void deg3(const int* __restrict__ e0, const int* __restrict__ e1,
                     const int* __restrict__ e2)
{
    int hop = blockIdx.y;
    const int* ei = (hop == 0) ? e0 : (hop == 1) ? e1 : e2;
    int t = blockIdx.x * blockDim.x + threadIdx.x;
    if (t >= NITEMS) return;
    int dst = (t < NE) ? ei[NE + t] : t - NE;
    atomicAdd(&g_deg[hop * NN + dst], 1);
}

__global__ __launch_bounds__(1024) void scan3() {
    __shared__ int part[1024];
    const int hop = blockIdx.x;
    const int t = threadIdx.x;
    const int CH = (NN + 1023) / 1024;
    int beg = t * CH, end = beg + CH;
    if (end > NN) end = NN;
    int s = 0;
    for (int i = beg; i < end; i++) s += g_deg[hop * NN + i];
    part[t] = s;
    __syncthreads();
    for (int o = 1; o < 1024; o <<= 1) {
        int u = (t >= o) ? part[t - o] : 0;
        __syncthreads();
        part[t] += u;
        __syncthreads();
    }
    int run = part[t] - s;
    for (int i = beg; i < end; i++) {
        int d = g_deg[hop * NN + i];
        g_off[hop * (NN + 1) + i] = run;
        g_cur[hop * NN + i] = run;
        run += d;
    }
    if (t == 0) g_off[hop * (NN + 1) + NN] = NITEMS;
}

__global__ void edge_scat3(const int* __restrict__ e0, const int* __restrict__ e1,
                           const int* __restrict__ e2)
{
    int hop = blockIdx.y;
    const int* ei = (hop == 0) ? e0 : (hop == 1) ? e1 : e2;
    int t = blockIdx.x * blockDim.x + threadIdx.x;
    if (t >= NITEMS) return;
    int src, dst;
    if (t < NE) { src = ei[t]; dst = ei[NE + t]; }
    else { src = dst = t - NE; }
    float4 a = *(const float4*)&g_als3[(src * 3 + hop) * 4];
    float4 b = *(const float4*)&g_ald3[(dst * 3 + hop) * 4];
    float4 ew;
    ew.x = expf(leakyf(a.x + b.x, 0.2f));
    ew.y = expf(leakyf(a.y + b.y, 0.2f));
    ew.z = expf(leakyf(a.z + b.z, 0.2f));
    ew.w = expf(leakyf(a.w + b.w, 0.2f));
    int pos = atomicAdd(&g_cur[hop * NN + dst], 1);
    g_srcS[(size_t)hop * NITEMS + pos] = src;
    *(float4*)&g_ew[((size_t)hop * NITEMS + pos) * 4] = ew;
}

__global__ void aggr3(const float* __restrict__ bias) {
    int gid = blockIdx.x * blockDim.x + threadIdx.x;
    int dst = gid >> 5, lane = gid & 31;
    int hop = blockIdx.y;
    if (dst >= NN) return;
    int e0 = g_off[hop * (NN + 1) + dst];
    int e1 = g_off[hop * (NN + 1) + dst + 1];
    float4 den = make_float4(0.f, 0.f, 0.f, 0.f);
    for (int e = e0 + lane; e < e1; e += 32) {
        float4 w4 = *(const float4*)&g_ew[((size_t)hop * NITEMS + e) * 4];
        den.x += w4.x; den.y += w4.y; den.z += w4.z; den.w += w4.w;
    }
#pragma unroll
    for (int o = 16; o > 0; o >>= 1) {
        den.x += __shfl_xor_sync(0xffffffffu, den.x, o);
        den.y += __shfl_xor_sync(0xffffffffu, den.y, o);
        den.z += __shfl_xor_sync(0xffffffffu, den.z, o);
        den.w += __shfl_xor_sync(0xffffffffu, den.w, o);
    }
    float4 inv = make_float4(1.f / den.x, 1.f / den.y, 1.f / den.z, 1.f / den.w);
    float a0 = 0.f, a1 = 0.f, a2 = 0.f, a3 = 0.f;
    for (int e = e0; e < e1; e++) {
        float4 w4 = *(const float4*)&g_ew[((size_t)hop * NITEMS + e) * 4];
        int src = g_srcS[(size_t)hop * NITEMS + e];
        const __half* hs = g_h316 + (size_t)src * 384 + hop * 128;
        a0 += w4.x * inv.x * __half2float(hs[lane]);
        a1 += w4.y * inv.y * __half2float(hs[32 + lane]);
        a2 += w4.z * inv.z * __half2float(hs[64 + lane]);
        a3 += w4.w * inv.w * __half2float(hs[96 + lane]);
    }
    __half* gd = g_gout316 + (size_t)dst * 384 + hop * 128;
    const float* bb = bias + hop * 128;
    gd[lane]      = __float2half(a0 + bb[lane]);
    gd[32 + lane] = __float2half(a1 + bb[32 + lane]);
    gd[64 + lane] = __float2half(a2 + bb[64 + lane]);
    gd[96 + lane] = __float2half(a3 + bb[96 + lane]);
}

// ---------------- position / count kernels ----------------
__global__ void hist_kernel(const int* __restrict__ genre) {
    __shared__ int loc[NG];
    if (threadIdx.x < NG) loc[threadIdx.x] = 0;
    __syncthreads();
    int i = blockIdx.x * 128 + threadIdx.x;
    if (i < NM) atomicAdd(&loc[genre[i]], 1);
    __syncthreads();
    if (threadIdx.x < NG) g_chist[blockIdx.x * NG + threadIdx.x] = loc[threadIdx.x];
}
__global__ void scan_kernel() {
    int g = threadIdx.x;
    if (g >= NG) return;
    int run = 0;
    for (int c = 0; c < NCHUNK; c++) {
        int t = g_chist[c * NG + g];
        g_chist[c * NG + g] = run;
        run += t;
    }
    g_cnt[g] = run;
}
__global__ void pos_kernel(const int* __restrict__ genre) {
    int c = blockIdx.x * blockDim.x + threadIdx.x;
    if (c >= NCHUNK) return;
    int off[NG];
    for (int g = 0; g < NG; g++) off[g] = g_chist[c * NG + g];
    int base = c * 128;
    int end = base + 128; if (end > NM) end = NM;
    for (int i = base; i < end; i++) {
        int g = genre[i];
        g_pos[i] = off[g]++;
    }
}

__global__ void gather_kernel(const int* __restrict__ movie_idx, const int* __restrict__ genre,
                              const float* __restrict__ src)
{
    int t = blockIdx.x * blockDim.x + threadIdx.x;
    if (t >= NM * 32) return;
    int i = t >> 5, c4 = (t & 31) * 4;
    float4 v = *(const float4*)&src[(size_t)movie_idx[i] * DD + c4];
    uint2 h2 = make_uint2(f2h2(v.x, v.y), f2h2(v.z, v.w));
    *(uint2*)(g_xm16 + (size_t)i * DD + c4) = h2;
    int row = genre[i] * LMAX + g_pos[i];
    *(float4*)&g_y[(size_t)row * DD + c4] = v;
    *(uint2*)(g_y16 + (size_t)row * DD + c4) = h2;
}

// ---------------- LayerNorm (fused residual, dual fp32+fp16 output) ----------------
__global__ void ln_kernel(float* __restrict__ y, __half* __restrict__ y16,
                          const float* __restrict__ t,
                          const float* __restrict__ gam, const float* __restrict__ bet,
                          int rows)
{
    int gid = blockIdx.x * blockDim.x + threadIdx.x;
    int row = gid >> 5, lane = gid & 31;
    if (row >= rows) return;
    size_t off = (size_t)row * DD + lane * 4;
    float4 v = *(float4*)(y + off);
    float4 tv = *(const float4*)(t + off);
    v.x += tv.x; v.y += tv.y; v.z += tv.z; v.w += tv.w;
    float s = v.x + v.y + v.z + v.w;
#pragma unroll
    for (int o = 16; o > 0; o >>= 1) s += __shfl_xor_sync(0xffffffffu, s, o);
    float mean = s * (1.f / DD);
    float dx = v.x - mean, dy = v.y - mean, dz = v.z - mean, dw = v.w - mean;
    float ss = dx * dx + dy * dy + dz * dz + dw * dw;
#pragma unroll
    for (int o = 16; o > 0; o >>= 1) ss += __shfl_xor_sync(0xffffffffu, ss, o);
    float inv = rsqrtf(ss * (1.f / DD) + 1e-5f);
    float4 gg = *(const float4*)(gam + lane * 4);
    float4 bb = *(const float4*)(bet + lane * 4);
    v.x = dx * inv * gg.x + bb.x;
    v.y = dy * inv * gg.y + bb.y;
    v.z = dz * inv * gg.z + bb.z;
    v.w = dw * inv * gg.w + bb.w;
    *(float4*)(y + off) = v;
    *(uint2*)(y16 + off) = make_uint2(f2h2(v.x, v.y), f2h2(v.z, v.w));
}

// ---------------- pooling / fusion ----------------
__global__ void pool_kernel() {
    int g = blockIdx.x, d = threadIdx.x;
    int cnt = g_cnt[g];
    float s = 0.f;
    for (int t = 0; t < cnt; t++) s += g_y[(size_t)(g * LMAX + t) * DD + d];
    g_pooled[g * DD + d] = s / fmaxf((float)cnt, 1.f);
}

__global__ void pe_kernel(const float* __restrict__ fus_w) {
    int g = blockIdx.x, n = threadIdx.x;
    float s = 0.f;
    for (int k = 0; k < DD; k++)
        s += g_pooled[g * DD + k] * fus_w[n * 256 + 128 + k];
    g_pe[g * DD + n] = s;
}

__global__ void fuse_out_kernel(const int* __restrict__ movie_idx, const int* __restrict__ genre,
                                const float* __restrict__ fus_b, float* __restrict__ out)
{
    int t = blockIdx.x * blockDim.x + threadIdx.x;
    if (t >= NM * 32) return;
    int i = t >> 5, c4 = (t & 31) * 4;
    float4 v = *(const float4*)&g_tmp[(size_t)i * DD + c4];
    float4 p = *(const float4*)&g_pe[genre[i] * DD + c4];
    float4 bb = *(const float4*)(fus_b + c4);
    v.x = leakyf(v.x + p.x + bb.x, 0.01f);
    v.y = leakyf(v.y + p.y + bb.y, 0.01f);
    v.z = leakyf(v.z + p.z + bb.z, 0.01f);
    v.w = leakyf(v.w + p.w + bb.w, 0.01f);
    *(float4*)&out[(size_t)movie_idx[i] * DD + c4] = v;
}

// ---------------- launch ----------------
extern "C" void kernel_launch(void* const* d_in, const int* in_sizes, int n_in,
                              void* d_out, int out_size)
{
    const float* x        = (const float*)d_in[0];
    const int*   e0       = (const int*)d_in[1];
    const int*   e1       = (const int*)d_in[2];
    const int*   e2       = (const int*)d_in[3];
    const int*   movie_idx = (const int*)d_in[4];
    const int*   genre     = (const int*)d_in[5];
    const float* gat_W    = (const float*)d_in[6];
    const float* att_src  = (const float*)d_in[7];
    const float* att_dst  = (const float*)d_in[8];
    const float* gat_bias = (const float*)d_in[9];
    const float* dec_W    = (const float*)d_in[10];
    const float* dec_b    = (const float*)d_in[11];
    const float* qkv_w    = (const float*)d_in[12];
    const float* qkv_b    = (const float*)d_in[13];
    const float* out_w    = (const float*)d_in[14];
    const float* out_b    = (const float*)d_in[15];
    const float* ln1_g    = (const float*)d_in[16];
    const float* ln1_b    = (const float*)d_in[17];
    const float* ln2_g    = (const float*)d_in[18];
    const float* ln2_b    = (const float*)d_in[19];
    const float* ffn_w1   = (const float*)d_in[20];
    const float* ffn_b1   = (const float*)d_in[21];
    const float* ffn_w2   = (const float*)d_in[22];
    const float* ffn_b2   = (const float*)d_in[23];
    const float* fus_w    = (const float*)d_in[24];
    const float* fus_b    = (const float*)d_in[25];
    float* out = (float*)d_out;

    float *p_y, *p_tmp;
    __half *p_x16, *p_h316, *p_gout316, *p_y16, *p_qkv16, *p_attn16, *p_ffn16, *p_xm16;
    __half *p_gatW16, *p_decW16, *p_qkvW16, *p_outW16, *p_fw116, *p_fw216, *p_fusW16;
    cudaGetSymbolAddress((void**)&p_y,      g_y);
    cudaGetSymbolAddress((void**)&p_tmp,    g_tmp);
    cudaGetSymbolAddress((void**)&p_x16,    g_x16);
    cudaGetSymbolAddress((void**)&p_h316,   g_h316);
    cudaGetSymbolAddress((void**)&p_gout316, g_gout316);
    cudaGetSymbolAddress((void**)&p_y16,    g_y16);
    cudaGetSymbolAddress((void**)&p_qkv16,  g_qkv16);
    cudaGetSymbolAddress((void**)&p_attn16, g_attn16);
    cudaGetSymbolAddress((void**)&p_ffn16,  g_ffn16);
    cudaGetSymbolAddress((void**)&p_xm16,   g_xm16);
    cudaGetSymbolAddress((void**)&p_gatW16, g_gatW16);
    cudaGetSymbolAddress((void**)&p_decW16, g_decW16);
    cudaGetSymbolAddress((void**)&p_qkvW16, g_qkvW16);
    cudaGetSymbolAddress((void**)&p_outW16, g_outW16);
    cudaGetSymbolAddress((void**)&p_fw116,  g_fw116);
    cudaGetSymbolAddress((void**)&p_fw216,  g_fw216);
    cudaGetSymbolAddress((void**)&p_fusW16, g_fusW16);

    const int GSMEM = 4 * TBUF * 4;   // 40960 B
    cudaFuncSetAttribute(gemm_mma, cudaFuncAttributeMaxDynamicSharedMemorySize, GSMEM);
    cudaFuncSetAttribute(gemm_dec, cudaFuncAttributeMaxDynamicSharedMemorySize, GSMEM);

    const int MTN = (NN + 127) / 128;  // 391
    const int MT  = (NM + 127) / 128;  // 160

#define F2H(src, dst, n) f2h_kernel<<<((n) / 4 + 255) / 256, 256>>>(src, dst, (n) / 4)
    F2H(x, p_x16, NN * DD);
    F2H(gat_W, p_gatW16, 3 * DD * DD);
    F2H(dec_W, p_decW16, 3 * DD * DD);
    F2H(qkv_w, p_qkvW16, NL * 3 * DD * DD);
    F2H(out_w, p_outW16, NL * DD * DD);
    F2H(ffn_w1, p_fw116, NL * FFD * DD);
    F2H(ffn_w2, p_fw216, NL * DD * FFD);
    F2H(fus_w, p_fusW16, DD * 256);

    // -------- GAT --------
    gemm_mma<<<dim3(3, MTN), 256, GSMEM>>>(p_x16, p_gatW16, nullptr, nullptr, p_h316,
                                           NN, 384, DD, DD, DD, 3);
    gat_prep3<<<dim3((NN * 32 + 255) / 256, 3), 256>>>(att_src, att_dst);
    deg3<<<dim3((NITEMS + 255) / 256, 3), 256>>>(e0, e1, e2);
    scan3<<<3, 1024>>>();
    edge_scat3<<<dim3((NITEMS + 255) / 256, 3), 256>>>(e0, e1, e2);
    aggr3<<<dim3((NN * 32 + 255) / 256, 3), 256>>>(gat_bias);
    gemm_dec<<<dim3(1, MTN), 256, GSMEM>>>(p_gout316, p_decW16, dec_b, out, NN);

    // -------- build genre sequences (reads GAT result from out) --------
    hist_kernel<<<NCHUNK, 128>>>(genre);
    scan_kernel<<<1, 32>>>();
    pos_kernel<<<1, 256>>>(genre);
    zero_y_kernel<<<(NM * DD / 4 + 255) / 256, 256>>>();
    gather_kernel<<<(NM * 32 + 255) / 256, 256>>>(movie_idx, genre, out);

    // -------- transformer (4 layers) --------
    for (int l = 0; l < NL; l++) {
        gemm_mma<<<dim3(3 * DD / 128, MT), 256, GSMEM>>>(
            p_y16, p_qkvW16 + (size_t)l * 3 * DD * DD, qkv_b + l * 3 * DD,
            nullptr, p_qkv16, NM, 3 * DD, DD, DD, DD, 3);
        attn_tc<<<dim3((LMAX + 127) / 128, NHEADS, NG), 256>>>();
        gemm_mma<<<dim3(1, MT), 256, GSMEM>>>(
            p_attn16, p_outW16 + (size_t)l * DD * DD, out_b + l * DD,
            p_tmp, nullptr, NM, DD, DD, DD, DD, 0);
        ln_kernel<<<(NM * 32 + 255) / 256, 256>>>(p_y, p_y16, p_tmp,
                                                  ln1_g + l * DD, ln1_b + l * DD, NM);
        gemm_mma<<<dim3(FFD / 128, MT), 256, GSMEM>>>(
            p_y16, p_fw116 + (size_t)l * FFD * DD, ffn_b1 + l * FFD,
            nullptr, p_ffn16, NM, FFD, DD, DD, DD, 4);
        gemm_mma<<<dim3(1, MT), 256, GSMEM>>>(
            p_ffn16, p_fw216 + (size_t)l * DD * FFD, ffn_b2 + l * DD,
            p_tmp, nullptr, NM, DD, FFD, FFD, FFD, 0);
        ln_kernel<<<(NM * 32 + 255) / 256, 256>>>(p_y, p_y16, p_tmp,
                                                  ln2_g + l * DD, ln2_b + l * DD, NM);
    }

    // -------- pool + fuse + write output --------
    pool_kernel<<<NG, DD>>>();
    pe_kernel<<<NG, DD>>>(fus_w);
    gemm_mma<<<dim3(1, MT), 256, GSMEM>>>(p_xm16, p_fusW16, nullptr, p_tmp, nullptr,
                                          NM, DD, DD, DD, 256, 0);
    fuse_out_kernel<<<(NM * 32 + 255) / 256, 256>>>(movie_idx, genre, fus_b, out);
}